// round 10
// baseline (speedup 1.0000x reference)
#include <cuda_runtime.h>
#include <cuda_fp16.h>
#include <math.h>
#include <stdint.h>

#define NIMG 16
#define CCH 256
#define NPIX 4096            // 64*64

// ---- scratch (static device globals; no allocation) ----
__device__ __half g_Qp[16777216];
__device__ __half g_Kp[16777216];
__device__ __half g_Vp[16777216];
__device__ float  g_S[2*2048*2048];
__device__ __half g_Sh[2*2048*2048];
__device__ float  g_part[8388608];
__device__ float  g_xs1[NIMG*CCH*NPIX];
__device__ __half g_xsh [NIMG*CCH*NPIX];
__device__ __half g_atth[NIMG*CCH*NPIX];
__device__ __half g_xs1h[NIMG*CCH*NPIX];
__device__ __half g_ffh [NIMG*CCH*NPIX];
__device__ __half g_Wqh[65536], g_Wkh[65536], g_Wvh[65536];
__device__ __half g_Wlh[589824], g_Wf1h[589824], g_Wf2h[589824];   // tap-major

// ============================================================================
// helpers
// ============================================================================
__device__ __forceinline__ void mma16(float* d, const uint32_t* a, const uint32_t* b) {
    asm volatile(
        "mma.sync.aligned.m16n8k16.row.col.f32.f16.f16.f32 "
        "{%0,%1,%2,%3}, {%4,%5,%6,%7}, {%8,%9}, {%0,%1,%2,%3};"
        : "+f"(d[0]), "+f"(d[1]), "+f"(d[2]), "+f"(d[3])
        : "r"(a[0]), "r"(a[1]), "r"(a[2]), "r"(a[3]), "r"(b[0]), "r"(b[1]));
}

__device__ __forceinline__ void ldsm4(uint32_t* r, const void* p) {
    uint32_t addr = (uint32_t)__cvta_generic_to_shared(p);
    asm volatile("ldmatrix.sync.aligned.m8n8.x4.shared.b16 {%0,%1,%2,%3}, [%4];"
        : "=r"(r[0]), "=r"(r[1]), "=r"(r[2]), "=r"(r[3]) : "r"(addr));
}

__device__ __forceinline__ void ldsm4t(uint32_t* r, const void* p) {
    uint32_t addr = (uint32_t)__cvta_generic_to_shared(p);
    asm volatile("ldmatrix.sync.aligned.m8n8.x4.trans.shared.b16 {%0,%1,%2,%3}, [%4];"
        : "=r"(r[0]), "=r"(r[1]), "=r"(r[2]), "=r"(r[3]) : "r"(addr));
}

__device__ __forceinline__ uint32_t pack_h2(float a, float b) {
    __half2 h = __floats2half2_rn(a, b);
    return *(uint32_t*)&h;
}

__device__ __forceinline__ void cpa16(uint32_t dst, const void* src, unsigned sz) {
    asm volatile("cp.async.ca.shared.global [%0], [%1], 16, %2;"
                 :: "r"(dst), "l"(src), "r"(sz) : "memory");
}
__device__ __forceinline__ void cpcommit() {
    asm volatile("cp.async.commit_group;" ::: "memory");
}
template <int N>
__device__ __forceinline__ void cpwait() {
    asm volatile("cp.async.wait_group %0;" :: "n"(N) : "memory");
}

// f32 -> f16 bulk convert (exact multiples of 1024 elems)
__global__ void f2h_kernel(const float* __restrict__ src, __half* __restrict__ dst) {
    long i = ((long)blockIdx.x * 256 + threadIdx.x) * 4;
    float4 v = *(const float4*)(src + i);
    *(uint32_t*)(dst + i)     = pack_h2(v.x, v.y);
    *(uint32_t*)(dst + i + 2) = pack_h2(v.z, v.w);
}

// conv weight transpose+convert: W[oc][c][tap] f32 -> Wt2[oc][tap][c] half
__global__ void wtrans_kernel(const float* __restrict__ W, __half* __restrict__ Wt2) {
    int idx = blockIdx.x * 256 + threadIdx.x;
    int oc = idx / 2304, r = idx - oc * 2304;
    int tap = r >> 8, c = r & 255;
    Wt2[idx] = __float2half(W[oc * 2304 + c * 9 + tap]);
}

// scatter index into patchified buffer: scale = oc>>6
__device__ __forceinline__ long pat_index(int img, int oc, int pix) {
    int s  = oc >> 6, cc = oc & 63;
    int lp = 5 - s;
    int lo = 1 + s;
    int Pm = (1 << lp) - 1;
    int y = pix >> 6, x = pix & 63;
    int ohi = y >> lp, pi = y & Pm, owi = x >> lp, pj = x & Pm;
    int t = img & 7, b = img >> 3;
    int nn = (t << (2*lo)) + (ohi << lo) + owi;
    int dd = (cc << (2*lp)) + (pi << lp) + pj;
    return (long)s * 4194304 + (long)b * 2097152 + (long)nn * (64 << (2*lp)) + dd;
}

// ============================================================================
// hconv2 (ks==1): QKV projection, cp.async pipelined, 256 threads
// ============================================================================
__global__ void __launch_bounds__(256, 2) hconv2_kernel(
    const __half* __restrict__ in, const __half* __restrict__ Wt,
    const float* __restrict__ bias, __half* __restrict__ outh_pat)
{
    __shared__ __half A2[2 * 128 * 40];
    __shared__ __half B2[2 * 32 * 136];

    const int tid = threadIdx.x;
    const int lane = tid & 31, wid = tid >> 5;
    const int wm = wid & 1, wn = wid >> 1;
    const int img = blockIdx.x >> 5;
    const int p0 = (blockIdx.x & 31) * 128;
    const int m0 = blockIdx.y * 128;
    const __half* inimg = in + (long)img * CCH * NPIX;

    const uint32_t sA2 = (uint32_t)__cvta_generic_to_shared(A2);
    const uint32_t sB2 = (uint32_t)__cvta_generic_to_shared(B2);

#define ISSUE1(KCN, NB)                                                         \
    {                                                                           \
        const int k0n = (KCN) * 32;                                             \
        {                                                                       \
            int row = tid >> 1, seg = (tid & 1) * 16;                           \
            const __half* src = Wt + (long)(m0 + row) * 256 + k0n + seg;        \
            uint32_t dst = sA2 + (uint32_t)(((NB) * 5120 + row * 40 + seg) * 2);\
            cpa16(dst, src, 16u); cpa16(dst + 16, src + 8, 16u);                \
        }                                                                       \
        {                                                                       \
            int k = tid >> 3, u = tid & 7;                                      \
            const __half* src = inimg + ((long)(k0n + k) << 12) + p0 + u * 8;   \
            uint32_t dst = sB2 + (uint32_t)(((NB) * 4352 + k * 136 + u * 8) * 2); \
            cpa16(dst, src, 16u);                                               \
            cpa16(dst + 128, src + 64, 16u);                                    \
        }                                                                       \
        cpcommit();                                                             \
    }

    float acc[4][4][4] = {};
    ISSUE1(0, 0);

    for (int kc = 0; kc < 8; kc++) {
        cpwait<0>();
        __syncthreads();
        if (kc + 1 < 8) ISSUE1(kc + 1, (kc + 1) & 1);

        const __half* Ap = A2 + (kc & 1) * 5120;
        const __half* Bp = B2 + (kc & 1) * 4352;
#pragma unroll
        for (int kstep = 0; kstep < 2; kstep++) {
            uint32_t a[4][4], b[4][2];
            {
                const int arow = wm * 64 + ((lane >> 3) & 1) * 8 + (lane & 7);
                const int akc  = kstep * 16 + (lane >> 4) * 8;
#pragma unroll
                for (int mi = 0; mi < 4; mi++)
                    ldsm4(a[mi], Ap + (arow + mi * 16) * 40 + akc);
            }
            {
                const int brow = kstep * 16 + (lane & 7) + ((lane >> 3) & 1) * 8;
#pragma unroll
                for (int ni2 = 0; ni2 < 2; ni2++) {
                    const int bcol = wn * 32 + ni2 * 16 + ((lane >> 4) & 1) * 8;
                    uint32_t r[4];
                    ldsm4t(r, Bp + brow * 136 + bcol);
                    b[2*ni2    ][0] = r[0]; b[2*ni2    ][1] = r[1];
                    b[2*ni2 + 1][0] = r[2]; b[2*ni2 + 1][1] = r[3];
                }
            }
#pragma unroll
            for (int mi = 0; mi < 4; mi++)
#pragma unroll
                for (int ni = 0; ni < 4; ni++)
                    mma16(acc[mi][ni], a[mi], b[ni]);
        }
    }
#undef ISSUE1

    const int orow = m0 + wm * 64 + (lane >> 2);
    const int ocol = p0 + wn * 32 + (lane & 3) * 2;
#pragma unroll
    for (int mi = 0; mi < 4; mi++) {
        const int oca = orow + mi * 16, ocb = oca + 8;
        const float ba = bias[oca], bb = bias[ocb];
#pragma unroll
        for (int ni = 0; ni < 4; ni++) {
            const int n = ocol + ni * 8;
            long ia = pat_index(img, oca, n);
            long ib = pat_index(img, ocb, n);
            *(__half2*)(outh_pat + ia) = __floats2half2_rn(acc[mi][ni][0] + ba, acc[mi][ni][1] + ba);
            *(__half2*)(outh_pat + ib) = __floats2half2_rn(acc[mi][ni][2] + bb, acc[mi][ni][3] + bb);
        }
    }
}

// ============================================================================
// hconvK v2: 3x3 conv, tap-major K, 256 threads, M=128 x N=128 tile,
//   K-chunk 64, ALL buffers double-buffered, ONE barrier per chunk,
//   B-build co-scheduled with MMA of the previous chunk.
//   dyn smem (halves): A2[2][128*72] | Bs[2][64*136] | Strip[2][64*160]
// ============================================================================
#define HK_BS    18432
#define HK_STRIP (18432 + 17408)
#define HK_SMEM  ((18432 + 17408 + 20480) * 2)

__global__ void __launch_bounds__(256, 2) hconvK_kernel(
    const __half* __restrict__ in, const __half* __restrict__ Wt,
    const float* __restrict__ bias, const float* __restrict__ res,
    float* __restrict__ out, __half* __restrict__ outh_img,
    int dil, int addres)
{
    extern __shared__ __half sh[];
    __half* A2    = sh;
    __half* Bs    = sh + HK_BS;
    __half* Strip = sh + HK_STRIP;

    const int tid = threadIdx.x;
    const int lane = tid & 31, wid = tid >> 5;
    const int wm = wid & 1, wn = wid >> 1;
    const int img = blockIdx.x >> 5;
    const int p0 = (blockIdx.x & 31) * 128;
    const int y0 = p0 >> 6;                 // 2 image rows: y0, y0+1
    const int m0 = blockIdx.y * 128;
    const __half* inimg = in + (long)img * CCH * NPIX;

    const uint32_t sA2    = (uint32_t)__cvta_generic_to_shared(A2);
    const uint32_t sStrip = (uint32_t)__cvta_generic_to_shared(Strip);

    // zero strip halos once, both buffers
    {
        int c = tid >> 2, u = tid & 3, r = u >> 1, side = u & 1;
        *(uint4*)(Strip +         c * 160 + r * 80 + side * 72) = make_uint4(0, 0, 0, 0);
        *(uint4*)(Strip + 10240 + c * 160 + r * 80 + side * 72) = make_uint4(0, 0, 0, 0);
    }

#define ISSUE_A(KCN)                                                             \
    {                                                                            \
        int row = tid >> 1, seg = (tid & 1) * 32;                                \
        const __half* src = Wt + (long)(m0 + row) * 2304 + (KCN) * 64 + seg;     \
        uint32_t dst = sA2 + (uint32_t)((((KCN) & 1) * 9216 + row * 72 + seg) * 2); \
        cpa16(dst,      src,      16u);                                          \
        cpa16(dst + 16, src + 8,  16u);                                          \
        cpa16(dst + 32, src + 16, 16u);                                          \
        cpa16(dst + 48, src + 24, 16u);                                          \
    }

#define ISSUE_S(KCN)                                                             \
    {                                                                            \
        int tapn = (KCN) >> 2;                                                   \
        int c0v = ((KCN) * 64) & 255;                                            \
        int dyd = (tapn / 3 - 1) * dil;                                          \
        int c = tid >> 2, u = tid & 3;                                           \
        int r = u >> 1, s = u & 1;                                               \
        int gy = y0 + r + dyd;                                                   \
        unsigned ok = ((unsigned)gy < 64u) ? 16u : 0u;                           \
        int gyc = gy < 0 ? 0 : (gy > 63 ? 63 : gy);                              \
        const __half* src = inimg + ((long)(c0v + c) << 12) + (gyc << 6) + s * 32; \
        uint32_t dst = sStrip + (uint32_t)((((KCN) & 1) * 10240 + c * 160 + r * 80 + 8 + s * 32) * 2); \
        cpa16(dst,      src,      ok);                                           \
        cpa16(dst + 16, src + 8,  ok);                                           \
        cpa16(dst + 32, src + 16, ok);                                           \
        cpa16(dst + 48, src + 24, ok);                                           \
    }

#define BUILD(KCN)                                                               \
    {                                                                            \
        const int tap = (KCN) >> 2;                                              \
        const int dxd = (tap - (tap / 3) * 3 - 1) * dil;                         \
        const int c = tid >> 2, u = tid & 3, prow = u >> 1, xseg = (u & 1) * 32; \
        const uint32_t* rowp = (const uint32_t*)(Strip + ((KCN) & 1) * 10240 + c * 160 + prow * 80); \
        const int h0 = 8 + dxd + xseg;                                           \
        uint32_t w[16];                                                          \
        if (dxd & 1) {                                                           \
            int k0i = (h0 - 1) >> 1;                                             \
            uint32_t prev = rowp[k0i];                                           \
            _Pragma("unroll")                                                    \
            for (int j = 0; j < 16; j++) {                                       \
                uint32_t nxt = rowp[k0i + 1 + j];                                \
                w[j] = __funnelshift_r(prev, nxt, 16);                           \
                prev = nxt;                                                      \
            }                                                                    \
        } else {                                                                 \
            int k0i = h0 >> 1;                                                   \
            _Pragma("unroll")                                                    \
            for (int j = 0; j < 16; j++) w[j] = rowp[k0i + j];                   \
        }                                                                        \
        uint4* bd = (uint4*)(Bs + ((KCN) & 1) * 8704 + c * 136 + prow * 64 + xseg); \
        _Pragma("unroll")                                                        \
        for (int j = 0; j < 4; j++)                                              \
            bd[j] = make_uint4(w[4*j], w[4*j+1], w[4*j+2], w[4*j+3]);            \
    }

    float acc[4][4][4] = {};

    // prologue
    ISSUE_S(0); cpcommit();
    cpwait<0>(); __syncthreads();
    BUILD(0);
    ISSUE_S(1); ISSUE_A(0); cpcommit();

    for (int kc = 0; kc < 36; kc++) {
        cpwait<0>();
        __syncthreads();
        // issue next loads
        if (kc + 2 < 36) ISSUE_S(kc + 2);
        if (kc + 1 < 36) ISSUE_A(kc + 1);
        cpcommit();
        // build next B tile (overlaps with MMA below — disjoint buffers)
        if (kc + 1 < 36) BUILD(kc + 1);

        const __half* Ap = A2 + (kc & 1) * 9216;
        const __half* Bp = Bs + (kc & 1) * 8704;
#pragma unroll
        for (int kstep = 0; kstep < 4; kstep++) {
            uint32_t a[4][4], b[4][2];
            {
                const int arow = wm * 64 + ((lane >> 3) & 1) * 8 + (lane & 7);
                const int akc  = kstep * 16 + (lane >> 4) * 8;
#pragma unroll
                for (int mi = 0; mi < 4; mi++)
                    ldsm4(a[mi], Ap + (arow + mi * 16) * 72 + akc);
            }
            {
                const int brow = kstep * 16 + (lane & 7) + ((lane >> 3) & 1) * 8;
#pragma unroll
                for (int ni2 = 0; ni2 < 2; ni2++) {
                    const int bcol = wn * 32 + ni2 * 16 + ((lane >> 4) & 1) * 8;
                    uint32_t r[4];
                    ldsm4t(r, Bp + brow * 136 + bcol);
                    b[2*ni2    ][0] = r[0]; b[2*ni2    ][1] = r[1];
                    b[2*ni2 + 1][0] = r[2]; b[2*ni2 + 1][1] = r[3];
                }
            }
#pragma unroll
            for (int mi = 0; mi < 4; mi++)
#pragma unroll
                for (int ni = 0; ni < 4; ni++)
                    mma16(acc[mi][ni], a[mi], b[ni]);
        }
    }
#undef ISSUE_A
#undef ISSUE_S
#undef BUILD

    const int orow = m0 + wm * 64 + (lane >> 2);
    const int ocol = p0 + wn * 32 + (lane & 3) * 2;
#pragma unroll
    for (int mi = 0; mi < 4; mi++) {
        const int oca = orow + mi * 16;
        const int ocb = oca + 8;
        const float ba = bias[oca], bb = bias[ocb];
#pragma unroll
        for (int ni = 0; ni < 4; ni++) {
            const int n = ocol + ni * 8;
            long ia = ((long)img * 256 + oca) * NPIX + n;
            long ib = ((long)img * 256 + ocb) * NPIX + n;
            float v0 = acc[mi][ni][0] + ba, v1 = acc[mi][ni][1] + ba;
            float v2 = acc[mi][ni][2] + bb, v3 = acc[mi][ni][3] + bb;
            v0 = (v0 > 0.f) ? v0 : 0.2f * v0;
            v1 = (v1 > 0.f) ? v1 : 0.2f * v1;
            v2 = (v2 > 0.f) ? v2 : 0.2f * v2;
            v3 = (v3 > 0.f) ? v3 : 0.2f * v3;
            if (addres) {
                v0 += res[ia]; v1 += res[ia + 1];
                v2 += res[ib]; v3 += res[ib + 1];
            }
            if (out) {
                out[ia] = v0; out[ia + 1] = v1;
                out[ib] = v2; out[ib + 1] = v3;
            }
            if (outh_img) {
                *(__half2*)(outh_img + ia) = __floats2half2_rn(v0, v1);
                *(__half2*)(outh_img + ib) = __floats2half2_rn(v2, v3);
            }
        }
    }
}

// ============================================================================
// fp16 NT GEMM with deterministic split-K (scores), f32 out
// ============================================================================
__global__ void __launch_bounds__(256) hgemm_nt_kernel(
    const __half* __restrict__ A, const __half* __restrict__ B, float* __restrict__ C,
    int N, int K, int splitk, long sAB, long sC)
{
    __shared__ __half As[128 * 40];
    __shared__ __half Bs[128 * 40];
    const int tid = threadIdx.x;
    const int lane = tid & 31, wid = tid >> 5;
    const int wm = wid & 1, wn = wid >> 1;
    const int n0 = blockIdx.x * 128, m0 = blockIdx.y * 128;
    const int z = blockIdx.z, bat = z / splitk, ks = z - bat * splitk;
    A += (long)bat * sAB;
    B += (long)bat * sAB;
    C += (long)z * sC;
    const int kchunk = K / splitk, kbeg = ks * kchunk;
    const int wr = tid >> 1, wkh = (tid & 1) * 16;

    float acc[4][4][4] = {};
    for (int k0 = kbeg; k0 < kbeg + kchunk; k0 += 32) {
        __syncthreads();
        {
            const __half* sa = A + (long)(m0 + wr) * K + k0 + wkh;
            const __half* sb = B + (long)(n0 + wr) * K + k0 + wkh;
            *(uint4*)(As + wr * 40 + wkh)     = *(const uint4*)sa;
            *(uint4*)(As + wr * 40 + wkh + 8) = *(const uint4*)(sa + 8);
            *(uint4*)(Bs + wr * 40 + wkh)     = *(const uint4*)sb;
            *(uint4*)(Bs + wr * 40 + wkh + 8) = *(const uint4*)(sb + 8);
        }
        __syncthreads();
#pragma unroll
        for (int kstep = 0; kstep < 2; kstep++) {
            uint32_t a[4][4], b[4][2];
            {
                const int arow = wm * 64 + ((lane >> 3) & 1) * 8 + (lane & 7);
                const int akc  = kstep * 16 + (lane >> 4) * 8;
#pragma unroll
                for (int mi = 0; mi < 4; mi++)
                    ldsm4(a[mi], As + (arow + mi * 16) * 40 + akc);
            }
            {
                const int bkc = kstep * 16 + ((lane >> 3) & 1) * 8;
#pragma unroll
                for (int ni2 = 0; ni2 < 2; ni2++) {
                    const int brow = wn * 32 + ni2 * 16 + ((lane >> 4) & 1) * 8 + (lane & 7);
                    uint32_t r[4];
                    ldsm4(r, Bs + brow * 40 + bkc);
                    b[2*ni2    ][0] = r[0]; b[2*ni2    ][1] = r[1];
                    b[2*ni2 + 1][0] = r[2]; b[2*ni2 + 1][1] = r[3];
                }
            }
#pragma unroll
            for (int mi = 0; mi < 4; mi++)
#pragma unroll
                for (int ni = 0; ni < 4; ni++)
                    mma16(acc[mi][ni], a[mi], b[ni]);
        }
    }
    const int orow = m0 + wm * 64 + (lane >> 2);
    const int ocol = n0 + wn * 32 + (lane & 3) * 2;
#pragma unroll
    for (int mi = 0; mi < 4; mi++) {
        long ra = (long)(orow + mi * 16) * N;
        long rb = (long)(orow + mi * 16 + 8) * N;
#pragma unroll
        for (int ni = 0; ni < 4; ni++) {
            int n = ocol + ni * 8;
            C[ra + n] = acc[mi][ni][0]; C[ra + n + 1] = acc[mi][ni][1];
            C[rb + n] = acc[mi][ni][2]; C[rb + n + 1] = acc[mi][ni][3];
        }
    }
}

// ============================================================================
// fp16 AV GEMM (probs in HALF, NN via trans-ldmatrix B), scatter -> half image
// ============================================================================
__global__ void __launch_bounds__(256) hgemm_av_kernel(
    const __half* __restrict__ S, const __half* __restrict__ V, __half* __restrict__ out,
    int n, int d, int lp, int c0)
{
    __shared__ __half As[128 * 40];
    __shared__ __half Bs[32 * 136];
    const int tid = threadIdx.x;
    const int lane = tid & 31, wid = tid >> 5;
    const int wm = wid & 1, wn = wid >> 1;
    const int z = blockIdx.z;
    S += (long)z * n * n;
    V += (long)z * n * d;
    const int n0 = blockIdx.x * 128;
    const int m0 = blockIdx.y * 128;
    const int wr = tid >> 1, wkh = (tid & 1) * 16;
    const int bk = tid >> 3, bn0 = (tid & 7) * 16;

    float acc[4][4][4] = {};
    for (int k0 = 0; k0 < n; k0 += 32) {
        __syncthreads();
        {
            const __half* sa = S + (long)(m0 + wr) * n + k0 + wkh;
            *(uint4*)(As + wr * 40 + wkh)     = *(const uint4*)sa;
            *(uint4*)(As + wr * 40 + wkh + 8) = *(const uint4*)(sa + 8);
            const __half* sb = V + (long)(k0 + bk) * d + n0 + bn0;
            *(uint4*)(Bs + bk * 136 + bn0)     = *(const uint4*)sb;
            *(uint4*)(Bs + bk * 136 + bn0 + 8) = *(const uint4*)(sb + 8);
        }
        __syncthreads();
#pragma unroll
        for (int kstep = 0; kstep < 2; kstep++) {
            uint32_t a[4][4], b[4][2];
            {
                const int arow = wm * 64 + ((lane >> 3) & 1) * 8 + (lane & 7);
                const int akc  = kstep * 16 + (lane >> 4) * 8;
#pragma unroll
                for (int mi = 0; mi < 4; mi++)
                    ldsm4(a[mi], As + (arow + mi * 16) * 40 + akc);
            }
            {
                const int brow = kstep * 16 + (lane & 7) + ((lane >> 3) & 1) * 8;
#pragma unroll
                for (int ni2 = 0; ni2 < 2; ni2++) {
                    const int bcol = wn * 32 + ni2 * 16 + ((lane >> 4) & 1) * 8;
                    uint32_t r[4];
                    ldsm4t(r, Bs + brow * 136 + bcol);
                    b[2*ni2    ][0] = r[0]; b[2*ni2    ][1] = r[1];
                    b[2*ni2 + 1][0] = r[2]; b[2*ni2 + 1][1] = r[3];
                }
            }
#pragma unroll
            for (int mi = 0; mi < 4; mi++)
#pragma unroll
                for (int ni = 0; ni < 4; ni++)
                    mma16(acc[mi][ni], a[mi], b[ni]);
        }
    }

    const int lo = 6 - lp;
    const int orow = m0 + wm * 64 + (lane >> 2);
    const int ocol = n0 + wn * 32 + (lane & 3) * 2;
#pragma unroll
    for (int mi = 0; mi < 4; mi++) {
#pragma unroll
        for (int hf = 0; hf < 2; hf++) {
            const int m = orow + mi * 16 + hf * 8;
            const int t = m >> (2 * lo);
            const int r = m & ((1 << (2 * lo)) - 1);
            const int ohi = r >> lo, owi = r & ((1 << lo) - 1);
#pragma unroll
            for (int ni = 0; ni < 4; ni++) {
                const int col = ocol + ni * 8;
                const int cc = col >> (2 * lp);
                const int rr = col & ((1 << (2 * lp)) - 1);
                const int pi = rr >> lp, pj = rr & ((1 << lp) - 1);
                long dst = ((long)((z * 8 + t) * 256 + c0 + cc) << 12)
                         + (((ohi << lp) + pi) << 6) + (owi << lp) + pj;
                *(__half2*)(out + dst) = __floats2half2_rn(acc[mi][ni][hf*2], acc[mi][ni][hf*2 + 1]);
            }
        }
    }
}

// ============================================================================
// fp16 mma 32x32 NT split-K (P=32 scores): 2 warps, cross-warp smem reduce
// ============================================================================
__global__ void __launch_bounds__(64) hgemm32_kernel(
    const __half* __restrict__ A, const __half* __restrict__ B, float* __restrict__ C,
    int K, int splitk)
{
    __shared__ __half Qs[32 * 136];
    __shared__ __half Ks[32 * 136];
    __shared__ float buf[32][33];
    const int tid = threadIdx.x;
    const int lane = tid & 31, wrp = tid >> 5;
    const int z = blockIdx.z, bat = z / splitk, ks = z - bat * splitk;
    A += (long)bat * 32 * K;
    B += (long)bat * 32 * K;
    const int kchunk = K / splitk, kbeg = ks * kchunk;

    float acc[2][4][4] = {};
    for (int k0 = kbeg; k0 < kbeg + kchunk; k0 += 128) {
        __syncthreads();
#pragma unroll
        for (int i = 0; i < 8; i++) {
            int u = i * 64 + tid;
            int row = u >> 4, seg = (u & 15) * 8;
            *(uint4*)(Qs + row * 136 + seg) = *(const uint4*)(A + (long)row * K + k0 + seg);
            *(uint4*)(Ks + row * 136 + seg) = *(const uint4*)(B + (long)row * K + k0 + seg);
        }
        __syncthreads();
        for (int s = wrp; s < 8; s += 2) {
            const int kc = s * 16;
            uint32_t a[2][4], b[4][2];
            {
                const int arow = ((lane >> 3) & 1) * 8 + (lane & 7);
                const int akc  = kc + (lane >> 4) * 8;
                ldsm4(a[0], Qs + arow * 136 + akc);
                ldsm4(a[1], Qs + (arow + 16) * 136 + akc);
            }
            {
                const int bkc = kc + ((lane >> 3) & 1) * 8;
#pragma unroll
                for (int ni2 = 0; ni2 < 2; ni2++) {
                    const int brow = ni2 * 16 + ((lane >> 4) & 1) * 8 + (lane & 7);
                    uint32_t r[4];
                    ldsm4(r, Ks + brow * 136 + bkc);
                    b[2*ni2    ][0] = r[0]; b[2*ni2    ][1] = r[1];
                    b[2*ni2 + 1][0] = r[2]; b[2*ni2 + 1][1] = r[3];
                }
            }
#pragma unroll
            for (int mi = 0; mi < 2; mi++)
#pragma unroll
                for (int ni = 0; ni < 4; ni++)
                    mma16(acc[mi][ni], a[mi], b[ni]);
        }
    }

    const int rr = lane >> 2, cc = (lane & 3) * 2;
    if (wrp == 0) {
#pragma unroll
        for (int mi = 0; mi < 2; mi++)
#pragma unroll
            for (int ni = 0; ni < 4; ni++) {
                buf[mi*16 + rr    ][ni*8 + cc]     = acc[mi][ni][0];
                buf[mi*16 + rr    ][ni*8 + cc + 1] = acc[mi][ni][1];
                buf[mi*16 + rr + 8][ni*8 + cc]     = acc[mi][ni][2];
                buf[mi*16 + rr + 8][ni*8 + cc + 1] = acc[mi][ni][3];
            }
    }
    __syncthreads();
    if (wrp == 1) {
#pragma unroll
        for (int mi = 0; mi < 2; mi++)
#pragma unroll
            for (int ni = 0; ni < 4; ni++) {
                buf[mi*16 + rr    ][ni*8 + cc]     += acc[mi][ni][0];
                buf[mi*16 + rr    ][ni*8 + cc + 1] += acc[mi][ni][1];
                buf[mi*16 + rr + 8][ni*8 + cc]     += acc[mi][ni][2];
                buf[mi*16 + rr + 8][ni*8 + cc + 1] += acc[mi][ni][3];
            }
    }
    __syncthreads();
    float* Cz = C + (long)z * 1024;
    for (int i = tid; i < 1024; i += 64)
        Cz[i] = buf[i >> 5][i & 31];
}

__global__ void reduce_splitk_kernel(const float* __restrict__ part, float* __restrict__ S,
                                     int per, int splitk)
{
    long idx = (long)blockIdx.x * 256 + threadIdx.x;
    int b = (int)(idx / per);
    int r = (int)(idx - (long)b * per);
    float s = 0.f;
    for (int ks = 0; ks < splitk; ks++)
        s += part[(long)(b * splitk + ks) * per + r];
    S[idx] = s;
}

// ===================== SIMT AV for P=32 (probs half, half V, half out) ============
__global__ void __launch_bounds__(256) gemm_av32_kernel(
    const __half* __restrict__ A, const __half* __restrict__ B, __half* __restrict__ out,
    int n, int d, int lp, int c0)
{
    const int z = blockIdx.z;
    A += (long)z * n * n;
    B += (long)z * n * d;
    const int m0 = blockIdx.y * 64, n0 = blockIdx.x * 64;
    __shared__ __align__(16) float As[16][68];
    __shared__ __align__(16) float Bs[16][64];
    const int tid = threadIdx.x;
    const int tx = tid & 15, ty = tid >> 4;
    float acc[4][4] = {};
    for (int k0 = 0; k0 < n; k0 += 16) {
#pragma unroll
        for (int it = 0; it < 4; it++) {
            int id = tid + it * 256;
            int m = id >> 4, kk = id & 15;
            As[kk][m] = (m0 + m < n) ? __half2float(A[(long)(m0 + m) * n + k0 + kk]) : 0.f;
        }
#pragma unroll
        for (int it = 0; it < 4; it++) {
            int id = tid + it * 256;
            int kk = id >> 6, nnn = id & 63;
            Bs[kk][nnn] = __half2float(B[(long)(k0 + kk) * d + n0 + nnn]);
        }
        __syncthreads();
#pragma unroll
        for (int kk = 0; kk < 16; kk++) {
            float4 a4 = *(const float4*)&As[kk][ty * 4];
            float4 b4 = *(const float4*)&Bs[kk][tx * 4];
            float ar[4] = {a4.x, a4.y, a4.z, a4.w};
            float br[4] = {b4.x, b4.y, b4.z, b4.w};
#pragma unroll
            for (int i = 0; i < 4; i++)
#pragma unroll
                for (int j = 0; j < 4; j++)
                    acc[i][j] += ar[i] * br[j];
        }
        __syncthreads();
    }
    const int lo = 6 - lp, o = 1 << lo, P = 1 << lp;
#pragma unroll
    for (int i = 0; i < 4; i++) {
        int m = m0 + ty * 4 + i;
        if (m >= n) continue;
        int t = m >> (2 * lo);
        int r = m & ((1 << (2 * lo)) - 1);
        int ohi = r >> lo, owi = r & (o - 1);
        int col = n0 + tx * 4;
        int cc = col >> (2 * lp);
        int rr = col & (P * P - 1);
        int pi = rr >> lp, pj = rr & (P - 1);
        long dst = ((long)((z * 8 + t) * 256 + c0 + cc) << 12)
                 + (((ohi << lp) + pi) << 6) + (owi << lp) + pj;
        *(__half2*)(out + dst)     = __floats2half2_rn(acc[i][0], acc[i][1]);
        *(__half2*)(out + dst + 2) = __floats2half2_rn(acc[i][2], acc[i][3]);
    }
}

// ===================== softmax (row-wise, scale folded in, HALF out) ==============
__global__ void softmax_kernel(const float* __restrict__ S, __half* __restrict__ Sh,
                               int n, float scale)
{
    __shared__ float buf[2048];
    __shared__ float red[256];
    const long row = blockIdx.x;
    const float* p = S + row * (long)n;
    __half* ph = Sh + row * (long)n;
    const int tid = threadIdx.x;
    float m = -1e30f;
    for (int i = tid; i < n; i += 256) { float v = p[i] * scale; buf[i] = v; m = fmaxf(m, v); }
    red[tid] = m; __syncthreads();
    for (int s = 128; s > 0; s >>= 1) { if (tid < s) red[tid] = fmaxf(red[tid], red[tid + s]); __syncthreads(); }
    m = red[0]; __syncthreads();
    float sum = 0.f;
    for (int i = tid; i < n; i += 256) { float e = expf(buf[i] - m); buf[i] = e; sum += e; }
    red[tid] = sum; __syncthreads();
    for (int s = 128; s > 0; s >>= 1) { if (tid < s) red[tid] += red[tid + s]; __syncthreads(); }
    float inv = 1.f / red[0];
    for (int i = tid; i < n; i += 256) ph[i] = __float2half(buf[i] * inv);
}

// ===================== launcher ===================================================
extern "C" void kernel_launch(void* const* d_in, const int* in_sizes, int n_in,
                              void* d_out, int out_size)
{
    const float* xs  = (const float*)d_in[0];
    const float* Wq  = (const float*)d_in[2];
    const float* bq  = (const float*)d_in[3];
    const float* Wk  = (const float*)d_in[4];
    const float* bk  = (const float*)d_in[5];
    const float* Wv  = (const float*)d_in[6];
    const float* bv  = (const float*)d_in[7];
    const float* Wl  = (const float*)d_in[8];
    const float* bl  = (const float*)d_in[9];
    const float* Wf1 = (const float*)d_in[10];
    const float* bf1 = (const float*)d_in[11];
    const float* Wf2 = (const float*)d_in[12];
    const float* bf2 = (const float*)d_in[13];
    float* out = (float*)d_out;

    __half *gQp, *gKp, *gVp, *gXsh, *gAtth, *gXs1h, *gFfh, *gSh;
    __half *gWqh, *gWkh, *gWvh, *gWlh, *gWf1h, *gWf2h;
    float *gS, *gPart, *gXs1;
    cudaGetSymbolAddress((void**)&gQp,   g_Qp);
    cudaGetSymbolAddress((void**)&gKp,   g_Kp);
    cudaGetSymbolAddress((void**)&gVp,   g_Vp);
    cudaGetSymbolAddress((void**)&gS,    g_S);
    cudaGetSymbolAddress((void**)&gSh,   g_Sh);
    cudaGetSymbolAddress((void**)&gPart, g_part);
    cudaGetSymbolAddress((void**)&gXs1,  g_xs1);
    cudaGetSymbolAddress((void**)&gXsh,  g_xsh);
    cudaGetSymbolAddress((void**)&gAtth, g_atth);
    cudaGetSymbolAddress((void**)&gXs1h, g_xs1h);
    cudaGetSymbolAddress((void**)&gFfh,  g_ffh);
    cudaGetSymbolAddress((void**)&gWqh,  g_Wqh);
    cudaGetSymbolAddress((void**)&gWkh,  g_Wkh);
    cudaGetSymbolAddress((void**)&gWvh,  g_Wvh);
    cudaGetSymbolAddress((void**)&gWlh,  g_Wlh);
    cudaGetSymbolAddress((void**)&gWf1h, g_Wf1h);
    cudaGetSymbolAddress((void**)&gWf2h, g_Wf2h);

    cudaFuncSetAttribute(hconvK_kernel,
                         cudaFuncAttributeMaxDynamicSharedMemorySize, HK_SMEM);

    dim3 blk(256);
    dim3 qgrid(NIMG * 32, 2);

    // pre-convert inputs + weights (convs: transpose to tap-major)
    f2h_kernel<<<16384, blk>>>(xs,  gXsh);
    f2h_kernel<<<64,    blk>>>(Wq,  gWqh);
    f2h_kernel<<<64,    blk>>>(Wk,  gWkh);
    f2h_kernel<<<64,    blk>>>(Wv,  gWvh);
    wtrans_kernel<<<2304, blk>>>(Wl,  gWlh);
    wtrans_kernel<<<2304, blk>>>(Wf1, gWf1h);
    wtrans_kernel<<<2304, blk>>>(Wf2, gWf2h);

    // QKV projections -> patchified half buffers (bias fused)
    hconv2_kernel<<<qgrid, blk>>>(gXsh, gWqh, bq, gQp);
    hconv2_kernel<<<qgrid, blk>>>(gXsh, gWkh, bk, gKp);
    hconv2_kernel<<<qgrid, blk>>>(gXsh, gWvh, bv, gVp);

    // ---- P=32 (n=32, d=65536) ----
    {
        const int n = 32, d = 65536, splitk = 256;
        hgemm32_kernel<<<dim3(1, 1, 2 * splitk), 64>>>(gQp, gKp, gPart, d, splitk);
        reduce_splitk_kernel<<<(2 * n * n) / 256, blk>>>(gPart, gS, n * n, splitk);
        softmax_kernel<<<2 * n, blk>>>(gS, gSh, n, 1.0f / 256.0f);
        gemm_av32_kernel<<<dim3(d / 64, 1, 2), blk>>>(gSh, gVp, gAtth, n, d, 5, 0);
    }
    // ---- P=16 (n=128, d=16384) ----
    {
        const int n = 128, d = 16384, splitk = 64;
        const long soff = 4194304;
        hgemm_nt_kernel<<<dim3(1, 1, 2 * splitk), blk>>>(
            gQp + soff, gKp + soff, gPart, n, d, splitk, (long)n * d, (long)n * n);
        reduce_splitk_kernel<<<(2 * n * n) / 256, blk>>>(gPart, gS, n * n, splitk);
        softmax_kernel<<<2 * n, blk>>>(gS, gSh, n, 1.0f / 128.0f);
        hgemm_av_kernel<<<dim3(d / 128, n / 128, 2), blk>>>(gSh, gVp + soff, gAtth, n, d, 4, 64);
    }
    // ---- P=8 (n=512, d=4096) ----
    {
        const int n = 512, d = 4096, splitk = 8;
        const long soff = 2L * 4194304;
        hgemm_nt_kernel<<<dim3(n / 128, n / 128, 2 * splitk), blk>>>(
            gQp + soff, gKp + soff, gPart, n, d, splitk, (long)n * d, (long)n * n);
        reduce_splitk_kernel<<<(2 * n * n) / 256, blk>>>(gPart, gS, n * n, splitk);
        softmax_kernel<<<2 * n, blk>>>(gS, gSh, n, 1.0f / 64.0f);
        hgemm_av_kernel<<<dim3(d / 128, n / 128, 2), blk>>>(gSh, gVp + soff, gAtth, n, d, 3, 128);
    }
    // ---- P=4 (n=2048, d=1024) ----
    {
        const int n = 2048, d = 1024;
        const long soff = 3L * 4194304;
        hgemm_nt_kernel<<<dim3(n / 128, n / 128, 2), blk>>>(
            gQp + soff, gKp + soff, gS, n, d, 1, (long)n * d, (long)n * n);
        softmax_kernel<<<2 * n, blk>>>(gS, gSh, n, 1.0f / 32.0f);
        hgemm_av_kernel<<<dim3(d / 128, n / 128, 2), blk>>>(gSh, gVp + soff, gAtth, n, d, 2, 192);
    }

    // convs: 128-pixel tiles, K-chunk 64, single-barrier pipeline (hconvK v2)
    hconvK_kernel<<<qgrid, blk, HK_SMEM>>>(gAtth, gWlh,  bl,  xs,      gXs1,    gXs1h, 1, 1);
    hconvK_kernel<<<qgrid, blk, HK_SMEM>>>(gXs1h, gWf1h, bf1, nullptr, nullptr, gFfh,  1, 0);
    hconvK_kernel<<<qgrid, blk, HK_SMEM>>>(gFfh,  gWf2h, bf2, gXs1,    out,     nullptr, 2, 1);
}

// round 11
// speedup vs baseline: 1.0432x; 1.0432x over previous
#include <cuda_runtime.h>
#include <cuda_fp16.h>
#include <math.h>
#include <stdint.h>

#define NIMG 16
#define CCH 256
#define NPIX 4096            // 64*64

// ---- scratch (static device globals; no allocation) ----
__device__ __half g_Qp[16777216];
__device__ __half g_Kp[16777216];
__device__ __half g_Vp[16777216];
__device__ float  g_S[2*2048*2048];
__device__ __half g_Sh[2*2048*2048];
__device__ float  g_part[8388608];
__device__ float  g_xs1[NIMG*CCH*NPIX];
__device__ __half g_xsh [NIMG*CCH*NPIX];
__device__ __half g_atth[NIMG*CCH*NPIX];
__device__ __half g_xs1h[NIMG*CCH*NPIX];
__device__ __half g_ffh [NIMG*CCH*NPIX];
__device__ __half g_Wqh[65536], g_Wkh[65536], g_Wvh[65536];
__device__ __half g_Wlh[589824], g_Wf1h[589824], g_Wf2h[589824];   // tap-major

// ============================================================================
// helpers
// ============================================================================
__device__ __forceinline__ void mma16(float* d, const uint32_t* a, const uint32_t* b) {
    asm volatile(
        "mma.sync.aligned.m16n8k16.row.col.f32.f16.f16.f32 "
        "{%0,%1,%2,%3}, {%4,%5,%6,%7}, {%8,%9}, {%0,%1,%2,%3};"
        : "+f"(d[0]), "+f"(d[1]), "+f"(d[2]), "+f"(d[3])
        : "r"(a[0]), "r"(a[1]), "r"(a[2]), "r"(a[3]), "r"(b[0]), "r"(b[1]));
}

__device__ __forceinline__ void ldsm4(uint32_t* r, const void* p) {
    uint32_t addr = (uint32_t)__cvta_generic_to_shared(p);
    asm volatile("ldmatrix.sync.aligned.m8n8.x4.shared.b16 {%0,%1,%2,%3}, [%4];"
        : "=r"(r[0]), "=r"(r[1]), "=r"(r[2]), "=r"(r[3]) : "r"(addr));
}

__device__ __forceinline__ void ldsm4t(uint32_t* r, const void* p) {
    uint32_t addr = (uint32_t)__cvta_generic_to_shared(p);
    asm volatile("ldmatrix.sync.aligned.m8n8.x4.trans.shared.b16 {%0,%1,%2,%3}, [%4];"
        : "=r"(r[0]), "=r"(r[1]), "=r"(r[2]), "=r"(r[3]) : "r"(addr));
}

__device__ __forceinline__ uint32_t pack_h2(float a, float b) {
    __half2 h = __floats2half2_rn(a, b);
    return *(uint32_t*)&h;
}

__device__ __forceinline__ void cpa16(uint32_t dst, const void* src, unsigned sz) {
    asm volatile("cp.async.ca.shared.global [%0], [%1], 16, %2;"
                 :: "r"(dst), "l"(src), "r"(sz) : "memory");
}
__device__ __forceinline__ void cpcommit() {
    asm volatile("cp.async.commit_group;" ::: "memory");
}
template <int N>
__device__ __forceinline__ void cpwait() {
    asm volatile("cp.async.wait_group %0;" :: "n"(N) : "memory");
}

// f32 -> f16 bulk convert (exact multiples of 1024 elems)
__global__ void f2h_kernel(const float* __restrict__ src, __half* __restrict__ dst) {
    long i = ((long)blockIdx.x * 256 + threadIdx.x) * 4;
    float4 v = *(const float4*)(src + i);
    *(uint32_t*)(dst + i)     = pack_h2(v.x, v.y);
    *(uint32_t*)(dst + i + 2) = pack_h2(v.z, v.w);
}

// conv weight transpose+convert: W[oc][c][tap] f32 -> Wt2[oc][tap][c] half
__global__ void wtrans_kernel(const float* __restrict__ W, __half* __restrict__ Wt2) {
    int idx = blockIdx.x * 256 + threadIdx.x;
    int oc = idx / 2304, r = idx - oc * 2304;
    int tap = r >> 8, c = r & 255;
    Wt2[idx] = __float2half(W[oc * 2304 + c * 9 + tap]);
}

// scatter index into patchified buffer: scale = oc>>6
__device__ __forceinline__ long pat_index(int img, int oc, int pix) {
    int s  = oc >> 6, cc = oc & 63;
    int lp = 5 - s;
    int lo = 1 + s;
    int Pm = (1 << lp) - 1;
    int y = pix >> 6, x = pix & 63;
    int ohi = y >> lp, pi = y & Pm, owi = x >> lp, pj = x & Pm;
    int t = img & 7, b = img >> 3;
    int nn = (t << (2*lo)) + (ohi << lo) + owi;
    int dd = (cc << (2*lp)) + (pi << lp) + pj;
    return (long)s * 4194304 + (long)b * 2097152 + (long)nn * (64 << (2*lp)) + dd;
}

// ============================================================================
// hconv2 (ks==1): QKV projection, cp.async pipelined, 256 threads
// ============================================================================
__global__ void __launch_bounds__(256, 2) hconv2_kernel(
    const __half* __restrict__ in, const __half* __restrict__ Wt,
    const float* __restrict__ bias, __half* __restrict__ outh_pat)
{
    __shared__ __half A2[2 * 128 * 40];
    __shared__ __half B2[2 * 32 * 136];

    const int tid = threadIdx.x;
    const int lane = tid & 31, wid = tid >> 5;
    const int wm = wid & 1, wn = wid >> 1;
    const int img = blockIdx.x >> 5;
    const int p0 = (blockIdx.x & 31) * 128;
    const int m0 = blockIdx.y * 128;
    const __half* inimg = in + (long)img * CCH * NPIX;

    const uint32_t sA2 = (uint32_t)__cvta_generic_to_shared(A2);
    const uint32_t sB2 = (uint32_t)__cvta_generic_to_shared(B2);

#define ISSUE1(KCN, NB)                                                         \
    {                                                                           \
        const int k0n = (KCN) * 32;                                             \
        {                                                                       \
            int row = tid >> 1, seg = (tid & 1) * 16;                           \
            const __half* src = Wt + (long)(m0 + row) * 256 + k0n + seg;        \
            uint32_t dst = sA2 + (uint32_t)(((NB) * 5120 + row * 40 + seg) * 2);\
            cpa16(dst, src, 16u); cpa16(dst + 16, src + 8, 16u);                \
        }                                                                       \
        {                                                                       \
            int k = tid >> 3, u = tid & 7;                                      \
            const __half* src = inimg + ((long)(k0n + k) << 12) + p0 + u * 8;   \
            uint32_t dst = sB2 + (uint32_t)(((NB) * 4352 + k * 136 + u * 8) * 2); \
            cpa16(dst, src, 16u);                                               \
            cpa16(dst + 128, src + 64, 16u);                                    \
        }                                                                       \
        cpcommit();                                                             \
    }

    float acc[4][4][4] = {};
    ISSUE1(0, 0);

    for (int kc = 0; kc < 8; kc++) {
        cpwait<0>();
        __syncthreads();
        if (kc + 1 < 8) ISSUE1(kc + 1, (kc + 1) & 1);

        const __half* Ap = A2 + (kc & 1) * 5120;
        const __half* Bp = B2 + (kc & 1) * 4352;
#pragma unroll
        for (int kstep = 0; kstep < 2; kstep++) {
            uint32_t a[4][4], b[4][2];
            {
                const int arow = wm * 64 + ((lane >> 3) & 1) * 8 + (lane & 7);
                const int akc  = kstep * 16 + (lane >> 4) * 8;
#pragma unroll
                for (int mi = 0; mi < 4; mi++)
                    ldsm4(a[mi], Ap + (arow + mi * 16) * 40 + akc);
            }
            {
                const int brow = kstep * 16 + (lane & 7) + ((lane >> 3) & 1) * 8;
#pragma unroll
                for (int ni2 = 0; ni2 < 2; ni2++) {
                    const int bcol = wn * 32 + ni2 * 16 + ((lane >> 4) & 1) * 8;
                    uint32_t r[4];
                    ldsm4t(r, Bp + brow * 136 + bcol);
                    b[2*ni2    ][0] = r[0]; b[2*ni2    ][1] = r[1];
                    b[2*ni2 + 1][0] = r[2]; b[2*ni2 + 1][1] = r[3];
                }
            }
#pragma unroll
            for (int mi = 0; mi < 4; mi++)
#pragma unroll
                for (int ni = 0; ni < 4; ni++)
                    mma16(acc[mi][ni], a[mi], b[ni]);
        }
    }
#undef ISSUE1

    const int orow = m0 + wm * 64 + (lane >> 2);
    const int ocol = p0 + wn * 32 + (lane & 3) * 2;
#pragma unroll
    for (int mi = 0; mi < 4; mi++) {
        const int oca = orow + mi * 16, ocb = oca + 8;
        const float ba = bias[oca], bb = bias[ocb];
#pragma unroll
        for (int ni = 0; ni < 4; ni++) {
            const int n = ocol + ni * 8;
            long ia = pat_index(img, oca, n);
            long ib = pat_index(img, ocb, n);
            *(__half2*)(outh_pat + ia) = __floats2half2_rn(acc[mi][ni][0] + ba, acc[mi][ni][1] + ba);
            *(__half2*)(outh_pat + ib) = __floats2half2_rn(acc[mi][ni][2] + bb, acc[mi][ni][3] + bb);
        }
    }
}

// ============================================================================
// hconvK (R9 structure): 3x3 conv, tap-major K, 256 threads, M=128 x N=128,
//   K-chunk 64, A double-buffered, Strip/Bs single-buffered, 2 barriers/chunk
//   dyn smem (halves): A2[2*128*72] | Bs[64*136] | Strip[64*160]
// ============================================================================
#define HK_A2    0
#define HK_BS    18432
#define HK_STRIP (18432 + 8704)
#define HK_SMEM  ((18432 + 8704 + 10240) * 2)

__global__ void __launch_bounds__(256, 2) hconvK_kernel(
    const __half* __restrict__ in, const __half* __restrict__ Wt,
    const float* __restrict__ bias, const float* __restrict__ res,
    float* __restrict__ out, __half* __restrict__ outh_img,
    int dil, int addres)
{
    extern __shared__ __half sh[];
    __half* A2    = sh + HK_A2;
    __half* Bs    = sh + HK_BS;
    __half* Strip = sh + HK_STRIP;

    const int tid = threadIdx.x;
    const int lane = tid & 31, wid = tid >> 5;
    const int wm = wid & 1, wn = wid >> 1;
    const int img = blockIdx.x >> 5;
    const int p0 = (blockIdx.x & 31) * 128;
    const int y0 = p0 >> 6;                 // 2 image rows: y0, y0+1
    const int m0 = blockIdx.y * 128;
    const __half* inimg = in + (long)img * CCH * NPIX;

    const uint32_t sA2    = (uint32_t)__cvta_generic_to_shared(A2);
    const uint32_t sStrip = (uint32_t)__cvta_generic_to_shared(Strip);

    // zero strip halos once
    {
        int c = tid >> 2, u = tid & 3, r = u >> 1, side = u & 1;
        *(uint4*)(Strip + c * 160 + r * 80 + side * 72) = make_uint4(0, 0, 0, 0);
    }

#define ISSUEK(KCN, NB)                                                          \
    {                                                                            \
        const int k0n = (KCN) * 64;                                              \
        {   /* A: 128 oc x 64 k */                                               \
            int row = tid >> 1, seg = (tid & 1) * 32;                            \
            const __half* src = Wt + (long)(m0 + row) * 2304 + k0n + seg;        \
            uint32_t dst = sA2 + (uint32_t)(((NB) * 9216 + row * 72 + seg) * 2); \
            cpa16(dst,      src,      16u);                                      \
            cpa16(dst + 16, src + 8,  16u);                                      \
            cpa16(dst + 32, src + 16, 16u);                                      \
            cpa16(dst + 48, src + 24, 16u);                                      \
        }                                                                        \
        {   /* strip: 64 ch x 2 rows x 64 px */                                  \
            int tapn = (KCN) >> 2;                                               \
            int c0 = (k0n) & 255;                                                \
            int dyd = (tapn / 3 - 1) * dil;                                      \
            int c = tid >> 2, u = tid & 3;                                       \
            int r = u >> 1, s = u & 1;                                           \
            int gy = y0 + r + dyd;                                               \
            unsigned ok = ((unsigned)gy < 64u) ? 16u : 0u;                       \
            int gyc = gy < 0 ? 0 : (gy > 63 ? 63 : gy);                          \
            const __half* src = inimg + ((long)(c0 + c) << 12) + (gyc << 6) + s * 32; \
            uint32_t dst = sStrip + (uint32_t)((c * 160 + r * 80 + 8 + s * 32) * 2);  \
            cpa16(dst,      src,      ok);                                       \
            cpa16(dst + 16, src + 8,  ok);                                       \
            cpa16(dst + 32, src + 16, ok);                                       \
            cpa16(dst + 48, src + 24, ok);                                       \
        }                                                                        \
        cpcommit();                                                              \
    }

    float acc[4][4][4] = {};
    ISSUEK(0, 0);

    for (int kc = 0; kc < 36; kc++) {
        cpwait<0>();
        __syncthreads();

        // build shifted B tile (64 k-rows x 128 px) from strip
        {
            const int tap = kc >> 2;
            const int dxd = (tap - (tap / 3) * 3 - 1) * dil;
            const int c = tid >> 2, u = tid & 3, prow = u >> 1, xseg = (u & 1) * 32;
            const uint32_t* rowp = (const uint32_t*)(Strip + c * 160 + prow * 80);
            const int h0 = 8 + dxd + xseg;
            uint32_t w[16];
            if (dxd & 1) {
                int k0 = (h0 - 1) >> 1;
                uint32_t prev = rowp[k0];
#pragma unroll
                for (int j = 0; j < 16; j++) {
                    uint32_t nxt = rowp[k0 + 1 + j];
                    w[j] = __funnelshift_r(prev, nxt, 16);
                    prev = nxt;
                }
            } else {
                int k0 = h0 >> 1;
#pragma unroll
                for (int j = 0; j < 16; j++) w[j] = rowp[k0 + j];
            }
            uint4* bd = (uint4*)(Bs + c * 136 + prow * 64 + xseg);
#pragma unroll
            for (int j = 0; j < 4; j++)
                bd[j] = make_uint4(w[4*j], w[4*j+1], w[4*j+2], w[4*j+3]);
        }
        __syncthreads();

        if (kc + 1 < 36) ISSUEK(kc + 1, (kc + 1) & 1);

        const __half* Ap = A2 + (kc & 1) * 9216;
#pragma unroll
        for (int kstep = 0; kstep < 4; kstep++) {
            uint32_t a[4][4], b[4][2];
            {
                const int arow = wm * 64 + ((lane >> 3) & 1) * 8 + (lane & 7);
                const int akc  = kstep * 16 + (lane >> 4) * 8;
#pragma unroll
                for (int mi = 0; mi < 4; mi++)
                    ldsm4(a[mi], Ap + (arow + mi * 16) * 72 + akc);
            }
            {
                const int brow = kstep * 16 + (lane & 7) + ((lane >> 3) & 1) * 8;
#pragma unroll
                for (int ni2 = 0; ni2 < 2; ni2++) {
                    const int bcol = wn * 32 + ni2 * 16 + ((lane >> 4) & 1) * 8;
                    uint32_t r[4];
                    ldsm4t(r, Bs + brow * 136 + bcol);
                    b[2*ni2    ][0] = r[0]; b[2*ni2    ][1] = r[1];
                    b[2*ni2 + 1][0] = r[2]; b[2*ni2 + 1][1] = r[3];
                }
            }
#pragma unroll
            for (int mi = 0; mi < 4; mi++)
#pragma unroll
                for (int ni = 0; ni < 4; ni++)
                    mma16(acc[mi][ni], a[mi], b[ni]);
        }
    }
#undef ISSUEK

    const int orow = m0 + wm * 64 + (lane >> 2);
    const int ocol = p0 + wn * 32 + (lane & 3) * 2;
#pragma unroll
    for (int mi = 0; mi < 4; mi++) {
        const int oca = orow + mi * 16;
        const int ocb = oca + 8;
        const float ba = bias[oca], bb = bias[ocb];
#pragma unroll
        for (int ni = 0; ni < 4; ni++) {
            const int n = ocol + ni * 8;
            long ia = ((long)img * 256 + oca) * NPIX + n;
            long ib = ((long)img * 256 + ocb) * NPIX + n;
            float v0 = acc[mi][ni][0] + ba, v1 = acc[mi][ni][1] + ba;
            float v2 = acc[mi][ni][2] + bb, v3 = acc[mi][ni][3] + bb;
            v0 = (v0 > 0.f) ? v0 : 0.2f * v0;
            v1 = (v1 > 0.f) ? v1 : 0.2f * v1;
            v2 = (v2 > 0.f) ? v2 : 0.2f * v2;
            v3 = (v3 > 0.f) ? v3 : 0.2f * v3;
            if (addres) {
                v0 += res[ia]; v1 += res[ia + 1];
                v2 += res[ib]; v3 += res[ib + 1];
            }
            if (out) {
                out[ia] = v0; out[ia + 1] = v1;
                out[ib] = v2; out[ib + 1] = v3;
            }
            if (outh_img) {
                *(__half2*)(outh_img + ia) = __floats2half2_rn(v0, v1);
                *(__half2*)(outh_img + ib) = __floats2half2_rn(v2, v3);
            }
        }
    }
}

// ============================================================================
// fp16 NT GEMM with deterministic split-K (scores), f32 out
// ============================================================================
__global__ void __launch_bounds__(256) hgemm_nt_kernel(
    const __half* __restrict__ A, const __half* __restrict__ B, float* __restrict__ C,
    int N, int K, int splitk, long sAB, long sC)
{
    __shared__ __half As[128 * 40];
    __shared__ __half Bs[128 * 40];
    const int tid = threadIdx.x;
    const int lane = tid & 31, wid = tid >> 5;
    const int wm = wid & 1, wn = wid >> 1;
    const int n0 = blockIdx.x * 128, m0 = blockIdx.y * 128;
    const int z = blockIdx.z, bat = z / splitk, ks = z - bat * splitk;
    A += (long)bat * sAB;
    B += (long)bat * sAB;
    C += (long)z * sC;
    const int kchunk = K / splitk, kbeg = ks * kchunk;
    const int wr = tid >> 1, wkh = (tid & 1) * 16;

    float acc[4][4][4] = {};
    for (int k0 = kbeg; k0 < kbeg + kchunk; k0 += 32) {
        __syncthreads();
        {
            const __half* sa = A + (long)(m0 + wr) * K + k0 + wkh;
            const __half* sb = B + (long)(n0 + wr) * K + k0 + wkh;
            *(uint4*)(As + wr * 40 + wkh)     = *(const uint4*)sa;
            *(uint4*)(As + wr * 40 + wkh + 8) = *(const uint4*)(sa + 8);
            *(uint4*)(Bs + wr * 40 + wkh)     = *(const uint4*)sb;
            *(uint4*)(Bs + wr * 40 + wkh + 8) = *(const uint4*)(sb + 8);
        }
        __syncthreads();
#pragma unroll
        for (int kstep = 0; kstep < 2; kstep++) {
            uint32_t a[4][4], b[4][2];
            {
                const int arow = wm * 64 + ((lane >> 3) & 1) * 8 + (lane & 7);
                const int akc  = kstep * 16 + (lane >> 4) * 8;
#pragma unroll
                for (int mi = 0; mi < 4; mi++)
                    ldsm4(a[mi], As + (arow + mi * 16) * 40 + akc);
            }
            {
                const int bkc = kstep * 16 + ((lane >> 3) & 1) * 8;
#pragma unroll
                for (int ni2 = 0; ni2 < 2; ni2++) {
                    const int brow = wn * 32 + ni2 * 16 + ((lane >> 4) & 1) * 8 + (lane & 7);
                    uint32_t r[4];
                    ldsm4(r, Bs + brow * 40 + bkc);
                    b[2*ni2    ][0] = r[0]; b[2*ni2    ][1] = r[1];
                    b[2*ni2 + 1][0] = r[2]; b[2*ni2 + 1][1] = r[3];
                }
            }
#pragma unroll
            for (int mi = 0; mi < 4; mi++)
#pragma unroll
                for (int ni = 0; ni < 4; ni++)
                    mma16(acc[mi][ni], a[mi], b[ni]);
        }
    }
    const int orow = m0 + wm * 64 + (lane >> 2);
    const int ocol = n0 + wn * 32 + (lane & 3) * 2;
#pragma unroll
    for (int mi = 0; mi < 4; mi++) {
        long ra = (long)(orow + mi * 16) * N;
        long rb = (long)(orow + mi * 16 + 8) * N;
#pragma unroll
        for (int ni = 0; ni < 4; ni++) {
            int n = ocol + ni * 8;
            C[ra + n] = acc[mi][ni][0]; C[ra + n + 1] = acc[mi][ni][1];
            C[rb + n] = acc[mi][ni][2]; C[rb + n + 1] = acc[mi][ni][3];
        }
    }
}

// ============================================================================
// fp16 AV GEMM (probs in HALF, NN via trans-ldmatrix B), scatter -> half image
// ============================================================================
__global__ void __launch_bounds__(256) hgemm_av_kernel(
    const __half* __restrict__ S, const __half* __restrict__ V, __half* __restrict__ out,
    int n, int d, int lp, int c0)
{
    __shared__ __half As[128 * 40];
    __shared__ __half Bs[32 * 136];
    const int tid = threadIdx.x;
    const int lane = tid & 31, wid = tid >> 5;
    const int wm = wid & 1, wn = wid >> 1;
    const int z = blockIdx.z;
    S += (long)z * n * n;
    V += (long)z * n * d;
    const int n0 = blockIdx.x * 128;
    const int m0 = blockIdx.y * 128;
    const int wr = tid >> 1, wkh = (tid & 1) * 16;
    const int bk = tid >> 3, bn0 = (tid & 7) * 16;

    float acc[4][4][4] = {};
    for (int k0 = 0; k0 < n; k0 += 32) {
        __syncthreads();
        {
            const __half* sa = S + (long)(m0 + wr) * n + k0 + wkh;
            *(uint4*)(As + wr * 40 + wkh)     = *(const uint4*)sa;
            *(uint4*)(As + wr * 40 + wkh + 8) = *(const uint4*)(sa + 8);
            const __half* sb = V + (long)(k0 + bk) * d + n0 + bn0;
            *(uint4*)(Bs + bk * 136 + bn0)     = *(const uint4*)sb;
            *(uint4*)(Bs + bk * 136 + bn0 + 8) = *(const uint4*)(sb + 8);
        }
        __syncthreads();
#pragma unroll
        for (int kstep = 0; kstep < 2; kstep++) {
            uint32_t a[4][4], b[4][2];
            {
                const int arow = wm * 64 + ((lane >> 3) & 1) * 8 + (lane & 7);
                const int akc  = kstep * 16 + (lane >> 4) * 8;
#pragma unroll
                for (int mi = 0; mi < 4; mi++)
                    ldsm4(a[mi], As + (arow + mi * 16) * 40 + akc);
            }
            {
                const int brow = kstep * 16 + (lane & 7) + ((lane >> 3) & 1) * 8;
#pragma unroll
                for (int ni2 = 0; ni2 < 2; ni2++) {
                    const int bcol = wn * 32 + ni2 * 16 + ((lane >> 4) & 1) * 8;
                    uint32_t r[4];
                    ldsm4t(r, Bs + brow * 136 + bcol);
                    b[2*ni2    ][0] = r[0]; b[2*ni2    ][1] = r[1];
                    b[2*ni2 + 1][0] = r[2]; b[2*ni2 + 1][1] = r[3];
                }
            }
#pragma unroll
            for (int mi = 0; mi < 4; mi++)
#pragma unroll
                for (int ni = 0; ni < 4; ni++)
                    mma16(acc[mi][ni], a[mi], b[ni]);
        }
    }

    const int lo = 6 - lp;
    const int orow = m0 + wm * 64 + (lane >> 2);
    const int ocol = n0 + wn * 32 + (lane & 3) * 2;
#pragma unroll
    for (int mi = 0; mi < 4; mi++) {
#pragma unroll
        for (int hf = 0; hf < 2; hf++) {
            const int m = orow + mi * 16 + hf * 8;
            const int t = m >> (2 * lo);
            const int r = m & ((1 << (2 * lo)) - 1);
            const int ohi = r >> lo, owi = r & ((1 << lo) - 1);
#pragma unroll
            for (int ni = 0; ni < 4; ni++) {
                const int col = ocol + ni * 8;
                const int cc = col >> (2 * lp);
                const int rr = col & ((1 << (2 * lp)) - 1);
                const int pi = rr >> lp, pj = rr & ((1 << lp) - 1);
                long dst = ((long)((z * 8 + t) * 256 + c0 + cc) << 12)
                         + (((ohi << lp) + pi) << 6) + (owi << lp) + pj;
                *(__half2*)(out + dst) = __floats2half2_rn(acc[mi][ni][hf*2], acc[mi][ni][hf*2 + 1]);
            }
        }
    }
}

// ============================================================================
// fp16 mma 32x32 NT split-K (P=32 scores): 2 warps, cross-warp smem reduce
// ============================================================================
__global__ void __launch_bounds__(64) hgemm32_kernel(
    const __half* __restrict__ A, const __half* __restrict__ B, float* __restrict__ C,
    int K, int splitk)
{
    __shared__ __half Qs[32 * 136];
    __shared__ __half Ks[32 * 136];
    __shared__ float buf[32][33];
    const int tid = threadIdx.x;
    const int lane = tid & 31, wrp = tid >> 5;
    const int z = blockIdx.z, bat = z / splitk, ks = z - bat * splitk;
    A += (long)bat * 32 * K;
    B += (long)bat * 32 * K;
    const int kchunk = K / splitk, kbeg = ks * kchunk;

    float acc[2][4][4] = {};
    for (int k0 = kbeg; k0 < kbeg + kchunk; k0 += 128) {
        __syncthreads();
#pragma unroll
        for (int i = 0; i < 8; i++) {
            int u = i * 64 + tid;
            int row = u >> 4, seg = (u & 15) * 8;
            *(uint4*)(Qs + row * 136 + seg) = *(const uint4*)(A + (long)row * K + k0 + seg);
            *(uint4*)(Ks + row * 136 + seg) = *(const uint4*)(B + (long)row * K + k0 + seg);
        }
        __syncthreads();
        for (int s = wrp; s < 8; s += 2) {
            const int kc = s * 16;
            uint32_t a[2][4], b[4][2];
            {
                const int arow = ((lane >> 3) & 1) * 8 + (lane & 7);
                const int akc  = kc + (lane >> 4) * 8;
                ldsm4(a[0], Qs + arow * 136 + akc);
                ldsm4(a[1], Qs + (arow + 16) * 136 + akc);
            }
            {
                const int bkc = kc + ((lane >> 3) & 1) * 8;
#pragma unroll
                for (int ni2 = 0; ni2 < 2; ni2++) {
                    const int brow = ni2 * 16 + ((lane >> 4) & 1) * 8 + (lane & 7);
                    uint32_t r[4];
                    ldsm4(r, Ks + brow * 136 + bkc);
                    b[2*ni2    ][0] = r[0]; b[2*ni2    ][1] = r[1];
                    b[2*ni2 + 1][0] = r[2]; b[2*ni2 + 1][1] = r[3];
                }
            }
#pragma unroll
            for (int mi = 0; mi < 2; mi++)
#pragma unroll
                for (int ni = 0; ni < 4; ni++)
                    mma16(acc[mi][ni], a[mi], b[ni]);
        }
    }

    const int rr = lane >> 2, cc = (lane & 3) * 2;
    if (wrp == 0) {
#pragma unroll
        for (int mi = 0; mi < 2; mi++)
#pragma unroll
            for (int ni = 0; ni < 4; ni++) {
                buf[mi*16 + rr    ][ni*8 + cc]     = acc[mi][ni][0];
                buf[mi*16 + rr    ][ni*8 + cc + 1] = acc[mi][ni][1];
                buf[mi*16 + rr + 8][ni*8 + cc]     = acc[mi][ni][2];
                buf[mi*16 + rr + 8][ni*8 + cc + 1] = acc[mi][ni][3];
            }
    }
    __syncthreads();
    if (wrp == 1) {
#pragma unroll
        for (int mi = 0; mi < 2; mi++)
#pragma unroll
            for (int ni = 0; ni < 4; ni++) {
                buf[mi*16 + rr    ][ni*8 + cc]     += acc[mi][ni][0];
                buf[mi*16 + rr    ][ni*8 + cc + 1] += acc[mi][ni][1];
                buf[mi*16 + rr + 8][ni*8 + cc]     += acc[mi][ni][2];
                buf[mi*16 + rr + 8][ni*8 + cc + 1] += acc[mi][ni][3];
            }
    }
    __syncthreads();
    float* Cz = C + (long)z * 1024;
    for (int i = tid; i < 1024; i += 64)
        Cz[i] = buf[i >> 5][i & 31];
}

__global__ void reduce_splitk_kernel(const float* __restrict__ part, float* __restrict__ S,
                                     int per, int splitk)
{
    long idx = (long)blockIdx.x * 256 + threadIdx.x;
    int b = (int)(idx / per);
    int r = (int)(idx - (long)b * per);
    float s = 0.f;
    for (int ks = 0; ks < splitk; ks++)
        s += part[(long)(b * splitk + ks) * per + r];
    S[idx] = s;
}

// ===================== SIMT AV for P=32 (probs half, half V, half out) ============
__global__ void __launch_bounds__(256) gemm_av32_kernel(
    const __half* __restrict__ A, const __half* __restrict__ B, __half* __restrict__ out,
    int n, int d, int lp, int c0)
{
    const int z = blockIdx.z;
    A += (long)z * n * n;
    B += (long)z * n * d;
    const int m0 = blockIdx.y * 64, n0 = blockIdx.x * 64;
    __shared__ __align__(16) float As[16][68];
    __shared__ __align__(16) float Bs[16][64];
    const int tid = threadIdx.x;
    const int tx = tid & 15, ty = tid >> 4;
    float acc[4][4] = {};
    for (int k0 = 0; k0 < n; k0 += 16) {
#pragma unroll
        for (int it = 0; it < 4; it++) {
            int id = tid + it * 256;
            int m = id >> 4, kk = id & 15;
            As[kk][m] = (m0 + m < n) ? __half2float(A[(long)(m0 + m) * n + k0 + kk]) : 0.f;
        }
#pragma unroll
        for (int it = 0; it < 4; it++) {
            int id = tid + it * 256;
            int kk = id >> 6, nnn = id & 63;
            Bs[kk][nnn] = __half2float(B[(long)(k0 + kk) * d + n0 + nnn]);
        }
        __syncthreads();
#pragma unroll
        for (int kk = 0; kk < 16; kk++) {
            float4 a4 = *(const float4*)&As[kk][ty * 4];
            float4 b4 = *(const float4*)&Bs[kk][tx * 4];
            float ar[4] = {a4.x, a4.y, a4.z, a4.w};
            float br[4] = {b4.x, b4.y, b4.z, b4.w};
#pragma unroll
            for (int i = 0; i < 4; i++)
#pragma unroll
                for (int j = 0; j < 4; j++)
                    acc[i][j] += ar[i] * br[j];
        }
        __syncthreads();
    }
    const int lo = 6 - lp, o = 1 << lo, P = 1 << lp;
#pragma unroll
    for (int i = 0; i < 4; i++) {
        int m = m0 + ty * 4 + i;
        if (m >= n) continue;
        int t = m >> (2 * lo);
        int r = m & ((1 << (2 * lo)) - 1);
        int ohi = r >> lo, owi = r & (o - 1);
        int col = n0 + tx * 4;
        int cc = col >> (2 * lp);
        int rr = col & (P * P - 1);
        int pi = rr >> lp, pj = rr & (P - 1);
        long dst = ((long)((z * 8 + t) * 256 + c0 + cc) << 12)
                 + (((ohi << lp) + pi) << 6) + (owi << lp) + pj;
        *(__half2*)(out + dst)     = __floats2half2_rn(acc[i][0], acc[i][1]);
        *(__half2*)(out + dst + 2) = __floats2half2_rn(acc[i][2], acc[i][3]);
    }
}

// ===================== softmax (row-wise, scale folded in, HALF out) ==============
__global__ void softmax_kernel(const float* __restrict__ S, __half* __restrict__ Sh,
                               int n, float scale)
{
    __shared__ float buf[2048];
    __shared__ float red[256];
    const long row = blockIdx.x;
    const float* p = S + row * (long)n;
    __half* ph = Sh + row * (long)n;
    const int tid = threadIdx.x;
    float m = -1e30f;
    for (int i = tid; i < n; i += 256) { float v = p[i] * scale; buf[i] = v; m = fmaxf(m, v); }
    red[tid] = m; __syncthreads();
    for (int s = 128; s > 0; s >>= 1) { if (tid < s) red[tid] = fmaxf(red[tid], red[tid + s]); __syncthreads(); }
    m = red[0]; __syncthreads();
    float sum = 0.f;
    for (int i = tid; i < n; i += 256) { float e = expf(buf[i] - m); buf[i] = e; sum += e; }
    red[tid] = sum; __syncthreads();
    for (int s = 128; s > 0; s >>= 1) { if (tid < s) red[tid] += red[tid + s]; __syncthreads(); }
    float inv = 1.f / red[0];
    for (int i = tid; i < n; i += 256) ph[i] = __float2half(buf[i] * inv);
}

// ===================== launcher ===================================================
extern "C" void kernel_launch(void* const* d_in, const int* in_sizes, int n_in,
                              void* d_out, int out_size)
{
    const float* xs  = (const float*)d_in[0];
    const float* Wq  = (const float*)d_in[2];
    const float* bq  = (const float*)d_in[3];
    const float* Wk  = (const float*)d_in[4];
    const float* bk  = (const float*)d_in[5];
    const float* Wv  = (const float*)d_in[6];
    const float* bv  = (const float*)d_in[7];
    const float* Wl  = (const float*)d_in[8];
    const float* bl  = (const float*)d_in[9];
    const float* Wf1 = (const float*)d_in[10];
    const float* bf1 = (const float*)d_in[11];
    const float* Wf2 = (const float*)d_in[12];
    const float* bf2 = (const float*)d_in[13];
    float* out = (float*)d_out;

    __half *gQp, *gKp, *gVp, *gXsh, *gAtth, *gXs1h, *gFfh, *gSh;
    __half *gWqh, *gWkh, *gWvh, *gWlh, *gWf1h, *gWf2h;
    float *gS, *gPart, *gXs1;
    cudaGetSymbolAddress((void**)&gQp,   g_Qp);
    cudaGetSymbolAddress((void**)&gKp,   g_Kp);
    cudaGetSymbolAddress((void**)&gVp,   g_Vp);
    cudaGetSymbolAddress((void**)&gS,    g_S);
    cudaGetSymbolAddress((void**)&gSh,   g_Sh);
    cudaGetSymbolAddress((void**)&gPart, g_part);
    cudaGetSymbolAddress((void**)&gXs1,  g_xs1);
    cudaGetSymbolAddress((void**)&gXsh,  g_xsh);
    cudaGetSymbolAddress((void**)&gAtth, g_atth);
    cudaGetSymbolAddress((void**)&gXs1h, g_xs1h);
    cudaGetSymbolAddress((void**)&gFfh,  g_ffh);
    cudaGetSymbolAddress((void**)&gWqh,  g_Wqh);
    cudaGetSymbolAddress((void**)&gWkh,  g_Wkh);
    cudaGetSymbolAddress((void**)&gWvh,  g_Wvh);
    cudaGetSymbolAddress((void**)&gWlh,  g_Wlh);
    cudaGetSymbolAddress((void**)&gWf1h, g_Wf1h);
    cudaGetSymbolAddress((void**)&gWf2h, g_Wf2h);

    cudaFuncSetAttribute(hconvK_kernel,
                         cudaFuncAttributeMaxDynamicSharedMemorySize, HK_SMEM);

    dim3 blk(256);
    dim3 qgrid(NIMG * 32, 2);

    // pre-convert inputs + weights (convs: transpose to tap-major)
    f2h_kernel<<<16384, blk>>>(xs,  gXsh);
    f2h_kernel<<<64,    blk>>>(Wq,  gWqh);
    f2h_kernel<<<64,    blk>>>(Wk,  gWkh);
    f2h_kernel<<<64,    blk>>>(Wv,  gWvh);
    wtrans_kernel<<<2304, blk>>>(Wl,  gWlh);
    wtrans_kernel<<<2304, blk>>>(Wf1, gWf1h);
    wtrans_kernel<<<2304, blk>>>(Wf2, gWf2h);

    // QKV projections -> patchified half buffers (bias fused)
    hconv2_kernel<<<qgrid, blk>>>(gXsh, gWqh, bq, gQp);
    hconv2_kernel<<<qgrid, blk>>>(gXsh, gWkh, bk, gKp);
    hconv2_kernel<<<qgrid, blk>>>(gXsh, gWvh, bv, gVp);

    // ---- P=32 (n=32, d=65536) ----
    {
        const int n = 32, d = 65536, splitk = 256;
        hgemm32_kernel<<<dim3(1, 1, 2 * splitk), 64>>>(gQp, gKp, gPart, d, splitk);
        reduce_splitk_kernel<<<(2 * n * n) / 256, blk>>>(gPart, gS, n * n, splitk);
        softmax_kernel<<<2 * n, blk>>>(gS, gSh, n, 1.0f / 256.0f);
        gemm_av32_kernel<<<dim3(d / 64, 1, 2), blk>>>(gSh, gVp, gAtth, n, d, 5, 0);
    }
    // ---- P=16 (n=128, d=16384) ----
    {
        const int n = 128, d = 16384, splitk = 64;
        const long soff = 4194304;
        hgemm_nt_kernel<<<dim3(1, 1, 2 * splitk), blk>>>(
            gQp + soff, gKp + soff, gPart, n, d, splitk, (long)n * d, (long)n * n);
        reduce_splitk_kernel<<<(2 * n * n) / 256, blk>>>(gPart, gS, n * n, splitk);
        softmax_kernel<<<2 * n, blk>>>(gS, gSh, n, 1.0f / 128.0f);
        hgemm_av_kernel<<<dim3(d / 128, n / 128, 2), blk>>>(gSh, gVp + soff, gAtth, n, d, 4, 64);
    }
    // ---- P=8 (n=512, d=4096) ----
    {
        const int n = 512, d = 4096, splitk = 8;
        const long soff = 2L * 4194304;
        hgemm_nt_kernel<<<dim3(n / 128, n / 128, 2 * splitk), blk>>>(
            gQp + soff, gKp + soff, gPart, n, d, splitk, (long)n * d, (long)n * n);
        reduce_splitk_kernel<<<(2 * n * n) / 256, blk>>>(gPart, gS, n * n, splitk);
        softmax_kernel<<<2 * n, blk>>>(gS, gSh, n, 1.0f / 64.0f);
        hgemm_av_kernel<<<dim3(d / 128, n / 128, 2), blk>>>(gSh, gVp + soff, gAtth, n, d, 3, 128);
    }
    // ---- P=4 (n=2048, d=1024) ----
    {
        const int n = 2048, d = 1024;
        const long soff = 3L * 4194304;
        hgemm_nt_kernel<<<dim3(n / 128, n / 128, 2), blk>>>(
            gQp + soff, gKp + soff, gS, n, d, 1, (long)n * d, (long)n * n);
        softmax_kernel<<<2 * n, blk>>>(gS, gSh, n, 1.0f / 32.0f);
        hgemm_av_kernel<<<dim3(d / 128, n / 128, 2), blk>>>(gSh, gVp + soff, gAtth, n, d, 2, 192);
    }

    // convs: 128-pixel tiles, K-chunk 64 (R9 hconvK)
    hconvK_kernel<<<qgrid, blk, HK_SMEM>>>(gAtth, gWlh,  bl,  xs,      gXs1,    gXs1h, 1, 1);
    hconvK_kernel<<<qgrid, blk, HK_SMEM>>>(gXs1h, gWf1h, bf1, nullptr, nullptr, gFfh,  1, 0);
    hconvK_kernel<<<qgrid, blk, HK_SMEM>>>(gFfh,  gWf2h, bf2, gXs1,    out,     nullptr, 2, 1);
}

// round 12
// speedup vs baseline: 1.0565x; 1.0127x over previous
#include <cuda_runtime.h>
#include <cuda_fp16.h>
#include <math.h>
#include <stdint.h>

#define NIMG 16
#define CCH 256
#define NPIX 4096            // 64*64

// ---- scratch (static device globals; no allocation) ----
__device__ __half g_Qp[16777216];
__device__ __half g_Kp[16777216];
__device__ __half g_Vp[16777216];
__device__ float  g_S[2*2048*2048];
__device__ __half g_Sh[2*2048*2048];
__device__ float  g_part[8388608];
__device__ float  g_xs1[NIMG*CCH*NPIX];
__device__ __half g_xsh [NIMG*CCH*NPIX];
__device__ __half g_atth[NIMG*CCH*NPIX];
__device__ __half g_xs1h[NIMG*CCH*NPIX];
__device__ __half g_ffh [NIMG*CCH*NPIX];
__device__ __half g_Wqh[65536], g_Wkh[65536], g_Wvh[65536];
__device__ __half g_Wlh[589824], g_Wf1h[589824], g_Wf2h[589824];   // tap-major

// ============================================================================
// helpers
// ============================================================================
__device__ __forceinline__ void mma16(float* d, const uint32_t* a, const uint32_t* b) {
    asm volatile(
        "mma.sync.aligned.m16n8k16.row.col.f32.f16.f16.f32 "
        "{%0,%1,%2,%3}, {%4,%5,%6,%7}, {%8,%9}, {%0,%1,%2,%3};"
        : "+f"(d[0]), "+f"(d[1]), "+f"(d[2]), "+f"(d[3])
        : "r"(a[0]), "r"(a[1]), "r"(a[2]), "r"(a[3]), "r"(b[0]), "r"(b[1]));
}

__device__ __forceinline__ void ldsm4(uint32_t* r, const void* p) {
    uint32_t addr = (uint32_t)__cvta_generic_to_shared(p);
    asm volatile("ldmatrix.sync.aligned.m8n8.x4.shared.b16 {%0,%1,%2,%3}, [%4];"
        : "=r"(r[0]), "=r"(r[1]), "=r"(r[2]), "=r"(r[3]) : "r"(addr));
}

__device__ __forceinline__ void ldsm4t(uint32_t* r, const void* p) {
    uint32_t addr = (uint32_t)__cvta_generic_to_shared(p);
    asm volatile("ldmatrix.sync.aligned.m8n8.x4.trans.shared.b16 {%0,%1,%2,%3}, [%4];"
        : "=r"(r[0]), "=r"(r[1]), "=r"(r[2]), "=r"(r[3]) : "r"(addr));
}

__device__ __forceinline__ uint32_t pack_h2(float a, float b) {
    __half2 h = __floats2half2_rn(a, b);
    return *(uint32_t*)&h;
}

__device__ __forceinline__ void cpa16(uint32_t dst, const void* src, unsigned sz) {
    asm volatile("cp.async.ca.shared.global [%0], [%1], 16, %2;"
                 :: "r"(dst), "l"(src), "r"(sz) : "memory");
}
__device__ __forceinline__ void cpcommit() {
    asm volatile("cp.async.commit_group;" ::: "memory");
}
template <int N>
__device__ __forceinline__ void cpwait() {
    asm volatile("cp.async.wait_group %0;" :: "n"(N) : "memory");
}

// f32 -> f16 bulk convert (exact multiples of 1024 elems)
__global__ void f2h_kernel(const float* __restrict__ src, __half* __restrict__ dst) {
    long i = ((long)blockIdx.x * 256 + threadIdx.x) * 4;
    float4 v = *(const float4*)(src + i);
    *(uint32_t*)(dst + i)     = pack_h2(v.x, v.y);
    *(uint32_t*)(dst + i + 2) = pack_h2(v.z, v.w);
}

// batched f2h for the three 65536-elem QKV weights (grid 192)
__global__ void f2h3_kernel(const float* __restrict__ s0, const float* __restrict__ s1,
                            const float* __restrict__ s2,
                            __half* __restrict__ d0, __half* __restrict__ d1,
                            __half* __restrict__ d2) {
    int z = blockIdx.x >> 6;
    const float* s = (z == 0) ? s0 : ((z == 1) ? s1 : s2);
    __half* d = (z == 0) ? d0 : ((z == 1) ? d1 : d2);
    long i = ((long)(blockIdx.x & 63) * 256 + threadIdx.x) * 4;
    float4 v = *(const float4*)(s + i);
    *(uint32_t*)(d + i)     = pack_h2(v.x, v.y);
    *(uint32_t*)(d + i + 2) = pack_h2(v.z, v.w);
}

// batched conv weight transpose: 3 weights in one launch (grid 3*2304)
__global__ void wtrans3_kernel(const float* __restrict__ W0, const float* __restrict__ W1,
                               const float* __restrict__ W2,
                               __half* __restrict__ D0, __half* __restrict__ D1,
                               __half* __restrict__ D2) {
    int z = blockIdx.x / 2304;
    const float* W = (z == 0) ? W0 : ((z == 1) ? W1 : W2);
    __half* Wt2 = (z == 0) ? D0 : ((z == 1) ? D1 : D2);
    int idx = (blockIdx.x - z * 2304) * 256 + threadIdx.x;
    int oc = idx / 2304, r = idx - oc * 2304;
    int tap = r >> 8, c = r & 255;
    Wt2[idx] = __float2half(W[oc * 2304 + c * 9 + tap]);
}

// scatter index into patchified buffer: scale = oc>>6
__device__ __forceinline__ long pat_index(int img, int oc, int pix) {
    int s  = oc >> 6, cc = oc & 63;
    int lp = 5 - s;
    int lo = 1 + s;
    int Pm = (1 << lp) - 1;
    int y = pix >> 6, x = pix & 63;
    int ohi = y >> lp, pi = y & Pm, owi = x >> lp, pj = x & Pm;
    int t = img & 7, b = img >> 3;
    int nn = (t << (2*lo)) + (ohi << lo) + owi;
    int dd = (cc << (2*lp)) + (pi << lp) + pj;
    return (long)s * 4194304 + (long)b * 2097152 + (long)nn * (64 << (2*lp)) + dd;
}

// ============================================================================
// hconv2 (ks==1): QKV projection, cp.async pipelined, 256 threads
// ============================================================================
__global__ void __launch_bounds__(256, 2) hconv2_kernel(
    const __half* __restrict__ in, const __half* __restrict__ Wt,
    const float* __restrict__ bias, __half* __restrict__ outh_pat)
{
    __shared__ __half A2[2 * 128 * 40];
    __shared__ __half B2[2 * 32 * 136];

    const int tid = threadIdx.x;
    const int lane = tid & 31, wid = tid >> 5;
    const int wm = wid & 1, wn = wid >> 1;
    const int img = blockIdx.x >> 5;
    const int p0 = (blockIdx.x & 31) * 128;
    const int m0 = blockIdx.y * 128;
    const __half* inimg = in + (long)img * CCH * NPIX;

    const uint32_t sA2 = (uint32_t)__cvta_generic_to_shared(A2);
    const uint32_t sB2 = (uint32_t)__cvta_generic_to_shared(B2);

#define ISSUE1(KCN, NB)                                                         \
    {                                                                           \
        const int k0n = (KCN) * 32;                                             \
        {                                                                       \
            int row = tid >> 1, seg = (tid & 1) * 16;                           \
            const __half* src = Wt + (long)(m0 + row) * 256 + k0n + seg;        \
            uint32_t dst = sA2 + (uint32_t)(((NB) * 5120 + row * 40 + seg) * 2);\
            cpa16(dst, src, 16u); cpa16(dst + 16, src + 8, 16u);                \
        }                                                                       \
        {                                                                       \
            int k = tid >> 3, u = tid & 7;                                      \
            const __half* src = inimg + ((long)(k0n + k) << 12) + p0 + u * 8;   \
            uint32_t dst = sB2 + (uint32_t)(((NB) * 4352 + k * 136 + u * 8) * 2); \
            cpa16(dst, src, 16u);                                               \
            cpa16(dst + 128, src + 64, 16u);                                    \
        }                                                                       \
        cpcommit();                                                             \
    }

    float acc[4][4][4] = {};
    ISSUE1(0, 0);

    for (int kc = 0; kc < 8; kc++) {
        cpwait<0>();
        __syncthreads();
        if (kc + 1 < 8) ISSUE1(kc + 1, (kc + 1) & 1);

        const __half* Ap = A2 + (kc & 1) * 5120;
        const __half* Bp = B2 + (kc & 1) * 4352;
#pragma unroll
        for (int kstep = 0; kstep < 2; kstep++) {
            uint32_t a[4][4], b[4][2];
            {
                const int arow = wm * 64 + ((lane >> 3) & 1) * 8 + (lane & 7);
                const int akc  = kstep * 16 + (lane >> 4) * 8;
#pragma unroll
                for (int mi = 0; mi < 4; mi++)
                    ldsm4(a[mi], Ap + (arow + mi * 16) * 40 + akc);
            }
            {
                const int brow = kstep * 16 + (lane & 7) + ((lane >> 3) & 1) * 8;
#pragma unroll
                for (int ni2 = 0; ni2 < 2; ni2++) {
                    const int bcol = wn * 32 + ni2 * 16 + ((lane >> 4) & 1) * 8;
                    uint32_t r[4];
                    ldsm4t(r, Bp + brow * 136 + bcol);
                    b[2*ni2    ][0] = r[0]; b[2*ni2    ][1] = r[1];
                    b[2*ni2 + 1][0] = r[2]; b[2*ni2 + 1][1] = r[3];
                }
            }
#pragma unroll
            for (int mi = 0; mi < 4; mi++)
#pragma unroll
                for (int ni = 0; ni < 4; ni++)
                    mma16(acc[mi][ni], a[mi], b[ni]);
        }
    }
#undef ISSUE1

    const int orow = m0 + wm * 64 + (lane >> 2);
    const int ocol = p0 + wn * 32 + (lane & 3) * 2;
#pragma unroll
    for (int mi = 0; mi < 4; mi++) {
        const int oca = orow + mi * 16, ocb = oca + 8;
        const float ba = bias[oca], bb = bias[ocb];
#pragma unroll
        for (int ni = 0; ni < 4; ni++) {
            const int n = ocol + ni * 8;
            long ia = pat_index(img, oca, n);
            long ib = pat_index(img, ocb, n);
            *(__half2*)(outh_pat + ia) = __floats2half2_rn(acc[mi][ni][0] + ba, acc[mi][ni][1] + ba);
            *(__half2*)(outh_pat + ib) = __floats2half2_rn(acc[mi][ni][2] + bb, acc[mi][ni][3] + bb);
        }
    }
}

// ============================================================================
// hconvK (R9 structure): 3x3 conv, tap-major K, 256 threads, M=128 x N=128,
//   K-chunk 64, A double-buffered, Strip/Bs single-buffered, 2 barriers/chunk
// ============================================================================
#define HK_A2    0
#define HK_BS    18432
#define HK_STRIP (18432 + 8704)
#define HK_SMEM  ((18432 + 8704 + 10240) * 2)

__global__ void __launch_bounds__(256, 2) hconvK_kernel(
    const __half* __restrict__ in, const __half* __restrict__ Wt,
    const float* __restrict__ bias, const float* __restrict__ res,
    float* __restrict__ out, __half* __restrict__ outh_img,
    int dil, int addres)
{
    extern __shared__ __half sh[];
    __half* A2    = sh + HK_A2;
    __half* Bs    = sh + HK_BS;
    __half* Strip = sh + HK_STRIP;

    const int tid = threadIdx.x;
    const int lane = tid & 31, wid = tid >> 5;
    const int wm = wid & 1, wn = wid >> 1;
    const int img = blockIdx.x >> 5;
    const int p0 = (blockIdx.x & 31) * 128;
    const int y0 = p0 >> 6;
    const int m0 = blockIdx.y * 128;
    const __half* inimg = in + (long)img * CCH * NPIX;

    const uint32_t sA2    = (uint32_t)__cvta_generic_to_shared(A2);
    const uint32_t sStrip = (uint32_t)__cvta_generic_to_shared(Strip);

    // zero strip halos once
    {
        int c = tid >> 2, u = tid & 3, r = u >> 1, side = u & 1;
        *(uint4*)(Strip + c * 160 + r * 80 + side * 72) = make_uint4(0, 0, 0, 0);
    }

#define ISSUEK(KCN, NB)                                                          \
    {                                                                            \
        const int k0n = (KCN) * 64;                                              \
        {   /* A: 128 oc x 64 k */                                               \
            int row = tid >> 1, seg = (tid & 1) * 32;                            \
            const __half* src = Wt + (long)(m0 + row) * 2304 + k0n + seg;        \
            uint32_t dst = sA2 + (uint32_t)(((NB) * 9216 + row * 72 + seg) * 2); \
            cpa16(dst,      src,      16u);                                      \
            cpa16(dst + 16, src + 8,  16u);                                      \
            cpa16(dst + 32, src + 16, 16u);                                      \
            cpa16(dst + 48, src + 24, 16u);                                      \
        }                                                                        \
        {   /* strip: 64 ch x 2 rows x 64 px */                                  \
            int tapn = (KCN) >> 2;                                               \
            int c0 = (k0n) & 255;                                                \
            int dyd = (tapn / 3 - 1) * dil;                                      \
            int c = tid >> 2, u = tid & 3;                                       \
            int r = u >> 1, s = u & 1;                                           \
            int gy = y0 + r + dyd;                                               \
            unsigned ok = ((unsigned)gy < 64u) ? 16u : 0u;                       \
            int gyc = gy < 0 ? 0 : (gy > 63 ? 63 : gy);                          \
            const __half* src = inimg + ((long)(c0 + c) << 12) + (gyc << 6) + s * 32; \
            uint32_t dst = sStrip + (uint32_t)((c * 160 + r * 80 + 8 + s * 32) * 2);  \
            cpa16(dst,      src,      ok);                                       \
            cpa16(dst + 16, src + 8,  ok);                                       \
            cpa16(dst + 32, src + 16, ok);                                       \
            cpa16(dst + 48, src + 24, ok);                                       \
        }                                                                        \
        cpcommit();                                                              \
    }

    float acc[4][4][4] = {};
    ISSUEK(0, 0);

    for (int kc = 0; kc < 36; kc++) {
        cpwait<0>();
        __syncthreads();

        // build shifted B tile (64 k-rows x 128 px) from strip
        {
            const int tap = kc >> 2;
            const int dxd = (tap - (tap / 3) * 3 - 1) * dil;
            const int c = tid >> 2, u = tid & 3, prow = u >> 1, xseg = (u & 1) * 32;
            const uint32_t* rowp = (const uint32_t*)(Strip + c * 160 + prow * 80);
            const int h0 = 8 + dxd + xseg;
            uint32_t w[16];
            if (dxd & 1) {
                int k0 = (h0 - 1) >> 1;
                uint32_t prev = rowp[k0];
#pragma unroll
                for (int j = 0; j < 16; j++) {
                    uint32_t nxt = rowp[k0 + 1 + j];
                    w[j] = __funnelshift_r(prev, nxt, 16);
                    prev = nxt;
                }
            } else {
                int k0 = h0 >> 1;
#pragma unroll
                for (int j = 0; j < 16; j++) w[j] = rowp[k0 + j];
            }
            uint4* bd = (uint4*)(Bs + c * 136 + prow * 64 + xseg);
#pragma unroll
            for (int j = 0; j < 4; j++)
                bd[j] = make_uint4(w[4*j], w[4*j+1], w[4*j+2], w[4*j+3]);
        }
        __syncthreads();

        if (kc + 1 < 36) ISSUEK(kc + 1, (kc + 1) & 1);

        const __half* Ap = A2 + (kc & 1) * 9216;
#pragma unroll
        for (int kstep = 0; kstep < 4; kstep++) {
            uint32_t a[4][4], b[4][2];
            {
                const int arow = wm * 64 + ((lane >> 3) & 1) * 8 + (lane & 7);
                const int akc  = kstep * 16 + (lane >> 4) * 8;
#pragma unroll
                for (int mi = 0; mi < 4; mi++)
                    ldsm4(a[mi], Ap + (arow + mi * 16) * 72 + akc);
            }
            {
                const int brow = kstep * 16 + (lane & 7) + ((lane >> 3) & 1) * 8;
#pragma unroll
                for (int ni2 = 0; ni2 < 2; ni2++) {
                    const int bcol = wn * 32 + ni2 * 16 + ((lane >> 4) & 1) * 8;
                    uint32_t r[4];
                    ldsm4t(r, Bs + brow * 136 + bcol);
                    b[2*ni2    ][0] = r[0]; b[2*ni2    ][1] = r[1];
                    b[2*ni2 + 1][0] = r[2]; b[2*ni2 + 1][1] = r[3];
                }
            }
#pragma unroll
            for (int mi = 0; mi < 4; mi++)
#pragma unroll
                for (int ni = 0; ni < 4; ni++)
                    mma16(acc[mi][ni], a[mi], b[ni]);
        }
    }
#undef ISSUEK

    const int orow = m0 + wm * 64 + (lane >> 2);
    const int ocol = p0 + wn * 32 + (lane & 3) * 2;
#pragma unroll
    for (int mi = 0; mi < 4; mi++) {
        const int oca = orow + mi * 16;
        const int ocb = oca + 8;
        const float ba = bias[oca], bb = bias[ocb];
#pragma unroll
        for (int ni = 0; ni < 4; ni++) {
            const int n = ocol + ni * 8;
            long ia = ((long)img * 256 + oca) * NPIX + n;
            long ib = ((long)img * 256 + ocb) * NPIX + n;
            float v0 = acc[mi][ni][0] + ba, v1 = acc[mi][ni][1] + ba;
            float v2 = acc[mi][ni][2] + bb, v3 = acc[mi][ni][3] + bb;
            v0 = (v0 > 0.f) ? v0 : 0.2f * v0;
            v1 = (v1 > 0.f) ? v1 : 0.2f * v1;
            v2 = (v2 > 0.f) ? v2 : 0.2f * v2;
            v3 = (v3 > 0.f) ? v3 : 0.2f * v3;
            if (addres) {
                v0 += res[ia]; v1 += res[ia + 1];
                v2 += res[ib]; v3 += res[ib + 1];
            }
            if (out) {
                out[ia] = v0; out[ia + 1] = v1;
                out[ib] = v2; out[ib + 1] = v3;
            }
            if (outh_img) {
                *(__half2*)(outh_img + ia) = __floats2half2_rn(v0, v1);
                *(__half2*)(outh_img + ib) = __floats2half2_rn(v2, v3);
            }
        }
    }
}

// ============================================================================
// fp16 NT GEMM with deterministic split-K (scores), f32 out
// ============================================================================
__global__ void __launch_bounds__(256) hgemm_nt_kernel(
    const __half* __restrict__ A, const __half* __restrict__ B, float* __restrict__ C,
    int N, int K, int splitk, long sAB, long sC)
{
    __shared__ __half As[128 * 40];
    __shared__ __half Bs[128 * 40];
    const int tid = threadIdx.x;
    const int lane = tid & 31, wid = tid >> 5;
    const int wm = wid & 1, wn = wid >> 1;
    const int n0 = blockIdx.x * 128, m0 = blockIdx.y * 128;
    const int z = blockIdx.z, bat = z / splitk, ks = z - bat * splitk;
    A += (long)bat * sAB;
    B += (long)bat * sAB;
    C += (long)z * sC;
    const int kchunk = K / splitk, kbeg = ks * kchunk;
    const int wr = tid >> 1, wkh = (tid & 1) * 16;

    float acc[4][4][4] = {};
    for (int k0 = kbeg; k0 < kbeg + kchunk; k0 += 32) {
        __syncthreads();
        {
            const __half* sa = A + (long)(m0 + wr) * K + k0 + wkh;
            const __half* sb = B + (long)(n0 + wr) * K + k0 + wkh;
            *(uint4*)(As + wr * 40 + wkh)     = *(const uint4*)sa;
            *(uint4*)(As + wr * 40 + wkh + 8) = *(const uint4*)(sa + 8);
            *(uint4*)(Bs + wr * 40 + wkh)     = *(const uint4*)sb;
            *(uint4*)(Bs + wr * 40 + wkh + 8) = *(const uint4*)(sb + 8);
        }
        __syncthreads();
#pragma unroll
        for (int kstep = 0; kstep < 2; kstep++) {
            uint32_t a[4][4], b[4][2];
            {
                const int arow = wm * 64 + ((lane >> 3) & 1) * 8 + (lane & 7);
                const int akc  = kstep * 16 + (lane >> 4) * 8;
#pragma unroll
                for (int mi = 0; mi < 4; mi++)
                    ldsm4(a[mi], As + (arow + mi * 16) * 40 + akc);
            }
            {
                const int bkc = kstep * 16 + ((lane >> 3) & 1) * 8;
#pragma unroll
                for (int ni2 = 0; ni2 < 2; ni2++) {
                    const int brow = wn * 32 + ni2 * 16 + ((lane >> 4) & 1) * 8 + (lane & 7);
                    uint32_t r[4];
                    ldsm4(r, Bs + brow * 40 + bkc);
                    b[2*ni2    ][0] = r[0]; b[2*ni2    ][1] = r[1];
                    b[2*ni2 + 1][0] = r[2]; b[2*ni2 + 1][1] = r[3];
                }
            }
#pragma unroll
            for (int mi = 0; mi < 4; mi++)
#pragma unroll
                for (int ni = 0; ni < 4; ni++)
                    mma16(acc[mi][ni], a[mi], b[ni]);
        }
    }
    const int orow = m0 + wm * 64 + (lane >> 2);
    const int ocol = n0 + wn * 32 + (lane & 3) * 2;
#pragma unroll
    for (int mi = 0; mi < 4; mi++) {
        long ra = (long)(orow + mi * 16) * N;
        long rb = (long)(orow + mi * 16 + 8) * N;
#pragma unroll
        for (int ni = 0; ni < 4; ni++) {
            int n = ocol + ni * 8;
            C[ra + n] = acc[mi][ni][0]; C[ra + n + 1] = acc[mi][ni][1];
            C[rb + n] = acc[mi][ni][2]; C[rb + n + 1] = acc[mi][ni][3];
        }
    }
}

// ============================================================================
// fp16 AV GEMM (probs in HALF, NN via trans-ldmatrix B), scatter -> half image
// ============================================================================
__global__ void __launch_bounds__(256) hgemm_av_kernel(
    const __half* __restrict__ S, const __half* __restrict__ V, __half* __restrict__ out,
    int n, int d, int lp, int c0)
{
    __shared__ __half As[128 * 40];
    __shared__ __half Bs[32 * 136];
    const int tid = threadIdx.x;
    const int lane = tid & 31, wid = tid >> 5;
    const int wm = wid & 1, wn = wid >> 1;
    const int z = blockIdx.z;
    S += (long)z * n * n;
    V += (long)z * n * d;
    const int n0 = blockIdx.x * 128;
    const int m0 = blockIdx.y * 128;
    const int wr = tid >> 1, wkh = (tid & 1) * 16;
    const int bk = tid >> 3, bn0 = (tid & 7) * 16;

    float acc[4][4][4] = {};
    for (int k0 = 0; k0 < n; k0 += 32) {
        __syncthreads();
        {
            const __half* sa = S + (long)(m0 + wr) * n + k0 + wkh;
            *(uint4*)(As + wr * 40 + wkh)     = *(const uint4*)sa;
            *(uint4*)(As + wr * 40 + wkh + 8) = *(const uint4*)(sa + 8);
            const __half* sb = V + (long)(k0 + bk) * d + n0 + bn0;
            *(uint4*)(Bs + bk * 136 + bn0)     = *(const uint4*)sb;
            *(uint4*)(Bs + bk * 136 + bn0 + 8) = *(const uint4*)(sb + 8);
        }
        __syncthreads();
#pragma unroll
        for (int kstep = 0; kstep < 2; kstep++) {
            uint32_t a[4][4], b[4][2];
            {
                const int arow = wm * 64 + ((lane >> 3) & 1) * 8 + (lane & 7);
                const int akc  = kstep * 16 + (lane >> 4) * 8;
#pragma unroll
                for (int mi = 0; mi < 4; mi++)
                    ldsm4(a[mi], As + (arow + mi * 16) * 40 + akc);
            }
            {
                const int brow = kstep * 16 + (lane & 7) + ((lane >> 3) & 1) * 8;
#pragma unroll
                for (int ni2 = 0; ni2 < 2; ni2++) {
                    const int bcol = wn * 32 + ni2 * 16 + ((lane >> 4) & 1) * 8;
                    uint32_t r[4];
                    ldsm4t(r, Bs + brow * 136 + bcol);
                    b[2*ni2    ][0] = r[0]; b[2*ni2    ][1] = r[1];
                    b[2*ni2 + 1][0] = r[2]; b[2*ni2 + 1][1] = r[3];
                }
            }
#pragma unroll
            for (int mi = 0; mi < 4; mi++)
#pragma unroll
                for (int ni = 0; ni < 4; ni++)
                    mma16(acc[mi][ni], a[mi], b[ni]);
        }
    }

    const int lo = 6 - lp;
    const int orow = m0 + wm * 64 + (lane >> 2);
    const int ocol = n0 + wn * 32 + (lane & 3) * 2;
#pragma unroll
    for (int mi = 0; mi < 4; mi++) {
#pragma unroll
        for (int hf = 0; hf < 2; hf++) {
            const int m = orow + mi * 16 + hf * 8;
            const int t = m >> (2 * lo);
            const int r = m & ((1 << (2 * lo)) - 1);
            const int ohi = r >> lo, owi = r & ((1 << lo) - 1);
#pragma unroll
            for (int ni = 0; ni < 4; ni++) {
                const int col = ocol + ni * 8;
                const int cc = col >> (2 * lp);
                const int rr = col & ((1 << (2 * lp)) - 1);
                const int pi = rr >> lp, pj = rr & ((1 << lp) - 1);
                long dst = ((long)((z * 8 + t) * 256 + c0 + cc) << 12)
                         + (((ohi << lp) + pi) << 6) + (owi << lp) + pj;
                *(__half2*)(out + dst) = __floats2half2_rn(acc[mi][ni][hf*2], acc[mi][ni][hf*2 + 1]);
            }
        }
    }
}

// ============================================================================
// fp16 mma 32x32 NT split-K (P=32 scores): 2 warps, cross-warp smem reduce
// ============================================================================
__global__ void __launch_bounds__(64) hgemm32_kernel(
    const __half* __restrict__ A, const __half* __restrict__ B, float* __restrict__ C,
    int K, int splitk)
{
    __shared__ __half Qs[32 * 136];
    __shared__ __half Ks[32 * 136];
    __shared__ float buf[32][33];
    const int tid = threadIdx.x;
    const int lane = tid & 31, wrp = tid >> 5;
    const int z = blockIdx.z, bat = z / splitk, ks = z - bat * splitk;
    A += (long)bat * 32 * K;
    B += (long)bat * 32 * K;
    const int kchunk = K / splitk, kbeg = ks * kchunk;

    float acc[2][4][4] = {};
    for (int k0 = kbeg; k0 < kbeg + kchunk; k0 += 128) {
        __syncthreads();
#pragma unroll
        for (int i = 0; i < 8; i++) {
            int u = i * 64 + tid;
            int row = u >> 4, seg = (u & 15) * 8;
            *(uint4*)(Qs + row * 136 + seg) = *(const uint4*)(A + (long)row * K + k0 + seg);
            *(uint4*)(Ks + row * 136 + seg) = *(const uint4*)(B + (long)row * K + k0 + seg);
        }
        __syncthreads();
        for (int s = wrp; s < 8; s += 2) {
            const int kc = s * 16;
            uint32_t a[2][4], b[4][2];
            {
                const int arow = ((lane >> 3) & 1) * 8 + (lane & 7);
                const int akc  = kc + (lane >> 4) * 8;
                ldsm4(a[0], Qs + arow * 136 + akc);
                ldsm4(a[1], Qs + (arow + 16) * 136 + akc);
            }
            {
                const int bkc = kc + ((lane >> 3) & 1) * 8;
#pragma unroll
                for (int ni2 = 0; ni2 < 2; ni2++) {
                    const int brow = ni2 * 16 + ((lane >> 4) & 1) * 8 + (lane & 7);
                    uint32_t r[4];
                    ldsm4(r, Ks + brow * 136 + bkc);
                    b[2*ni2    ][0] = r[0]; b[2*ni2    ][1] = r[1];
                    b[2*ni2 + 1][0] = r[2]; b[2*ni2 + 1][1] = r[3];
                }
            }
#pragma unroll
            for (int mi = 0; mi < 2; mi++)
#pragma unroll
                for (int ni = 0; ni < 4; ni++)
                    mma16(acc[mi][ni], a[mi], b[ni]);
        }
    }

    const int rr = lane >> 2, cc = (lane & 3) * 2;
    if (wrp == 0) {
#pragma unroll
        for (int mi = 0; mi < 2; mi++)
#pragma unroll
            for (int ni = 0; ni < 4; ni++) {
                buf[mi*16 + rr    ][ni*8 + cc]     = acc[mi][ni][0];
                buf[mi*16 + rr    ][ni*8 + cc + 1] = acc[mi][ni][1];
                buf[mi*16 + rr + 8][ni*8 + cc]     = acc[mi][ni][2];
                buf[mi*16 + rr + 8][ni*8 + cc + 1] = acc[mi][ni][3];
            }
    }
    __syncthreads();
    if (wrp == 1) {
#pragma unroll
        for (int mi = 0; mi < 2; mi++)
#pragma unroll
            for (int ni = 0; ni < 4; ni++) {
                buf[mi*16 + rr    ][ni*8 + cc]     += acc[mi][ni][0];
                buf[mi*16 + rr    ][ni*8 + cc + 1] += acc[mi][ni][1];
                buf[mi*16 + rr + 8][ni*8 + cc]     += acc[mi][ni][2];
                buf[mi*16 + rr + 8][ni*8 + cc + 1] += acc[mi][ni][3];
            }
    }
    __syncthreads();
    float* Cz = C + (long)z * 1024;
    for (int i = tid; i < 1024; i += 64)
        Cz[i] = buf[i >> 5][i & 31];
}

// ============================================================================
// fused split-K reduce + softmax + fp16 emit (one block per row)
// ============================================================================
__global__ void rsm_kernel(const float* __restrict__ part, __half* __restrict__ Sh,
                           int n, int splitk, float scale)
{
    __shared__ float buf[2048];
    __shared__ float red[256];
    const int row = blockIdx.x;               // 0 .. 2n-1
    const int b = row / n, r = row - b * n;
    const long base = ((long)b * splitk) * n * n + (long)r * n;
    const int tid = threadIdx.x;
    float m = -1e30f;
    for (int i = tid; i < n; i += 256) {
        float s = 0.f;
        for (int ks = 0; ks < splitk; ks++)
            s += part[base + (long)ks * n * n + i];
        s *= scale;
        buf[i] = s;
        m = fmaxf(m, s);
    }
    red[tid] = m; __syncthreads();
    for (int s = 128; s > 0; s >>= 1) { if (tid < s) red[tid] = fmaxf(red[tid], red[tid + s]); __syncthreads(); }
    m = red[0]; __syncthreads();
    float sum = 0.f;
    for (int i = tid; i < n; i += 256) { float e = expf(buf[i] - m); buf[i] = e; sum += e; }
    red[tid] = sum; __syncthreads();
    for (int s = 128; s > 0; s >>= 1) { if (tid < s) red[tid] += red[tid + s]; __syncthreads(); }
    float inv = 1.f / red[0];
    __half* ph = Sh + (long)row * n;
    for (int i = tid; i < n; i += 256) ph[i] = __float2half(buf[i] * inv);
}

// ===================== SIMT AV for P=32 (probs half, half V, half out) ============
__global__ void __launch_bounds__(256) gemm_av32_kernel(
    const __half* __restrict__ A, const __half* __restrict__ B, __half* __restrict__ out,
    int n, int d, int lp, int c0)
{
    const int z = blockIdx.z;
    A += (long)z * n * n;
    B += (long)z * n * d;
    const int m0 = blockIdx.y * 64, n0 = blockIdx.x * 64;
    __shared__ __align__(16) float As[16][68];
    __shared__ __align__(16) float Bs[16][64];
    const int tid = threadIdx.x;
    const int tx = tid & 15, ty = tid >> 4;
    float acc[4][4] = {};
    for (int k0 = 0; k0 < n; k0 += 16) {
#pragma unroll
        for (int it = 0; it < 4; it++) {
            int id = tid + it * 256;
            int m = id >> 4, kk = id & 15;
            As[kk][m] = (m0 + m < n) ? __half2float(A[(long)(m0 + m) * n + k0 + kk]) : 0.f;
        }
#pragma unroll
        for (int it = 0; it < 4; it++) {
            int id = tid + it * 256;
            int kk = id >> 6, nnn = id & 63;
            Bs[kk][nnn] = __half2float(B[(long)(k0 + kk) * d + n0 + nnn]);
        }
        __syncthreads();
#pragma unroll
        for (int kk = 0; kk < 16; kk++) {
            float4 a4 = *(const float4*)&As[kk][ty * 4];
            float4 b4 = *(const float4*)&Bs[kk][tx * 4];
            float ar[4] = {a4.x, a4.y, a4.z, a4.w};
            float br[4] = {b4.x, b4.y, b4.z, b4.w};
#pragma unroll
            for (int i = 0; i < 4; i++)
#pragma unroll
                for (int j = 0; j < 4; j++)
                    acc[i][j] += ar[i] * br[j];
        }
        __syncthreads();
    }
    const int lo = 6 - lp, o = 1 << lo, P = 1 << lp;
#pragma unroll
    for (int i = 0; i < 4; i++) {
        int m = m0 + ty * 4 + i;
        if (m >= n) continue;
        int t = m >> (2 * lo);
        int r = m & ((1 << (2 * lo)) - 1);
        int ohi = r >> lo, owi = r & (o - 1);
        int col = n0 + tx * 4;
        int cc = col >> (2 * lp);
        int rr = col & (P * P - 1);
        int pi = rr >> lp, pj = rr & (P - 1);
        long dst = ((long)((z * 8 + t) * 256 + c0 + cc) << 12)
                 + (((ohi << lp) + pi) << 6) + (owi << lp) + pj;
        *(__half2*)(out + dst)     = __floats2half2_rn(acc[i][0], acc[i][1]);
        *(__half2*)(out + dst + 2) = __floats2half2_rn(acc[i][2], acc[i][3]);
    }
}

// ===================== softmax (f32 in, HALF out; used by P=4 only) ===============
__global__ void softmax_kernel(const float* __restrict__ S, __half* __restrict__ Sh,
                               int n, float scale)
{
    __shared__ float buf[2048];
    __shared__ float red[256];
    const long row = blockIdx.x;
    const float* p = S + row * (long)n;
    __half* ph = Sh + row * (long)n;
    const int tid = threadIdx.x;
    float m = -1e30f;
    for (int i = tid; i < n; i += 256) { float v = p[i] * scale; buf[i] = v; m = fmaxf(m, v); }
    red[tid] = m; __syncthreads();
    for (int s = 128; s > 0; s >>= 1) { if (tid < s) red[tid] = fmaxf(red[tid], red[tid + s]); __syncthreads(); }
    m = red[0]; __syncthreads();
    float sum = 0.f;
    for (int i = tid; i < n; i += 256) { float e = expf(buf[i] - m); buf[i] = e; sum += e; }
    red[tid] = sum; __syncthreads();
    for (int s = 128; s > 0; s >>= 1) { if (tid < s) red[tid] += red[tid + s]; __syncthreads(); }
    float inv = 1.f / red[0];
    for (int i = tid; i < n; i += 256) ph[i] = __float2half(buf[i] * inv);
}

// ===================== launcher ===================================================
extern "C" void kernel_launch(void* const* d_in, const int* in_sizes, int n_in,
                              void* d_out, int out_size)
{
    const float* xs  = (const float*)d_in[0];
    const float* Wq  = (const float*)d_in[2];
    const float* bq  = (const float*)d_in[3];
    const float* Wk  = (const float*)d_in[4];
    const float* bk  = (const float*)d_in[5];
    const float* Wv  = (const float*)d_in[6];
    const float* bv  = (const float*)d_in[7];
    const float* Wl  = (const float*)d_in[8];
    const float* bl  = (const float*)d_in[9];
    const float* Wf1 = (const float*)d_in[10];
    const float* bf1 = (const float*)d_in[11];
    const float* Wf2 = (const float*)d_in[12];
    const float* bf2 = (const float*)d_in[13];
    float* out = (float*)d_out;

    __half *gQp, *gKp, *gVp, *gXsh, *gAtth, *gXs1h, *gFfh, *gSh;
    __half *gWqh, *gWkh, *gWvh, *gWlh, *gWf1h, *gWf2h;
    float *gS, *gPart, *gXs1;
    cudaGetSymbolAddress((void**)&gQp,   g_Qp);
    cudaGetSymbolAddress((void**)&gKp,   g_Kp);
    cudaGetSymbolAddress((void**)&gVp,   g_Vp);
    cudaGetSymbolAddress((void**)&gS,    g_S);
    cudaGetSymbolAddress((void**)&gSh,   g_Sh);
    cudaGetSymbolAddress((void**)&gPart, g_part);
    cudaGetSymbolAddress((void**)&gXs1,  g_xs1);
    cudaGetSymbolAddress((void**)&gXsh,  g_xsh);
    cudaGetSymbolAddress((void**)&gAtth, g_atth);
    cudaGetSymbolAddress((void**)&gXs1h, g_xs1h);
    cudaGetSymbolAddress((void**)&gFfh,  g_ffh);
    cudaGetSymbolAddress((void**)&gWqh,  g_Wqh);
    cudaGetSymbolAddress((void**)&gWkh,  g_Wkh);
    cudaGetSymbolAddress((void**)&gWvh,  g_Wvh);
    cudaGetSymbolAddress((void**)&gWlh,  g_Wlh);
    cudaGetSymbolAddress((void**)&gWf1h, g_Wf1h);
    cudaGetSymbolAddress((void**)&gWf2h, g_Wf2h);

    cudaFuncSetAttribute(hconvK_kernel,
                         cudaFuncAttributeMaxDynamicSharedMemorySize, HK_SMEM);

    dim3 blk(256);
    dim3 qgrid(NIMG * 32, 2);

    // pre-convert inputs + weights (batched launches)
    f2h_kernel<<<16384, blk>>>(xs, gXsh);
    f2h3_kernel<<<192, blk>>>(Wq, Wk, Wv, gWqh, gWkh, gWvh);
    wtrans3_kernel<<<3 * 2304, blk>>>(Wl, Wf1, Wf2, gWlh, gWf1h, gWf2h);

    // QKV projections -> patchified half buffers (bias fused)
    hconv2_kernel<<<qgrid, blk>>>(gXsh, gWqh, bq, gQp);
    hconv2_kernel<<<qgrid, blk>>>(gXsh, gWkh, bk, gKp);
    hconv2_kernel<<<qgrid, blk>>>(gXsh, gWvh, bv, gVp);

    // ---- P=32 (n=32, d=65536) ----
    {
        const int n = 32, d = 65536, splitk = 256;
        hgemm32_kernel<<<dim3(1, 1, 2 * splitk), 64>>>(gQp, gKp, gPart, d, splitk);
        rsm_kernel<<<2 * n, blk>>>(gPart, gSh, n, splitk, 1.0f / 256.0f);
        gemm_av32_kernel<<<dim3(d / 64, 1, 2), blk>>>(gSh, gVp, gAtth, n, d, 5, 0);
    }
    // ---- P=16 (n=128, d=16384) ----
    {
        const int n = 128, d = 16384, splitk = 64;
        const long soff = 4194304;
        hgemm_nt_kernel<<<dim3(1, 1, 2 * splitk), blk>>>(
            gQp + soff, gKp + soff, gPart, n, d, splitk, (long)n * d, (long)n * n);
        rsm_kernel<<<2 * n, blk>>>(gPart, gSh, n, splitk, 1.0f / 128.0f);
        hgemm_av_kernel<<<dim3(d / 128, n / 128, 2), blk>>>(gSh, gVp + soff, gAtth, n, d, 4, 64);
    }
    // ---- P=8 (n=512, d=4096) ----
    {
        const int n = 512, d = 4096, splitk = 8;
        const long soff = 2L * 4194304;
        hgemm_nt_kernel<<<dim3(n / 128, n / 128, 2 * splitk), blk>>>(
            gQp + soff, gKp + soff, gPart, n, d, splitk, (long)n * d, (long)n * n);
        rsm_kernel<<<2 * n, blk>>>(gPart, gSh, n, splitk, 1.0f / 64.0f);
        hgemm_av_kernel<<<dim3(d / 128, n / 128, 2), blk>>>(gSh, gVp + soff, gAtth, n, d, 3, 128);
    }
    // ---- P=4 (n=2048, d=1024) ----
    {
        const int n = 2048, d = 1024;
        const long soff = 3L * 4194304;
        hgemm_nt_kernel<<<dim3(n / 128, n / 128, 2), blk>>>(
            gQp + soff, gKp + soff, gS, n, d, 1, (long)n * d, (long)n * n);
        softmax_kernel<<<2 * n, blk>>>(gS, gSh, n, 1.0f / 32.0f);
        hgemm_av_kernel<<<dim3(d / 128, n / 128, 2), blk>>>(gSh, gVp + soff, gAtth, n, d, 2, 192);
    }

    // convs: 128-pixel tiles, K-chunk 64 (R9 hconvK)
    hconvK_kernel<<<qgrid, blk, HK_SMEM>>>(gAtth, gWlh,  bl,  xs,      gXs1,    gXs1h, 1, 1);
    hconvK_kernel<<<qgrid, blk, HK_SMEM>>>(gXs1h, gWf1h, bf1, nullptr, nullptr, gFfh,  1, 0);
    hconvK_kernel<<<qgrid, blk, HK_SMEM>>>(gFfh,  gWf2h, bf2, gXs1,    out,     nullptr, 2, 1);
}

// round 13
// speedup vs baseline: 1.1630x; 1.1008x over previous
#include <cuda_runtime.h>
#include <cuda_fp16.h>
#include <math.h>
#include <stdint.h>

#define NIMG 16
#define CCH 256
#define NPIX 4096            // 64*64

// ---- scratch (static device globals; no allocation) ----
__device__ __half g_Qp[16777216];
__device__ __half g_Kp[16777216];
__device__ __half g_Vp[16777216];
__device__ float  g_S[2*2048*2048];
__device__ __half g_Sh[2*2048*2048];
__device__ float  g_part[8388608];
__device__ __half g_xsh [NIMG*CCH*NPIX];
__device__ __half g_atth[NIMG*CCH*NPIX];
__device__ __half g_xs1h[NIMG*CCH*NPIX];
__device__ __half g_ffh [NIMG*CCH*NPIX];
__device__ __half g_Wqh[65536], g_Wkh[65536], g_Wvh[65536];
__device__ __half g_Wlh[589824], g_Wf1h[589824], g_Wf2h[589824];   // tap-row-major

// ============================================================================
// helpers
// ============================================================================
__device__ __forceinline__ void mma16(float* d, const uint32_t* a, const uint32_t* b) {
    asm volatile(
        "mma.sync.aligned.m16n8k16.row.col.f32.f16.f16.f32 "
        "{%0,%1,%2,%3}, {%4,%5,%6,%7}, {%8,%9}, {%0,%1,%2,%3};"
        : "+f"(d[0]), "+f"(d[1]), "+f"(d[2]), "+f"(d[3])
        : "r"(a[0]), "r"(a[1]), "r"(a[2]), "r"(a[3]), "r"(b[0]), "r"(b[1]));
}

__device__ __forceinline__ void ldsm4(uint32_t* r, const void* p) {
    uint32_t addr = (uint32_t)__cvta_generic_to_shared(p);
    asm volatile("ldmatrix.sync.aligned.m8n8.x4.shared.b16 {%0,%1,%2,%3}, [%4];"
        : "=r"(r[0]), "=r"(r[1]), "=r"(r[2]), "=r"(r[3]) : "r"(addr));
}

__device__ __forceinline__ void ldsm4t(uint32_t* r, const void* p) {
    uint32_t addr = (uint32_t)__cvta_generic_to_shared(p);
    asm volatile("ldmatrix.sync.aligned.m8n8.x4.trans.shared.b16 {%0,%1,%2,%3}, [%4];"
        : "=r"(r[0]), "=r"(r[1]), "=r"(r[2]), "=r"(r[3]) : "r"(addr));
}

__device__ __forceinline__ uint32_t pack_h2(float a, float b) {
    __half2 h = __floats2half2_rn(a, b);
    return *(uint32_t*)&h;
}

__device__ __forceinline__ void cpa16(uint32_t dst, const void* src, unsigned sz) {
    asm volatile("cp.async.ca.shared.global [%0], [%1], 16, %2;"
                 :: "r"(dst), "l"(src), "r"(sz) : "memory");
}
__device__ __forceinline__ void cpcommit() {
    asm volatile("cp.async.commit_group;" ::: "memory");
}
template <int N>
__device__ __forceinline__ void cpwait() {
    asm volatile("cp.async.wait_group %0;" :: "n"(N) : "memory");
}

// f32 -> f16 bulk convert (exact multiples of 1024 elems)
__global__ void f2h_kernel(const float* __restrict__ src, __half* __restrict__ dst) {
    long i = ((long)blockIdx.x * 256 + threadIdx.x) * 4;
    float4 v = *(const float4*)(src + i);
    *(uint32_t*)(dst + i)     = pack_h2(v.x, v.y);
    *(uint32_t*)(dst + i + 2) = pack_h2(v.z, v.w);
}

// batched f2h for the three 65536-elem QKV weights (grid 192)
__global__ void f2h3_kernel(const float* __restrict__ s0, const float* __restrict__ s1,
                            const float* __restrict__ s2,
                            __half* __restrict__ d0, __half* __restrict__ d1,
                            __half* __restrict__ d2) {
    int z = blockIdx.x >> 6;
    const float* s = (z == 0) ? s0 : ((z == 1) ? s1 : s2);
    __half* d = (z == 0) ? d0 : ((z == 1) ? d1 : d2);
    long i = ((long)(blockIdx.x & 63) * 256 + threadIdx.x) * 4;
    float4 v = *(const float4*)(s + i);
    *(uint32_t*)(d + i)     = pack_h2(v.x, v.y);
    *(uint32_t*)(d + i + 2) = pack_h2(v.z, v.w);
}

// batched conv weight permute to tap-row-major:
//   kNew = ((dy*4 + cg)*3 + tx)*64 + ci  <-  W[oc][cg*64+ci][dy*3+tx]
__global__ void wtrans3_kernel(const float* __restrict__ W0, const float* __restrict__ W1,
                               const float* __restrict__ W2,
                               __half* __restrict__ D0, __half* __restrict__ D1,
                               __half* __restrict__ D2) {
    int z = blockIdx.x / 2304;
    const float* W = (z == 0) ? W0 : ((z == 1) ? W1 : W2);
    __half* Wt2 = (z == 0) ? D0 : ((z == 1) ? D1 : D2);
    int idx = (blockIdx.x - z * 2304) * 256 + threadIdx.x;
    int oc = idx / 2304, r = idx - oc * 2304;
    int dy = r / 768;   int r2 = r - dy * 768;
    int cg = r2 / 192;  int r3 = r2 - cg * 192;
    int tx = r3 / 64;   int ci = r3 - tx * 64;
    Wt2[idx] = __float2half(W[oc * 2304 + (cg * 64 + ci) * 9 + dy * 3 + tx]);
}

// scatter index into patchified buffer: scale = oc>>6
__device__ __forceinline__ long pat_index(int img, int oc, int pix) {
    int s  = oc >> 6, cc = oc & 63;
    int lp = 5 - s;
    int lo = 1 + s;
    int Pm = (1 << lp) - 1;
    int y = pix >> 6, x = pix & 63;
    int ohi = y >> lp, pi = y & Pm, owi = x >> lp, pj = x & Pm;
    int t = img & 7, b = img >> 3;
    int nn = (t << (2*lo)) + (ohi << lo) + owi;
    int dd = (cc << (2*lp)) + (pi << lp) + pj;
    return (long)s * 4194304 + (long)b * 2097152 + (long)nn * (64 << (2*lp)) + dd;
}

// ============================================================================
// hconv2 (ks==1): QKV projection, cp.async pipelined, 256 threads
// ============================================================================
__global__ void __launch_bounds__(256, 2) hconv2_kernel(
    const __half* __restrict__ in, const __half* __restrict__ Wt,
    const float* __restrict__ bias, __half* __restrict__ outh_pat)
{
    __shared__ __half A2[2 * 128 * 40];
    __shared__ __half B2[2 * 32 * 136];

    const int tid = threadIdx.x;
    const int lane = tid & 31, wid = tid >> 5;
    const int wm = wid & 1, wn = wid >> 1;
    const int img = blockIdx.x >> 5;
    const int p0 = (blockIdx.x & 31) * 128;
    const int m0 = blockIdx.y * 128;
    const __half* inimg = in + (long)img * CCH * NPIX;

    const uint32_t sA2 = (uint32_t)__cvta_generic_to_shared(A2);
    const uint32_t sB2 = (uint32_t)__cvta_generic_to_shared(B2);

#define ISSUE1(KCN, NB)                                                         \
    {                                                                           \
        const int k0n = (KCN) * 32;                                             \
        {                                                                       \
            int row = tid >> 1, seg = (tid & 1) * 16;                           \
            const __half* src = Wt + (long)(m0 + row) * 256 + k0n + seg;        \
            uint32_t dst = sA2 + (uint32_t)(((NB) * 5120 + row * 40 + seg) * 2);\
            cpa16(dst, src, 16u); cpa16(dst + 16, src + 8, 16u);                \
        }                                                                       \
        {                                                                       \
            int k = tid >> 3, u = tid & 7;                                      \
            const __half* src = inimg + ((long)(k0n + k) << 12) + p0 + u * 8;   \
            uint32_t dst = sB2 + (uint32_t)(((NB) * 4352 + k * 136 + u * 8) * 2); \
            cpa16(dst, src, 16u);                                               \
            cpa16(dst + 128, src + 64, 16u);                                    \
        }                                                                       \
        cpcommit();                                                             \
    }

    float acc[4][4][4] = {};
    ISSUE1(0, 0);

    for (int kc = 0; kc < 8; kc++) {
        cpwait<0>();
        __syncthreads();
        if (kc + 1 < 8) ISSUE1(kc + 1, (kc + 1) & 1);

        const __half* Ap = A2 + (kc & 1) * 5120;
        const __half* Bp = B2 + (kc & 1) * 4352;
#pragma unroll
        for (int kstep = 0; kstep < 2; kstep++) {
            uint32_t a[4][4], b[4][2];
            {
                const int arow = wm * 64 + ((lane >> 3) & 1) * 8 + (lane & 7);
                const int akc  = kstep * 16 + (lane >> 4) * 8;
#pragma unroll
                for (int mi = 0; mi < 4; mi++)
                    ldsm4(a[mi], Ap + (arow + mi * 16) * 40 + akc);
            }
            {
                const int brow = kstep * 16 + (lane & 7) + ((lane >> 3) & 1) * 8;
#pragma unroll
                for (int ni2 = 0; ni2 < 2; ni2++) {
                    const int bcol = wn * 32 + ni2 * 16 + ((lane >> 4) & 1) * 8;
                    uint32_t r[4];
                    ldsm4t(r, Bp + brow * 136 + bcol);
                    b[2*ni2    ][0] = r[0]; b[2*ni2    ][1] = r[1];
                    b[2*ni2 + 1][0] = r[2]; b[2*ni2 + 1][1] = r[3];
                }
            }
#pragma unroll
            for (int mi = 0; mi < 4; mi++)
#pragma unroll
                for (int ni = 0; ni < 4; ni++)
                    mma16(acc[mi][ni], a[mi], b[ni]);
        }
    }
#undef ISSUE1

    const int orow = m0 + wm * 64 + (lane >> 2);
    const int ocol = p0 + wn * 32 + (lane & 3) * 2;
#pragma unroll
    for (int mi = 0; mi < 4; mi++) {
        const int oca = orow + mi * 16, ocb = oca + 8;
        const float ba = bias[oca], bb = bias[ocb];
#pragma unroll
        for (int ni = 0; ni < 4; ni++) {
            const int n = ocol + ni * 8;
            long ia = pat_index(img, oca, n);
            long ib = pat_index(img, ocb, n);
            *(__half2*)(outh_pat + ia) = __floats2half2_rn(acc[mi][ni][0] + ba, acc[mi][ni][1] + ba);
            *(__half2*)(outh_pat + ib) = __floats2half2_rn(acc[mi][ni][2] + bb, acc[mi][ni][3] + bb);
        }
    }
}

// ============================================================================
// hconvK: 3x3 conv, tap-ROW-major K (strip shared by 3 chunks), 256 threads,
//   M=128 x N=128, K-chunk 64, A double-buffered, Strip/Bs single-buffered
//   chunk kc: dy = kc/12, cg = (kc%12)/3, tx = kc%3; strip loaded when tx==0
// ============================================================================
#define HK_A2    0
#define HK_BS    18432
#define HK_STRIP (18432 + 8704)
#define HK_SMEM  ((18432 + 8704 + 10240) * 2)

__global__ void __launch_bounds__(256, 2) hconvK_kernel(
    const __half* __restrict__ in, const __half* __restrict__ Wt,
    const float* __restrict__ bias, const float* __restrict__ res,
    const __half* __restrict__ resh,
    float* __restrict__ out, __half* __restrict__ outh_img,
    int dil, int addres)
{
    extern __shared__ __half sh[];
    __half* A2    = sh + HK_A2;
    __half* Bs    = sh + HK_BS;
    __half* Strip = sh + HK_STRIP;

    const int tid = threadIdx.x;
    const int lane = tid & 31, wid = tid >> 5;
    const int wm = wid & 1, wn = wid >> 1;
    const int img = blockIdx.x >> 5;
    const int p0 = (blockIdx.x & 31) * 128;
    const int y0 = p0 >> 6;
    const int m0 = blockIdx.y * 128;
    const __half* inimg = in + (long)img * CCH * NPIX;

    const uint32_t sA2    = (uint32_t)__cvta_generic_to_shared(A2);
    const uint32_t sStrip = (uint32_t)__cvta_generic_to_shared(Strip);

    // zero strip halos once
    {
        int c = tid >> 2, u = tid & 3, r = u >> 1, side = u & 1;
        *(uint4*)(Strip + c * 160 + r * 80 + side * 72) = make_uint4(0, 0, 0, 0);
    }

#define ISSUE_A(KCN, NB)                                                         \
    {                                                                            \
        int row = tid >> 1, seg = (tid & 1) * 32;                                \
        const __half* src = Wt + (long)(m0 + row) * 2304 + (KCN) * 64 + seg;     \
        uint32_t dst = sA2 + (uint32_t)(((NB) * 9216 + row * 72 + seg) * 2);     \
        cpa16(dst,      src,      16u);                                          \
        cpa16(dst + 16, src + 8,  16u);                                          \
        cpa16(dst + 32, src + 16, 16u);                                          \
        cpa16(dst + 48, src + 24, 16u);                                          \
    }

#define ISSUE_S(KCN)                                                             \
    {   /* strip: 64 ch x 2 rows x 64 px; chunk's dy = KCN/12, cg = (KCN%12)/3 */\
        int dyg = (KCN) / 12;                                                    \
        int c0v = (((KCN) % 12) / 3) * 64;                                       \
        int dyd = (dyg - 1) * dil;                                               \
        int c = tid >> 2, u = tid & 3;                                           \
        int r = u >> 1, s = u & 1;                                               \
        int gy = y0 + r + dyd;                                                   \
        unsigned ok = ((unsigned)gy < 64u) ? 16u : 0u;                           \
        int gyc = gy < 0 ? 0 : (gy > 63 ? 63 : gy);                              \
        const __half* src = inimg + ((long)(c0v + c) << 12) + (gyc << 6) + s * 32; \
        uint32_t dst = sStrip + (uint32_t)((c * 160 + r * 80 + 8 + s * 32) * 2); \
        cpa16(dst,      src,      ok);                                           \
        cpa16(dst + 16, src + 8,  ok);                                           \
        cpa16(dst + 32, src + 16, ok);                                           \
        cpa16(dst + 48, src + 24, ok);                                           \
    }

    float acc[4][4][4] = {};
    ISSUE_A(0, 0);
    ISSUE_S(0);
    cpcommit();

    for (int kc = 0; kc < 36; kc++) {
        cpwait<0>();
        __syncthreads();

        // build shifted B tile (64 k-rows x 128 px) from strip; dx = kc%3 - 1
        {
            const int dxd = (kc % 3 - 1) * dil;
            const int c = tid >> 2, u = tid & 3, prow = u >> 1, xseg = (u & 1) * 32;
            const uint32_t* rowp = (const uint32_t*)(Strip + c * 160 + prow * 80);
            const int h0 = 8 + dxd + xseg;
            uint32_t w[16];
            if (dxd & 1) {
                int k0 = (h0 - 1) >> 1;
                uint32_t prev = rowp[k0];
#pragma unroll
                for (int j = 0; j < 16; j++) {
                    uint32_t nxt = rowp[k0 + 1 + j];
                    w[j] = __funnelshift_r(prev, nxt, 16);
                    prev = nxt;
                }
            } else {
                int k0 = h0 >> 1;
#pragma unroll
                for (int j = 0; j < 16; j++) w[j] = rowp[k0 + j];
            }
            uint4* bd = (uint4*)(Bs + c * 136 + prow * 64 + xseg);
#pragma unroll
            for (int j = 0; j < 4; j++)
                bd[j] = make_uint4(w[4*j], w[4*j+1], w[4*j+2], w[4*j+3]);
        }
        __syncthreads();

        if (kc + 1 < 36) {
            ISSUE_A(kc + 1, (kc + 1) & 1);
            if ((kc + 1) % 3 == 0) ISSUE_S(kc + 1);
            cpcommit();
        }

        const __half* Ap = A2 + (kc & 1) * 9216;
#pragma unroll
        for (int kstep = 0; kstep < 4; kstep++) {
            uint32_t a[4][4], b[4][2];
            {
                const int arow = wm * 64 + ((lane >> 3) & 1) * 8 + (lane & 7);
                const int akc  = kstep * 16 + (lane >> 4) * 8;
#pragma unroll
                for (int mi = 0; mi < 4; mi++)
                    ldsm4(a[mi], Ap + (arow + mi * 16) * 72 + akc);
            }
            {
                const int brow = kstep * 16 + (lane & 7) + ((lane >> 3) & 1) * 8;
#pragma unroll
                for (int ni2 = 0; ni2 < 2; ni2++) {
                    const int bcol = wn * 32 + ni2 * 16 + ((lane >> 4) & 1) * 8;
                    uint32_t r[4];
                    ldsm4t(r, Bs + brow * 136 + bcol);
                    b[2*ni2    ][0] = r[0]; b[2*ni2    ][1] = r[1];
                    b[2*ni2 + 1][0] = r[2]; b[2*ni2 + 1][1] = r[3];
                }
            }
#pragma unroll
            for (int mi = 0; mi < 4; mi++)
#pragma unroll
                for (int ni = 0; ni < 4; ni++)
                    mma16(acc[mi][ni], a[mi], b[ni]);
        }
    }
#undef ISSUE_A
#undef ISSUE_S

    const int orow = m0 + wm * 64 + (lane >> 2);
    const int ocol = p0 + wn * 32 + (lane & 3) * 2;
#pragma unroll
    for (int mi = 0; mi < 4; mi++) {
        const int oca = orow + mi * 16;
        const int ocb = oca + 8;
        const float ba = bias[oca], bb = bias[ocb];
#pragma unroll
        for (int ni = 0; ni < 4; ni++) {
            const int n = ocol + ni * 8;
            long ia = ((long)img * 256 + oca) * NPIX + n;
            long ib = ((long)img * 256 + ocb) * NPIX + n;
            float v0 = acc[mi][ni][0] + ba, v1 = acc[mi][ni][1] + ba;
            float v2 = acc[mi][ni][2] + bb, v3 = acc[mi][ni][3] + bb;
            v0 = (v0 > 0.f) ? v0 : 0.2f * v0;
            v1 = (v1 > 0.f) ? v1 : 0.2f * v1;
            v2 = (v2 > 0.f) ? v2 : 0.2f * v2;
            v3 = (v3 > 0.f) ? v3 : 0.2f * v3;
            if (addres) {
                if (resh) {
                    __half2 ra = *(const __half2*)(resh + ia);
                    __half2 rb = *(const __half2*)(resh + ib);
                    float2 fa = __half22float2(ra), fb = __half22float2(rb);
                    v0 += fa.x; v1 += fa.y; v2 += fb.x; v3 += fb.y;
                } else {
                    v0 += res[ia]; v1 += res[ia + 1];
                    v2 += res[ib]; v3 += res[ib + 1];
                }
            }
            if (out) {
                out[ia] = v0; out[ia + 1] = v1;
                out[ib] = v2; out[ib + 1] = v3;
            }
            if (outh_img) {
                *(__half2*)(outh_img + ia) = __floats2half2_rn(v0, v1);
                *(__half2*)(outh_img + ib) = __floats2half2_rn(v2, v3);
            }
        }
    }
}

// ============================================================================
// fp16 NT GEMM with deterministic split-K (scores), f32 out
// ============================================================================
__global__ void __launch_bounds__(256) hgemm_nt_kernel(
    const __half* __restrict__ A, const __half* __restrict__ B, float* __restrict__ C,
    int N, int K, int splitk, long sAB, long sC)
{
    __shared__ __half As[128 * 40];
    __shared__ __half Bs[128 * 40];
    const int tid = threadIdx.x;
    const int lane = tid & 31, wid = tid >> 5;
    const int wm = wid & 1, wn = wid >> 1;
    const int n0 = blockIdx.x * 128, m0 = blockIdx.y * 128;
    const int z = blockIdx.z, bat = z / splitk, ks = z - bat * splitk;
    A += (long)bat * sAB;
    B += (long)bat * sAB;
    C += (long)z * sC;
    const int kchunk = K / splitk, kbeg = ks * kchunk;
    const int wr = tid >> 1, wkh = (tid & 1) * 16;

    float acc[4][4][4] = {};
    for (int k0 = kbeg; k0 < kbeg + kchunk; k0 += 32) {
        __syncthreads();
        {
            const __half* sa = A + (long)(m0 + wr) * K + k0 + wkh;
            const __half* sb = B + (long)(n0 + wr) * K + k0 + wkh;
            *(uint4*)(As + wr * 40 + wkh)     = *(const uint4*)sa;
            *(uint4*)(As + wr * 40 + wkh + 8) = *(const uint4*)(sa + 8);
            *(uint4*)(Bs + wr * 40 + wkh)     = *(const uint4*)sb;
            *(uint4*)(Bs + wr * 40 + wkh + 8) = *(const uint4*)(sb + 8);
        }
        __syncthreads();
#pragma unroll
        for (int kstep = 0; kstep < 2; kstep++) {
            uint32_t a[4][4], b[4][2];
            {
                const int arow = wm * 64 + ((lane >> 3) & 1) * 8 + (lane & 7);
                const int akc  = kstep * 16 + (lane >> 4) * 8;
#pragma unroll
                for (int mi = 0; mi < 4; mi++)
                    ldsm4(a[mi], As + (arow + mi * 16) * 40 + akc);
            }
            {
                const int bkc = kstep * 16 + ((lane >> 3) & 1) * 8;
#pragma unroll
                for (int ni2 = 0; ni2 < 2; ni2++) {
                    const int brow = wn * 32 + ni2 * 16 + ((lane >> 4) & 1) * 8 + (lane & 7);
                    uint32_t r[4];
                    ldsm4(r, Bs + brow * 40 + bkc);
                    b[2*ni2    ][0] = r[0]; b[2*ni2    ][1] = r[1];
                    b[2*ni2 + 1][0] = r[2]; b[2*ni2 + 1][1] = r[3];
                }
            }
#pragma unroll
            for (int mi = 0; mi < 4; mi++)
#pragma unroll
                for (int ni = 0; ni < 4; ni++)
                    mma16(acc[mi][ni], a[mi], b[ni]);
        }
    }
    const int orow = m0 + wm * 64 + (lane >> 2);
    const int ocol = n0 + wn * 32 + (lane & 3) * 2;
#pragma unroll
    for (int mi = 0; mi < 4; mi++) {
        long ra = (long)(orow + mi * 16) * N;
        long rb = (long)(orow + mi * 16 + 8) * N;
#pragma unroll
        for (int ni = 0; ni < 4; ni++) {
            int n = ocol + ni * 8;
            C[ra + n] = acc[mi][ni][0]; C[ra + n + 1] = acc[mi][ni][1];
            C[rb + n] = acc[mi][ni][2]; C[rb + n + 1] = acc[mi][ni][3];
        }
    }
}

// ============================================================================
// fp16 AV GEMM (probs in HALF, NN via trans-ldmatrix B), scatter -> half image
// ============================================================================
__global__ void __launch_bounds__(256) hgemm_av_kernel(
    const __half* __restrict__ S, const __half* __restrict__ V, __half* __restrict__ out,
    int n, int d, int lp, int c0)
{
    __shared__ __half As[128 * 40];
    __shared__ __half Bs[32 * 136];
    const int tid = threadIdx.x;
    const int lane = tid & 31, wid = tid >> 5;
    const int wm = wid & 1, wn = wid >> 1;
    const int z = blockIdx.z;
    S += (long)z * n * n;
    V += (long)z * n * d;
    const int n0 = blockIdx.x * 128;
    const int m0 = blockIdx.y * 128;
    const int wr = tid >> 1, wkh = (tid & 1) * 16;
    const int bk = tid >> 3, bn0 = (tid & 7) * 16;

    float acc[4][4][4] = {};
    for (int k0 = 0; k0 < n; k0 += 32) {
        __syncthreads();
        {
            const __half* sa = S + (long)(m0 + wr) * n + k0 + wkh;
            *(uint4*)(As + wr * 40 + wkh)     = *(const uint4*)sa;
            *(uint4*)(As + wr * 40 + wkh + 8) = *(const uint4*)(sa + 8);
            const __half* sb = V + (long)(k0 + bk) * d + n0 + bn0;
            *(uint4*)(Bs + bk * 136 + bn0)     = *(const uint4*)sb;
            *(uint4*)(Bs + bk * 136 + bn0 + 8) = *(const uint4*)(sb + 8);
        }
        __syncthreads();
#pragma unroll
        for (int kstep = 0; kstep < 2; kstep++) {
            uint32_t a[4][4], b[4][2];
            {
                const int arow = wm * 64 + ((lane >> 3) & 1) * 8 + (lane & 7);
                const int akc  = kstep * 16 + (lane >> 4) * 8;
#pragma unroll
                for (int mi = 0; mi < 4; mi++)
                    ldsm4(a[mi], As + (arow + mi * 16) * 40 + akc);
            }
            {
                const int brow = kstep * 16 + (lane & 7) + ((lane >> 3) & 1) * 8;
#pragma unroll
                for (int ni2 = 0; ni2 < 2; ni2++) {
                    const int bcol = wn * 32 + ni2 * 16 + ((lane >> 4) & 1) * 8;
                    uint32_t r[4];
                    ldsm4t(r, Bs + brow * 136 + bcol);
                    b[2*ni2    ][0] = r[0]; b[2*ni2    ][1] = r[1];
                    b[2*ni2 + 1][0] = r[2]; b[2*ni2 + 1][1] = r[3];
                }
            }
#pragma unroll
            for (int mi = 0; mi < 4; mi++)
#pragma unroll
                for (int ni = 0; ni < 4; ni++)
                    mma16(acc[mi][ni], a[mi], b[ni]);
        }
    }

    const int lo = 6 - lp;
    const int orow = m0 + wm * 64 + (lane >> 2);
    const int ocol = n0 + wn * 32 + (lane & 3) * 2;
#pragma unroll
    for (int mi = 0; mi < 4; mi++) {
#pragma unroll
        for (int hf = 0; hf < 2; hf++) {
            const int m = orow + mi * 16 + hf * 8;
            const int t = m >> (2 * lo);
            const int r = m & ((1 << (2 * lo)) - 1);
            const int ohi = r >> lo, owi = r & ((1 << lo) - 1);
#pragma unroll
            for (int ni = 0; ni < 4; ni++) {
                const int col = ocol + ni * 8;
                const int cc = col >> (2 * lp);
                const int rr = col & ((1 << (2 * lp)) - 1);
                const int pi = rr >> lp, pj = rr & ((1 << lp) - 1);
                long dst = ((long)((z * 8 + t) * 256 + c0 + cc) << 12)
                         + (((ohi << lp) + pi) << 6) + (owi << lp) + pj;
                *(__half2*)(out + dst) = __floats2half2_rn(acc[mi][ni][hf*2], acc[mi][ni][hf*2 + 1]);
            }
        }
    }
}

// ============================================================================
// fp16 mma 32x32 NT split-K (P=32 scores): 2 warps, cross-warp smem reduce
// ============================================================================
__global__ void __launch_bounds__(64) hgemm32_kernel(
    const __half* __restrict__ A, const __half* __restrict__ B, float* __restrict__ C,
    int K, int splitk)
{
    __shared__ __half Qs[32 * 136];
    __shared__ __half Ks[32 * 136];
    __shared__ float buf[32][33];
    const int tid = threadIdx.x;
    const int lane = tid & 31, wrp = tid >> 5;
    const int z = blockIdx.z, bat = z / splitk, ks = z - bat * splitk;
    A += (long)bat * 32 * K;
    B += (long)bat * 32 * K;
    const int kchunk = K / splitk, kbeg = ks * kchunk;

    float acc[2][4][4] = {};
    for (int k0 = kbeg; k0 < kbeg + kchunk; k0 += 128) {
        __syncthreads();
#pragma unroll
        for (int i = 0; i < 8; i++) {
            int u = i * 64 + tid;
            int row = u >> 4, seg = (u & 15) * 8;
            *(uint4*)(Qs + row * 136 + seg) = *(const uint4*)(A + (long)row * K + k0 + seg);
            *(uint4*)(Ks + row * 136 + seg) = *(const uint4*)(B + (long)row * K + k0 + seg);
        }
        __syncthreads();
        for (int s = wrp; s < 8; s += 2) {
            const int kc = s * 16;
            uint32_t a[2][4], b[4][2];
            {
                const int arow = ((lane >> 3) & 1) * 8 + (lane & 7);
                const int akc  = kc + (lane >> 4) * 8;
                ldsm4(a[0], Qs + arow * 136 + akc);
                ldsm4(a[1], Qs + (arow + 16) * 136 + akc);
            }
            {
                const int bkc = kc + ((lane >> 3) & 1) * 8;
#pragma unroll
                for (int ni2 = 0; ni2 < 2; ni2++) {
                    const int brow = ni2 * 16 + ((lane >> 4) & 1) * 8 + (lane & 7);
                    uint32_t r[4];
                    ldsm4(r, Ks + brow * 136 + bkc);
                    b[2*ni2    ][0] = r[0]; b[2*ni2    ][1] = r[1];
                    b[2*ni2 + 1][0] = r[2]; b[2*ni2 + 1][1] = r[3];
                }
            }
#pragma unroll
            for (int mi = 0; mi < 2; mi++)
#pragma unroll
                for (int ni = 0; ni < 4; ni++)
                    mma16(acc[mi][ni], a[mi], b[ni]);
        }
    }

    const int rr = lane >> 2, cc = (lane & 3) * 2;
    if (wrp == 0) {
#pragma unroll
        for (int mi = 0; mi < 2; mi++)
#pragma unroll
            for (int ni = 0; ni < 4; ni++) {
                buf[mi*16 + rr    ][ni*8 + cc]     = acc[mi][ni][0];
                buf[mi*16 + rr    ][ni*8 + cc + 1] = acc[mi][ni][1];
                buf[mi*16 + rr + 8][ni*8 + cc]     = acc[mi][ni][2];
                buf[mi*16 + rr + 8][ni*8 + cc + 1] = acc[mi][ni][3];
            }
    }
    __syncthreads();
    if (wrp == 1) {
#pragma unroll
        for (int mi = 0; mi < 2; mi++)
#pragma unroll
            for (int ni = 0; ni < 4; ni++) {
                buf[mi*16 + rr    ][ni*8 + cc]     += acc[mi][ni][0];
                buf[mi*16 + rr    ][ni*8 + cc + 1] += acc[mi][ni][1];
                buf[mi*16 + rr + 8][ni*8 + cc]     += acc[mi][ni][2];
                buf[mi*16 + rr + 8][ni*8 + cc + 1] += acc[mi][ni][3];
            }
    }
    __syncthreads();
    float* Cz = C + (long)z * 1024;
    for (int i = tid; i < 1024; i += 64)
        Cz[i] = buf[i >> 5][i & 31];
}

// ============================================================================
// fused split-K reduce + softmax + fp16 emit (one block per row)
// ============================================================================
__global__ void rsm_kernel(const float* __restrict__ part, __half* __restrict__ Sh,
                           int n, int splitk, float scale)
{
    __shared__ float buf[2048];
    __shared__ float red[256];
    const int row = blockIdx.x;               // 0 .. 2n-1
    const int b = row / n, r = row - b * n;
    const long base = ((long)b * splitk) * n * n + (long)r * n;
    const int tid = threadIdx.x;
    float m = -1e30f;
    for (int i = tid; i < n; i += 256) {
        float s = 0.f;
        for (int ks = 0; ks < splitk; ks++)
            s += part[base + (long)ks * n * n + i];
        s *= scale;
        buf[i] = s;
        m = fmaxf(m, s);
    }
    red[tid] = m; __syncthreads();
    for (int s = 128; s > 0; s >>= 1) { if (tid < s) red[tid] = fmaxf(red[tid], red[tid + s]); __syncthreads(); }
    m = red[0]; __syncthreads();
    float sum = 0.f;
    for (int i = tid; i < n; i += 256) { float e = expf(buf[i] - m); buf[i] = e; sum += e; }
    red[tid] = sum; __syncthreads();
    for (int s = 128; s > 0; s >>= 1) { if (tid < s) red[tid] += red[tid + s]; __syncthreads(); }
    float inv = 1.f / red[0];
    __half* ph = Sh + (long)row * n;
    for (int i = tid; i < n; i += 256) ph[i] = __float2half(buf[i] * inv);
}

// ===================== SIMT AV for P=32 (probs half, half V, half out) ============
__global__ void __launch_bounds__(256) gemm_av32_kernel(
    const __half* __restrict__ A, const __half* __restrict__ B, __half* __restrict__ out,
    int n, int d, int lp, int c0)
{
    const int z = blockIdx.z;
    A += (long)z * n * n;
    B += (long)z * n * d;
    const int m0 = blockIdx.y * 64, n0 = blockIdx.x * 64;
    __shared__ __align__(16) float As[16][68];
    __shared__ __align__(16) float Bs[16][64];
    const int tid = threadIdx.x;
    const int tx = tid & 15, ty = tid >> 4;
    float acc[4][4] = {};
    for (int k0 = 0; k0 < n; k0 += 16) {
#pragma unroll
        for (int it = 0; it < 4; it++) {
            int id = tid + it * 256;
            int m = id >> 4, kk = id & 15;
            As[kk][m] = (m0 + m < n) ? __half2float(A[(long)(m0 + m) * n + k0 + kk]) : 0.f;
        }
#pragma unroll
        for (int it = 0; it < 4; it++) {
            int id = tid + it * 256;
            int kk = id >> 6, nnn = id & 63;
            Bs[kk][nnn] = __half2float(B[(long)(k0 + kk) * d + n0 + nnn]);
        }
        __syncthreads();
#pragma unroll
        for (int kk = 0; kk < 16; kk++) {
            float4 a4 = *(const float4*)&As[kk][ty * 4];
            float4 b4 = *(const float4*)&Bs[kk][tx * 4];
            float ar[4] = {a4.x, a4.y, a4.z, a4.w};
            float br[4] = {b4.x, b4.y, b4.z, b4.w};
#pragma unroll
            for (int i = 0; i < 4; i++)
#pragma unroll
                for (int j = 0; j < 4; j++)
                    acc[i][j] += ar[i] * br[j];
        }
        __syncthreads();
    }
    const int lo = 6 - lp, o = 1 << lo, P = 1 << lp;
#pragma unroll
    for (int i = 0; i < 4; i++) {
        int m = m0 + ty * 4 + i;
        if (m >= n) continue;
        int t = m >> (2 * lo);
        int r = m & ((1 << (2 * lo)) - 1);
        int ohi = r >> lo, owi = r & (o - 1);
        int col = n0 + tx * 4;
        int cc = col >> (2 * lp);
        int rr = col & (P * P - 1);
        int pi = rr >> lp, pj = rr & (P - 1);
        long dst = ((long)((z * 8 + t) * 256 + c0 + cc) << 12)
                 + (((ohi << lp) + pi) << 6) + (owi << lp) + pj;
        *(__half2*)(out + dst)     = __floats2half2_rn(acc[i][0], acc[i][1]);
        *(__half2*)(out + dst + 2) = __floats2half2_rn(acc[i][2], acc[i][3]);
    }
}

// ===================== softmax (f32 in, HALF out; used by P=4 only) ===============
__global__ void softmax_kernel(const float* __restrict__ S, __half* __restrict__ Sh,
                               int n, float scale)
{
    __shared__ float buf[2048];
    __shared__ float red[256];
    const long row = blockIdx.x;
    const float* p = S + row * (long)n;
    __half* ph = Sh + row * (long)n;
    const int tid = threadIdx.x;
    float m = -1e30f;
    for (int i = tid; i < n; i += 256) { float v = p[i] * scale; buf[i] = v; m = fmaxf(m, v); }
    red[tid] = m; __syncthreads();
    for (int s = 128; s > 0; s >>= 1) { if (tid < s) red[tid] = fmaxf(red[tid], red[tid + s]); __syncthreads(); }
    m = red[0]; __syncthreads();
    float sum = 0.f;
    for (int i = tid; i < n; i += 256) { float e = expf(buf[i] - m); buf[i] = e; sum += e; }
    red[tid] = sum; __syncthreads();
    for (int s = 128; s > 0; s >>= 1) { if (tid < s) red[tid] += red[tid + s]; __syncthreads(); }
    float inv = 1.f / red[0];
    for (int i = tid; i < n; i += 256) ph[i] = __float2half(buf[i] * inv);
}

// ===================== launcher ===================================================
extern "C" void kernel_launch(void* const* d_in, const int* in_sizes, int n_in,
                              void* d_out, int out_size)
{
    const float* xs  = (const float*)d_in[0];
    const float* Wq  = (const float*)d_in[2];
    const float* bq  = (const float*)d_in[3];
    const float* Wk  = (const float*)d_in[4];
    const float* bk  = (const float*)d_in[5];
    const float* Wv  = (const float*)d_in[6];
    const float* bv  = (const float*)d_in[7];
    const float* Wl  = (const float*)d_in[8];
    const float* bl  = (const float*)d_in[9];
    const float* Wf1 = (const float*)d_in[10];
    const float* bf1 = (const float*)d_in[11];
    const float* Wf2 = (const float*)d_in[12];
    const float* bf2 = (const float*)d_in[13];
    float* out = (float*)d_out;

    __half *gQp, *gKp, *gVp, *gXsh, *gAtth, *gXs1h, *gFfh, *gSh;
    __half *gWqh, *gWkh, *gWvh, *gWlh, *gWf1h, *gWf2h;
    float *gS, *gPart;
    cudaGetSymbolAddress((void**)&gQp,   g_Qp);
    cudaGetSymbolAddress((void**)&gKp,   g_Kp);
    cudaGetSymbolAddress((void**)&gVp,   g_Vp);
    cudaGetSymbolAddress((void**)&gS,    g_S);
    cudaGetSymbolAddress((void**)&gSh,   g_Sh);
    cudaGetSymbolAddress((void**)&gPart, g_part);
    cudaGetSymbolAddress((void**)&gXsh,  g_xsh);
    cudaGetSymbolAddress((void**)&gAtth, g_atth);
    cudaGetSymbolAddress((void**)&gXs1h, g_xs1h);
    cudaGetSymbolAddress((void**)&gFfh,  g_ffh);
    cudaGetSymbolAddress((void**)&gWqh,  g_Wqh);
    cudaGetSymbolAddress((void**)&gWkh,  g_Wkh);
    cudaGetSymbolAddress((void**)&gWvh,  g_Wvh);
    cudaGetSymbolAddress((void**)&gWlh,  g_Wlh);
    cudaGetSymbolAddress((void**)&gWf1h, g_Wf1h);
    cudaGetSymbolAddress((void**)&gWf2h, g_Wf2h);

    cudaFuncSetAttribute(hconvK_kernel,
                         cudaFuncAttributeMaxDynamicSharedMemorySize, HK_SMEM);

    dim3 blk(256);
    dim3 qgrid(NIMG * 32, 2);

    // pre-convert inputs + weights (batched launches)
    f2h_kernel<<<16384, blk>>>(xs, gXsh);
    f2h3_kernel<<<192, blk>>>(Wq, Wk, Wv, gWqh, gWkh, gWvh);
    wtrans3_kernel<<<3 * 2304, blk>>>(Wl, Wf1, Wf2, gWlh, gWf1h, gWf2h);

    // QKV projections -> patchified half buffers (bias fused)
    hconv2_kernel<<<qgrid, blk>>>(gXsh, gWqh, bq, gQp);
    hconv2_kernel<<<qgrid, blk>>>(gXsh, gWkh, bk, gKp);
    hconv2_kernel<<<qgrid, blk>>>(gXsh, gWvh, bv, gVp);

    // ---- P=32 (n=32, d=65536) ----
    {
        const int n = 32, d = 65536, splitk = 256;
        hgemm32_kernel<<<dim3(1, 1, 2 * splitk), 64>>>(gQp, gKp, gPart, d, splitk);
        rsm_kernel<<<2 * n, blk>>>(gPart, gSh, n, splitk, 1.0f / 256.0f);
        gemm_av32_kernel<<<dim3(d / 64, 1, 2), blk>>>(gSh, gVp, gAtth, n, d, 5, 0);
    }
    // ---- P=16 (n=128, d=16384) ----
    {
        const int n = 128, d = 16384, splitk = 64;
        const long soff = 4194304;
        hgemm_nt_kernel<<<dim3(1, 1, 2 * splitk), blk>>>(
            gQp + soff, gKp + soff, gPart, n, d, splitk, (long)n * d, (long)n * n);
        rsm_kernel<<<2 * n, blk>>>(gPart, gSh, n, splitk, 1.0f / 128.0f);
        hgemm_av_kernel<<<dim3(d / 128, n / 128, 2), blk>>>(gSh, gVp + soff, gAtth, n, d, 4, 64);
    }
    // ---- P=8 (n=512, d=4096) ----
    {
        const int n = 512, d = 4096, splitk = 8;
        const long soff = 2L * 4194304;
        hgemm_nt_kernel<<<dim3(n / 128, n / 128, 2 * splitk), blk>>>(
            gQp + soff, gKp + soff, gPart, n, d, splitk, (long)n * d, (long)n * n);
        rsm_kernel<<<2 * n, blk>>>(gPart, gSh, n, splitk, 1.0f / 64.0f);
        hgemm_av_kernel<<<dim3(d / 128, n / 128, 2), blk>>>(gSh, gVp + soff, gAtth, n, d, 3, 128);
    }
    // ---- P=4 (n=2048, d=1024) ----
    {
        const int n = 2048, d = 1024;
        const long soff = 3L * 4194304;
        hgemm_nt_kernel<<<dim3(n / 128, n / 128, 2), blk>>>(
            gQp + soff, gKp + soff, gS, n, d, 1, (long)n * d, (long)n * n);
        softmax_kernel<<<2 * n, blk>>>(gS, gSh, n, 1.0f / 32.0f);
        hgemm_av_kernel<<<dim3(d / 128, n / 128, 2), blk>>>(gSh, gVp + soff, gAtth, n, d, 2, 192);
    }

    // convs: tap-row-major K, strip shared across 3 chunks; half residual chain
    hconvK_kernel<<<qgrid, blk, HK_SMEM>>>(gAtth, gWlh,  bl,  xs,      nullptr, nullptr, gXs1h, 1, 1);
    hconvK_kernel<<<qgrid, blk, HK_SMEM>>>(gXs1h, gWf1h, bf1, nullptr, nullptr, nullptr, gFfh,  1, 0);
    hconvK_kernel<<<qgrid, blk, HK_SMEM>>>(gFfh,  gWf2h, bf2, nullptr, gXs1h,   out,     nullptr, 2, 1);
}

// round 14
// speedup vs baseline: 1.1955x; 1.0280x over previous
#include <cuda_runtime.h>
#include <cuda_fp16.h>
#include <math.h>
#include <stdint.h>

#define NIMG 16
#define CCH 256
#define NPIX 4096            // 64*64

// ---- scratch (static device globals; no allocation) ----
__device__ __half g_Qp[16777216];
__device__ __half g_Kp[16777216];
__device__ __half g_Vp[16777216];
__device__ float  g_S[2*2048*2048];
__device__ __half g_Sh[2*2048*2048];
__device__ float  g_part[8388608];
__device__ __half g_xsh [NIMG*CCH*NPIX];
__device__ __half g_atth[NIMG*CCH*NPIX];
__device__ __half g_xs1h[NIMG*CCH*NPIX];
__device__ __half g_ffh [NIMG*CCH*NPIX];
__device__ __half g_Wqkvh[196608];                                  // stacked [768][256]
__device__ __half g_Wlh[589824], g_Wf1h[589824], g_Wf2h[589824];   // tap-row-major

// ============================================================================
// helpers
// ============================================================================
__device__ __forceinline__ void mma16(float* d, const uint32_t* a, const uint32_t* b) {
    asm volatile(
        "mma.sync.aligned.m16n8k16.row.col.f32.f16.f16.f32 "
        "{%0,%1,%2,%3}, {%4,%5,%6,%7}, {%8,%9}, {%0,%1,%2,%3};"
        : "+f"(d[0]), "+f"(d[1]), "+f"(d[2]), "+f"(d[3])
        : "r"(a[0]), "r"(a[1]), "r"(a[2]), "r"(a[3]), "r"(b[0]), "r"(b[1]));
}

__device__ __forceinline__ void ldsm4(uint32_t* r, const void* p) {
    uint32_t addr = (uint32_t)__cvta_generic_to_shared(p);
    asm volatile("ldmatrix.sync.aligned.m8n8.x4.shared.b16 {%0,%1,%2,%3}, [%4];"
        : "=r"(r[0]), "=r"(r[1]), "=r"(r[2]), "=r"(r[3]) : "r"(addr));
}

__device__ __forceinline__ void ldsm4t(uint32_t* r, const void* p) {
    uint32_t addr = (uint32_t)__cvta_generic_to_shared(p);
    asm volatile("ldmatrix.sync.aligned.m8n8.x4.trans.shared.b16 {%0,%1,%2,%3}, [%4];"
        : "=r"(r[0]), "=r"(r[1]), "=r"(r[2]), "=r"(r[3]) : "r"(addr));
}

__device__ __forceinline__ uint32_t pack_h2(float a, float b) {
    __half2 h = __floats2half2_rn(a, b);
    return *(uint32_t*)&h;
}

__device__ __forceinline__ void cpa16(uint32_t dst, const void* src, unsigned sz) {
    asm volatile("cp.async.ca.shared.global [%0], [%1], 16, %2;"
                 :: "r"(dst), "l"(src), "r"(sz) : "memory");
}
__device__ __forceinline__ void cpcommit() {
    asm volatile("cp.async.commit_group;" ::: "memory");
}
template <int N>
__device__ __forceinline__ void cpwait() {
    asm volatile("cp.async.wait_group %0;" :: "n"(N) : "memory");
}

// f32 -> f16 bulk convert (exact multiples of 1024 elems)
__global__ void f2h_kernel(const float* __restrict__ src, __half* __restrict__ dst) {
    long i = ((long)blockIdx.x * 256 + threadIdx.x) * 4;
    float4 v = *(const float4*)(src + i);
    *(uint32_t*)(dst + i)     = pack_h2(v.x, v.y);
    *(uint32_t*)(dst + i + 2) = pack_h2(v.z, v.w);
}

// batched f2h: QKV weights into one stacked [768][256] half buffer
__global__ void f2h3_kernel(const float* __restrict__ s0, const float* __restrict__ s1,
                            const float* __restrict__ s2, __half* __restrict__ d) {
    int z = blockIdx.x >> 6;
    const float* s = (z == 0) ? s0 : ((z == 1) ? s1 : s2);
    long i = ((long)(blockIdx.x & 63) * 256 + threadIdx.x) * 4;
    __half* dz = d + (long)z * 65536;
    float4 v = *(const float4*)(s + i);
    *(uint32_t*)(dz + i)     = pack_h2(v.x, v.y);
    *(uint32_t*)(dz + i + 2) = pack_h2(v.z, v.w);
}

// batched conv weight permute to tap-row-major:
//   kNew = ((dy*4 + cg)*3 + tx)*64 + ci  <-  W[oc][cg*64+ci][dy*3+tx]
__global__ void wtrans3_kernel(const float* __restrict__ W0, const float* __restrict__ W1,
                               const float* __restrict__ W2,
                               __half* __restrict__ D0, __half* __restrict__ D1,
                               __half* __restrict__ D2) {
    int z = blockIdx.x / 2304;
    const float* W = (z == 0) ? W0 : ((z == 1) ? W1 : W2);
    __half* Wt2 = (z == 0) ? D0 : ((z == 1) ? D1 : D2);
    int idx = (blockIdx.x - z * 2304) * 256 + threadIdx.x;
    int oc = idx / 2304, r = idx - oc * 2304;
    int dy = r / 768;   int r2 = r - dy * 768;
    int cg = r2 / 192;  int r3 = r2 - cg * 192;
    int tx = r3 / 64;   int ci = r3 - tx * 64;
    Wt2[idx] = __float2half(W[oc * 2304 + (cg * 64 + ci) * 9 + dy * 3 + tx]);
}

// scatter index into patchified buffer: scale = oc>>6 (oc in [0,256))
__device__ __forceinline__ long pat_index(int img, int oc, int pix) {
    int s  = oc >> 6, cc = oc & 63;
    int lp = 5 - s;
    int lo = 1 + s;
    int Pm = (1 << lp) - 1;
    int y = pix >> 6, x = pix & 63;
    int ohi = y >> lp, pi = y & Pm, owi = x >> lp, pj = x & Pm;
    int t = img & 7, b = img >> 3;
    int nn = (t << (2*lo)) + (ohi << lo) + owi;
    int dd = (cc << (2*lp)) + (pi << lp) + pj;
    return (long)s * 4194304 + (long)b * 2097152 + (long)nn * (64 << (2*lp)) + dd;
}

// ============================================================================
// hconv2qkv: fused Q/K/V projection (stacked weights [768][256]), grid.y = 6
// ============================================================================
__global__ void __launch_bounds__(256, 2) hconv2_kernel(
    const __half* __restrict__ in, const __half* __restrict__ Wt,
    const float* __restrict__ bq, const float* __restrict__ bk, const float* __restrict__ bv,
    __half* __restrict__ Qp, __half* __restrict__ Kp, __half* __restrict__ Vp)
{
    __shared__ __half A2[2 * 128 * 40];
    __shared__ __half B2[2 * 32 * 136];

    const int tid = threadIdx.x;
    const int lane = tid & 31, wid = tid >> 5;
    const int wm = wid & 1, wn = wid >> 1;
    const int img = blockIdx.x >> 5;
    const int p0 = (blockIdx.x & 31) * 128;
    const int m0 = blockIdx.y * 128;          // 0..640 over stacked 768 rows
    const int proj = m0 >> 8;
    const __half* inimg = in + (long)img * CCH * NPIX;
    const float* bias = (proj == 0) ? bq : ((proj == 1) ? bk : bv);
    __half* outh_pat = (proj == 0) ? Qp : ((proj == 1) ? Kp : Vp);

    const uint32_t sA2 = (uint32_t)__cvta_generic_to_shared(A2);
    const uint32_t sB2 = (uint32_t)__cvta_generic_to_shared(B2);

#define ISSUE1(KCN, NB)                                                         \
    {                                                                           \
        const int k0n = (KCN) * 32;                                             \
        {                                                                       \
            int row = tid >> 1, seg = (tid & 1) * 16;                           \
            const __half* src = Wt + (long)(m0 + row) * 256 + k0n + seg;        \
            uint32_t dst = sA2 + (uint32_t)(((NB) * 5120 + row * 40 + seg) * 2);\
            cpa16(dst, src, 16u); cpa16(dst + 16, src + 8, 16u);                \
        }                                                                       \
        {                                                                       \
            int k = tid >> 3, u = tid & 7;                                      \
            const __half* src = inimg + ((long)(k0n + k) << 12) + p0 + u * 8;   \
            uint32_t dst = sB2 + (uint32_t)(((NB) * 4352 + k * 136 + u * 8) * 2); \
            cpa16(dst, src, 16u);                                               \
            cpa16(dst + 128, src + 64, 16u);                                    \
        }                                                                       \
        cpcommit();                                                             \
    }

    float acc[4][4][4] = {};
    ISSUE1(0, 0);

    for (int kc = 0; kc < 8; kc++) {
        cpwait<0>();
        __syncthreads();
        if (kc + 1 < 8) ISSUE1(kc + 1, (kc + 1) & 1);

        const __half* Ap = A2 + (kc & 1) * 5120;
        const __half* Bp = B2 + (kc & 1) * 4352;
#pragma unroll
        for (int kstep = 0; kstep < 2; kstep++) {
            uint32_t a[4][4], b[4][2];
            {
                const int arow = wm * 64 + ((lane >> 3) & 1) * 8 + (lane & 7);
                const int akc  = kstep * 16 + (lane >> 4) * 8;
#pragma unroll
                for (int mi = 0; mi < 4; mi++)
                    ldsm4(a[mi], Ap + (arow + mi * 16) * 40 + akc);
            }
            {
                const int brow = kstep * 16 + (lane & 7) + ((lane >> 3) & 1) * 8;
#pragma unroll
                for (int ni2 = 0; ni2 < 2; ni2++) {
                    const int bcol = wn * 32 + ni2 * 16 + ((lane >> 4) & 1) * 8;
                    uint32_t r[4];
                    ldsm4t(r, Bp + brow * 136 + bcol);
                    b[2*ni2    ][0] = r[0]; b[2*ni2    ][1] = r[1];
                    b[2*ni2 + 1][0] = r[2]; b[2*ni2 + 1][1] = r[3];
                }
            }
#pragma unroll
            for (int mi = 0; mi < 4; mi++)
#pragma unroll
                for (int ni = 0; ni < 4; ni++)
                    mma16(acc[mi][ni], a[mi], b[ni]);
        }
    }
#undef ISSUE1

    const int orow = (m0 & 255) + wm * 64 + (lane >> 2);
    const int ocol = p0 + wn * 32 + (lane & 3) * 2;
#pragma unroll
    for (int mi = 0; mi < 4; mi++) {
        const int oca = orow + mi * 16, ocb = oca + 8;
        const float ba = bias[oca], bb = bias[ocb];
#pragma unroll
        for (int ni = 0; ni < 4; ni++) {
            const int n = ocol + ni * 8;
            long ia = pat_index(img, oca, n);
            long ib = pat_index(img, ocb, n);
            *(__half2*)(outh_pat + ia) = __floats2half2_rn(acc[mi][ni][0] + ba, acc[mi][ni][1] + ba);
            *(__half2*)(outh_pat + ib) = __floats2half2_rn(acc[mi][ni][2] + bb, acc[mi][ni][3] + bb);
        }
    }
}

// ============================================================================
// hconvK: 3x3 conv, tap-ROW-major K (strip shared by 3 chunks), 256 threads
// ============================================================================
#define HK_A2    0
#define HK_BS    18432
#define HK_STRIP (18432 + 8704)
#define HK_SMEM  ((18432 + 8704 + 10240) * 2)

__global__ void __launch_bounds__(256, 2) hconvK_kernel(
    const __half* __restrict__ in, const __half* __restrict__ Wt,
    const float* __restrict__ bias, const float* __restrict__ res,
    const __half* __restrict__ resh,
    float* __restrict__ out, __half* __restrict__ outh_img,
    int dil, int addres)
{
    extern __shared__ __half sh[];
    __half* A2    = sh + HK_A2;
    __half* Bs    = sh + HK_BS;
    __half* Strip = sh + HK_STRIP;

    const int tid = threadIdx.x;
    const int lane = tid & 31, wid = tid >> 5;
    const int wm = wid & 1, wn = wid >> 1;
    const int img = blockIdx.x >> 5;
    const int p0 = (blockIdx.x & 31) * 128;
    const int y0 = p0 >> 6;
    const int m0 = blockIdx.y * 128;
    const __half* inimg = in + (long)img * CCH * NPIX;

    const uint32_t sA2    = (uint32_t)__cvta_generic_to_shared(A2);
    const uint32_t sStrip = (uint32_t)__cvta_generic_to_shared(Strip);

    {
        int c = tid >> 2, u = tid & 3, r = u >> 1, side = u & 1;
        *(uint4*)(Strip + c * 160 + r * 80 + side * 72) = make_uint4(0, 0, 0, 0);
    }

#define ISSUE_A(KCN, NB)                                                         \
    {                                                                            \
        int row = tid >> 1, seg = (tid & 1) * 32;                                \
        const __half* src = Wt + (long)(m0 + row) * 2304 + (KCN) * 64 + seg;     \
        uint32_t dst = sA2 + (uint32_t)(((NB) * 9216 + row * 72 + seg) * 2);     \
        cpa16(dst,      src,      16u);                                          \
        cpa16(dst + 16, src + 8,  16u);                                          \
        cpa16(dst + 32, src + 16, 16u);                                          \
        cpa16(dst + 48, src + 24, 16u);                                          \
    }

#define ISSUE_S(KCN)                                                             \
    {                                                                            \
        int dyg = (KCN) / 12;                                                    \
        int c0v = (((KCN) % 12) / 3) * 64;                                       \
        int dyd = (dyg - 1) * dil;                                               \
        int c = tid >> 2, u = tid & 3;                                           \
        int r = u >> 1, s = u & 1;                                               \
        int gy = y0 + r + dyd;                                                   \
        unsigned ok = ((unsigned)gy < 64u) ? 16u : 0u;                           \
        int gyc = gy < 0 ? 0 : (gy > 63 ? 63 : gy);                              \
        const __half* src = inimg + ((long)(c0v + c) << 12) + (gyc << 6) + s * 32; \
        uint32_t dst = sStrip + (uint32_t)((c * 160 + r * 80 + 8 + s * 32) * 2); \
        cpa16(dst,      src,      ok);                                           \
        cpa16(dst + 16, src + 8,  ok);                                           \
        cpa16(dst + 32, src + 16, ok);                                           \
        cpa16(dst + 48, src + 24, ok);                                           \
    }

    float acc[4][4][4] = {};
    ISSUE_A(0, 0);
    ISSUE_S(0);
    cpcommit();

    for (int kc = 0; kc < 36; kc++) {
        cpwait<0>();
        __syncthreads();

        {
            const int dxd = (kc % 3 - 1) * dil;
            const int c = tid >> 2, u = tid & 3, prow = u >> 1, xseg = (u & 1) * 32;
            const uint32_t* rowp = (const uint32_t*)(Strip + c * 160 + prow * 80);
            const int h0 = 8 + dxd + xseg;
            uint32_t w[16];
            if (dxd & 1) {
                int k0 = (h0 - 1) >> 1;
                uint32_t prev = rowp[k0];
#pragma unroll
                for (int j = 0; j < 16; j++) {
                    uint32_t nxt = rowp[k0 + 1 + j];
                    w[j] = __funnelshift_r(prev, nxt, 16);
                    prev = nxt;
                }
            } else {
                int k0 = h0 >> 1;
#pragma unroll
                for (int j = 0; j < 16; j++) w[j] = rowp[k0 + j];
            }
            uint4* bd = (uint4*)(Bs + c * 136 + prow * 64 + xseg);
#pragma unroll
            for (int j = 0; j < 4; j++)
                bd[j] = make_uint4(w[4*j], w[4*j+1], w[4*j+2], w[4*j+3]);
        }
        __syncthreads();

        if (kc + 1 < 36) {
            ISSUE_A(kc + 1, (kc + 1) & 1);
            if ((kc + 1) % 3 == 0) ISSUE_S(kc + 1);
            cpcommit();
        }

        const __half* Ap = A2 + (kc & 1) * 9216;
#pragma unroll
        for (int kstep = 0; kstep < 4; kstep++) {
            uint32_t a[4][4], b[4][2];
            {
                const int arow = wm * 64 + ((lane >> 3) & 1) * 8 + (lane & 7);
                const int akc  = kstep * 16 + (lane >> 4) * 8;
#pragma unroll
                for (int mi = 0; mi < 4; mi++)
                    ldsm4(a[mi], Ap + (arow + mi * 16) * 72 + akc);
            }
            {
                const int brow = kstep * 16 + (lane & 7) + ((lane >> 3) & 1) * 8;
#pragma unroll
                for (int ni2 = 0; ni2 < 2; ni2++) {
                    const int bcol = wn * 32 + ni2 * 16 + ((lane >> 4) & 1) * 8;
                    uint32_t r[4];
                    ldsm4t(r, Bs + brow * 136 + bcol);
                    b[2*ni2    ][0] = r[0]; b[2*ni2    ][1] = r[1];
                    b[2*ni2 + 1][0] = r[2]; b[2*ni2 + 1][1] = r[3];
                }
            }
#pragma unroll
            for (int mi = 0; mi < 4; mi++)
#pragma unroll
                for (int ni = 0; ni < 4; ni++)
                    mma16(acc[mi][ni], a[mi], b[ni]);
        }
    }
#undef ISSUE_A
#undef ISSUE_S

    const int orow = m0 + wm * 64 + (lane >> 2);
    const int ocol = p0 + wn * 32 + (lane & 3) * 2;
#pragma unroll
    for (int mi = 0; mi < 4; mi++) {
        const int oca = orow + mi * 16;
        const int ocb = oca + 8;
        const float ba = bias[oca], bb = bias[ocb];
#pragma unroll
        for (int ni = 0; ni < 4; ni++) {
            const int n = ocol + ni * 8;
            long ia = ((long)img * 256 + oca) * NPIX + n;
            long ib = ((long)img * 256 + ocb) * NPIX + n;
            float v0 = acc[mi][ni][0] + ba, v1 = acc[mi][ni][1] + ba;
            float v2 = acc[mi][ni][2] + bb, v3 = acc[mi][ni][3] + bb;
            v0 = (v0 > 0.f) ? v0 : 0.2f * v0;
            v1 = (v1 > 0.f) ? v1 : 0.2f * v1;
            v2 = (v2 > 0.f) ? v2 : 0.2f * v2;
            v3 = (v3 > 0.f) ? v3 : 0.2f * v3;
            if (addres) {
                if (resh) {
                    __half2 ra = *(const __half2*)(resh + ia);
                    __half2 rb = *(const __half2*)(resh + ib);
                    float2 fa = __half22float2(ra), fb = __half22float2(rb);
                    v0 += fa.x; v1 += fa.y; v2 += fb.x; v3 += fb.y;
                } else {
                    v0 += res[ia]; v1 += res[ia + 1];
                    v2 += res[ib]; v3 += res[ib + 1];
                }
            }
            if (out) {
                out[ia] = v0; out[ia + 1] = v1;
                out[ib] = v2; out[ib + 1] = v3;
            }
            if (outh_img) {
                *(__half2*)(outh_img + ia) = __floats2half2_rn(v0, v1);
                *(__half2*)(outh_img + ib) = __floats2half2_rn(v2, v3);
            }
        }
    }
}

// ============================================================================
// fp16 NT GEMM with split-K (scores), cp.async double-buffered, f32 out
// ============================================================================
__global__ void __launch_bounds__(256) hgemm_nt_kernel(
    const __half* __restrict__ A, const __half* __restrict__ B, float* __restrict__ C,
    int N, int K, int splitk, long sAB, long sC)
{
    __shared__ __half As[2 * 128 * 40];
    __shared__ __half Bs[2 * 128 * 40];
    const int tid = threadIdx.x;
    const int lane = tid & 31, wid = tid >> 5;
    const int wm = wid & 1, wn = wid >> 1;
    const int n0 = blockIdx.x * 128, m0 = blockIdx.y * 128;
    const int z = blockIdx.z, bat = z / splitk, ks = z - bat * splitk;
    A += (long)bat * sAB;
    B += (long)bat * sAB;
    C += (long)z * sC;
    const int kchunk = K / splitk, kbeg = ks * kchunk;
    const int nch = kchunk / 32;
    const int wr = tid >> 1, wkh = (tid & 1) * 16;

    const uint32_t sAs = (uint32_t)__cvta_generic_to_shared(As);
    const uint32_t sBs = (uint32_t)__cvta_generic_to_shared(Bs);

#define ISSUE_NT(K0v, NB)                                                       \
    {                                                                           \
        const __half* sa = A + (long)(m0 + wr) * K + (K0v) + wkh;               \
        const __half* sb = B + (long)(n0 + wr) * K + (K0v) + wkh;               \
        uint32_t da = sAs + (uint32_t)(((NB) * 5120 + wr * 40 + wkh) * 2);      \
        uint32_t db = sBs + (uint32_t)(((NB) * 5120 + wr * 40 + wkh) * 2);      \
        cpa16(da, sa, 16u); cpa16(da + 16, sa + 8, 16u);                        \
        cpa16(db, sb, 16u); cpa16(db + 16, sb + 8, 16u);                        \
        cpcommit();                                                             \
    }

    float acc[4][4][4] = {};
    ISSUE_NT(kbeg, 0);

    for (int i = 0; i < nch; i++) {
        cpwait<0>();
        __syncthreads();
        if (i + 1 < nch) ISSUE_NT(kbeg + (i + 1) * 32, (i + 1) & 1);

        const __half* Ap = As + (i & 1) * 5120;
        const __half* Bp = Bs + (i & 1) * 5120;
#pragma unroll
        for (int kstep = 0; kstep < 2; kstep++) {
            uint32_t a[4][4], b[4][2];
            {
                const int arow = wm * 64 + ((lane >> 3) & 1) * 8 + (lane & 7);
                const int akc  = kstep * 16 + (lane >> 4) * 8;
#pragma unroll
                for (int mi = 0; mi < 4; mi++)
                    ldsm4(a[mi], Ap + (arow + mi * 16) * 40 + akc);
            }
            {
                const int bkc = kstep * 16 + ((lane >> 3) & 1) * 8;
#pragma unroll
                for (int ni2 = 0; ni2 < 2; ni2++) {
                    const int brow = wn * 32 + ni2 * 16 + ((lane >> 4) & 1) * 8 + (lane & 7);
                    uint32_t r[4];
                    ldsm4(r, Bp + brow * 40 + bkc);
                    b[2*ni2    ][0] = r[0]; b[2*ni2    ][1] = r[1];
                    b[2*ni2 + 1][0] = r[2]; b[2*ni2 + 1][1] = r[3];
                }
            }
#pragma unroll
            for (int mi = 0; mi < 4; mi++)
#pragma unroll
                for (int ni = 0; ni < 4; ni++)
                    mma16(acc[mi][ni], a[mi], b[ni]);
        }
    }
#undef ISSUE_NT

    const int orow = m0 + wm * 64 + (lane >> 2);
    const int ocol = n0 + wn * 32 + (lane & 3) * 2;
#pragma unroll
    for (int mi = 0; mi < 4; mi++) {
        long ra = (long)(orow + mi * 16) * N;
        long rb = (long)(orow + mi * 16 + 8) * N;
#pragma unroll
        for (int ni = 0; ni < 4; ni++) {
            int n = ocol + ni * 8;
            C[ra + n] = acc[mi][ni][0]; C[ra + n + 1] = acc[mi][ni][1];
            C[rb + n] = acc[mi][ni][2]; C[rb + n + 1] = acc[mi][ni][3];
        }
    }
}

// ============================================================================
// fp16 AV GEMM (half probs, NN via trans-ldmatrix B), cp.async double-buffered
// ============================================================================
__global__ void __launch_bounds__(256) hgemm_av_kernel(
    const __half* __restrict__ S, const __half* __restrict__ V, __half* __restrict__ out,
    int n, int d, int lp, int c0)
{
    __shared__ __half As[2 * 128 * 40];
    __shared__ __half Bs[2 * 32 * 136];
    const int tid = threadIdx.x;
    const int lane = tid & 31, wid = tid >> 5;
    const int wm = wid & 1, wn = wid >> 1;
    const int z = blockIdx.z;
    S += (long)z * n * n;
    V += (long)z * n * d;
    const int n0 = blockIdx.x * 128;
    const int m0 = blockIdx.y * 128;
    const int wr = tid >> 1, wkh = (tid & 1) * 16;
    const int bk = tid >> 3, bn0 = (tid & 7) * 16;
    const int nch = n / 32;

    const uint32_t sAs = (uint32_t)__cvta_generic_to_shared(As);
    const uint32_t sBs = (uint32_t)__cvta_generic_to_shared(Bs);

#define ISSUE_AV(K0v, NB)                                                       \
    {                                                                           \
        const __half* sa = S + (long)(m0 + wr) * n + (K0v) + wkh;               \
        uint32_t da = sAs + (uint32_t)(((NB) * 5120 + wr * 40 + wkh) * 2);      \
        cpa16(da, sa, 16u); cpa16(da + 16, sa + 8, 16u);                        \
        const __half* sb = V + (long)((K0v) + bk) * d + n0 + bn0;               \
        uint32_t db = sBs + (uint32_t)(((NB) * 4352 + bk * 136 + bn0) * 2);     \
        cpa16(db, sb, 16u); cpa16(db + 16, sb + 8, 16u);                        \
        cpcommit();                                                             \
    }

    float acc[4][4][4] = {};
    ISSUE_AV(0, 0);

    for (int i = 0; i < nch; i++) {
        cpwait<0>();
        __syncthreads();
        if (i + 1 < nch) ISSUE_AV((i + 1) * 32, (i + 1) & 1);

        const __half* Ap = As + (i & 1) * 5120;
        const __half* Bp = Bs + (i & 1) * 4352;
#pragma unroll
        for (int kstep = 0; kstep < 2; kstep++) {
            uint32_t a[4][4], b[4][2];
            {
                const int arow = wm * 64 + ((lane >> 3) & 1) * 8 + (lane & 7);
                const int akc  = kstep * 16 + (lane >> 4) * 8;
#pragma unroll
                for (int mi = 0; mi < 4; mi++)
                    ldsm4(a[mi], Ap + (arow + mi * 16) * 40 + akc);
            }
            {
                const int brow = kstep * 16 + (lane & 7) + ((lane >> 3) & 1) * 8;
#pragma unroll
                for (int ni2 = 0; ni2 < 2; ni2++) {
                    const int bcol = wn * 32 + ni2 * 16 + ((lane >> 4) & 1) * 8;
                    uint32_t r[4];
                    ldsm4t(r, Bp + brow * 136 + bcol);
                    b[2*ni2    ][0] = r[0]; b[2*ni2    ][1] = r[1];
                    b[2*ni2 + 1][0] = r[2]; b[2*ni2 + 1][1] = r[3];
                }
            }
#pragma unroll
            for (int mi = 0; mi < 4; mi++)
#pragma unroll
                for (int ni = 0; ni < 4; ni++)
                    mma16(acc[mi][ni], a[mi], b[ni]);
        }
    }
#undef ISSUE_AV

    const int lo = 6 - lp;
    const int orow = m0 + wm * 64 + (lane >> 2);
    const int ocol = n0 + wn * 32 + (lane & 3) * 2;
#pragma unroll
    for (int mi = 0; mi < 4; mi++) {
#pragma unroll
        for (int hf = 0; hf < 2; hf++) {
            const int m = orow + mi * 16 + hf * 8;
            const int t = m >> (2 * lo);
            const int r = m & ((1 << (2 * lo)) - 1);
            const int ohi = r >> lo, owi = r & ((1 << lo) - 1);
#pragma unroll
            for (int ni = 0; ni < 4; ni++) {
                const int col = ocol + ni * 8;
                const int cc = col >> (2 * lp);
                const int rr = col & ((1 << (2 * lp)) - 1);
                const int pi = rr >> lp, pj = rr & ((1 << lp) - 1);
                long dst = ((long)((z * 8 + t) * 256 + c0 + cc) << 12)
                         + (((ohi << lp) + pi) << 6) + (owi << lp) + pj;
                *(__half2*)(out + dst) = __floats2half2_rn(acc[mi][ni][hf*2], acc[mi][ni][hf*2 + 1]);
            }
        }
    }
}

// ============================================================================
// fp16 mma 32x32 NT split-K (P=32 scores): 2 warps, cross-warp smem reduce
// ============================================================================
__global__ void __launch_bounds__(64) hgemm32_kernel(
    const __half* __restrict__ A, const __half* __restrict__ B, float* __restrict__ C,
    int K, int splitk)
{
    __shared__ __half Qs[32 * 136];
    __shared__ __half Ks[32 * 136];
    __shared__ float buf[32][33];
    const int tid = threadIdx.x;
    const int lane = tid & 31, wrp = tid >> 5;
    const int z = blockIdx.z, bat = z / splitk, ks = z - bat * splitk;
    A += (long)bat * 32 * K;
    B += (long)bat * 32 * K;
    const int kchunk = K / splitk, kbeg = ks * kchunk;

    float acc[2][4][4] = {};
    for (int k0 = kbeg; k0 < kbeg + kchunk; k0 += 128) {
        __syncthreads();
#pragma unroll
        for (int i = 0; i < 8; i++) {
            int u = i * 64 + tid;
            int row = u >> 4, seg = (u & 15) * 8;
            *(uint4*)(Qs + row * 136 + seg) = *(const uint4*)(A + (long)row * K + k0 + seg);
            *(uint4*)(Ks + row * 136 + seg) = *(const uint4*)(B + (long)row * K + k0 + seg);
        }
        __syncthreads();
        for (int s = wrp; s < 8; s += 2) {
            const int kc = s * 16;
            uint32_t a[2][4], b[4][2];
            {
                const int arow = ((lane >> 3) & 1) * 8 + (lane & 7);
                const int akc  = kc + (lane >> 4) * 8;
                ldsm4(a[0], Qs + arow * 136 + akc);
                ldsm4(a[1], Qs + (arow + 16) * 136 + akc);
            }
            {
                const int bkc = kc + ((lane >> 3) & 1) * 8;
#pragma unroll
                for (int ni2 = 0; ni2 < 2; ni2++) {
                    const int brow = ni2 * 16 + ((lane >> 4) & 1) * 8 + (lane & 7);
                    uint32_t r[4];
                    ldsm4(r, Ks + brow * 136 + bkc);
                    b[2*ni2    ][0] = r[0]; b[2*ni2    ][1] = r[1];
                    b[2*ni2 + 1][0] = r[2]; b[2*ni2 + 1][1] = r[3];
                }
            }
#pragma unroll
            for (int mi = 0; mi < 2; mi++)
#pragma unroll
                for (int ni = 0; ni < 4; ni++)
                    mma16(acc[mi][ni], a[mi], b[ni]);
        }
    }

    const int rr = lane >> 2, cc = (lane & 3) * 2;
    if (wrp == 0) {
#pragma unroll
        for (int mi = 0; mi < 2; mi++)
#pragma unroll
            for (int ni = 0; ni < 4; ni++) {
                buf[mi*16 + rr    ][ni*8 + cc]     = acc[mi][ni][0];
                buf[mi*16 + rr    ][ni*8 + cc + 1] = acc[mi][ni][1];
                buf[mi*16 + rr + 8][ni*8 + cc]     = acc[mi][ni][2];
                buf[mi*16 + rr + 8][ni*8 + cc + 1] = acc[mi][ni][3];
            }
    }
    __syncthreads();
    if (wrp == 1) {
#pragma unroll
        for (int mi = 0; mi < 2; mi++)
#pragma unroll
            for (int ni = 0; ni < 4; ni++) {
                buf[mi*16 + rr    ][ni*8 + cc]     += acc[mi][ni][0];
                buf[mi*16 + rr    ][ni*8 + cc + 1] += acc[mi][ni][1];
                buf[mi*16 + rr + 8][ni*8 + cc]     += acc[mi][ni][2];
                buf[mi*16 + rr + 8][ni*8 + cc + 1] += acc[mi][ni][3];
            }
    }
    __syncthreads();
    float* Cz = C + (long)z * 1024;
    for (int i = tid; i < 1024; i += 64)
        Cz[i] = buf[i >> 5][i & 31];
}

// ============================================================================
// fused split-K reduce + softmax + fp16 emit (one block per row)
// ============================================================================
__global__ void rsm_kernel(const float* __restrict__ part, __half* __restrict__ Sh,
                           int n, int splitk, float scale)
{
    __shared__ float buf[2048];
    __shared__ float red[256];
    const int row = blockIdx.x;
    const int b = row / n, r = row - b * n;
    const long base = ((long)b * splitk) * n * n + (long)r * n;
    const int tid = threadIdx.x;
    float m = -1e30f;
    for (int i = tid; i < n; i += 256) {
        float s = 0.f;
        for (int ks = 0; ks < splitk; ks++)
            s += part[base + (long)ks * n * n + i];
        s *= scale;
        buf[i] = s;
        m = fmaxf(m, s);
    }
    red[tid] = m; __syncthreads();
    for (int s = 128; s > 0; s >>= 1) { if (tid < s) red[tid] = fmaxf(red[tid], red[tid + s]); __syncthreads(); }
    m = red[0]; __syncthreads();
    float sum = 0.f;
    for (int i = tid; i < n; i += 256) { float e = expf(buf[i] - m); buf[i] = e; sum += e; }
    red[tid] = sum; __syncthreads();
    for (int s = 128; s > 0; s >>= 1) { if (tid < s) red[tid] += red[tid + s]; __syncthreads(); }
    float inv = 1.f / red[0];
    __half* ph = Sh + (long)row * n;
    for (int i = tid; i < n; i += 256) ph[i] = __float2half(buf[i] * inv);
}

// ===================== SIMT AV for P=32 (probs half, half V, half out) ============
__global__ void __launch_bounds__(256) gemm_av32_kernel(
    const __half* __restrict__ A, const __half* __restrict__ B, __half* __restrict__ out,
    int n, int d, int lp, int c0)
{
    const int z = blockIdx.z;
    A += (long)z * n * n;
    B += (long)z * n * d;
    const int m0 = blockIdx.y * 64, n0 = blockIdx.x * 64;
    __shared__ __align__(16) float As[16][68];
    __shared__ __align__(16) float Bs[16][64];
    const int tid = threadIdx.x;
    const int tx = tid & 15, ty = tid >> 4;
    float acc[4][4] = {};
    for (int k0 = 0; k0 < n; k0 += 16) {
#pragma unroll
        for (int it = 0; it < 4; it++) {
            int id = tid + it * 256;
            int m = id >> 4, kk = id & 15;
            As[kk][m] = (m0 + m < n) ? __half2float(A[(long)(m0 + m) * n + k0 + kk]) : 0.f;
        }
#pragma unroll
        for (int it = 0; it < 4; it++) {
            int id = tid + it * 256;
            int kk = id >> 6, nnn = id & 63;
            Bs[kk][nnn] = __half2float(B[(long)(k0 + kk) * d + n0 + nnn]);
        }
        __syncthreads();
#pragma unroll
        for (int kk = 0; kk < 16; kk++) {
            float4 a4 = *(const float4*)&As[kk][ty * 4];
            float4 b4 = *(const float4*)&Bs[kk][tx * 4];
            float ar[4] = {a4.x, a4.y, a4.z, a4.w};
            float br[4] = {b4.x, b4.y, b4.z, b4.w};
#pragma unroll
            for (int i = 0; i < 4; i++)
#pragma unroll
                for (int j = 0; j < 4; j++)
                    acc[i][j] += ar[i] * br[j];
        }
        __syncthreads();
    }
    const int lo = 6 - lp, o = 1 << lo, P = 1 << lp;
#pragma unroll
    for (int i = 0; i < 4; i++) {
        int m = m0 + ty * 4 + i;
        if (m >= n) continue;
        int t = m >> (2 * lo);
        int r = m & ((1 << (2 * lo)) - 1);
        int ohi = r >> lo, owi = r & (o - 1);
        int col = n0 + tx * 4;
        int cc = col >> (2 * lp);
        int rr = col & (P * P - 1);
        int pi = rr >> lp, pj = rr & (P - 1);
        long dst = ((long)((z * 8 + t) * 256 + c0 + cc) << 12)
                 + (((ohi << lp) + pi) << 6) + (owi << lp) + pj;
        *(__half2*)(out + dst)     = __floats2half2_rn(acc[i][0], acc[i][1]);
        *(__half2*)(out + dst + 2) = __floats2half2_rn(acc[i][2], acc[i][3]);
    }
}

// ===================== softmax (f32 in, HALF out; used by P=4 only) ===============
__global__ void softmax_kernel(const float* __restrict__ S, __half* __restrict__ Sh,
                               int n, float scale)
{
    __shared__ float buf[2048];
    __shared__ float red[256];
    const long row = blockIdx.x;
    const float* p = S + row * (long)n;
    __half* ph = Sh + row * (long)n;
    const int tid = threadIdx.x;
    float m = -1e30f;
    for (int i = tid; i < n; i += 256) { float v = p[i] * scale; buf[i] = v; m = fmaxf(m, v); }
    red[tid] = m; __syncthreads();
    for (int s = 128; s > 0; s >>= 1) { if (tid < s) red[tid] = fmaxf(red[tid], red[tid + s]); __syncthreads(); }
    m = red[0]; __syncthreads();
    float sum = 0.f;
    for (int i = tid; i < n; i += 256) { float e = expf(buf[i] - m); buf[i] = e; sum += e; }
    red[tid] = sum; __syncthreads();
    for (int s = 128; s > 0; s >>= 1) { if (tid < s) red[tid] += red[tid + s]; __syncthreads(); }
    float inv = 1.f / red[0];
    for (int i = tid; i < n; i += 256) ph[i] = __float2half(buf[i] * inv);
}

// ===================== launcher ===================================================
extern "C" void kernel_launch(void* const* d_in, const int* in_sizes, int n_in,
                              void* d_out, int out_size)
{
    const float* xs  = (const float*)d_in[0];
    const float* Wq  = (const float*)d_in[2];
    const float* bq  = (const float*)d_in[3];
    const float* Wk  = (const float*)d_in[4];
    const float* bk  = (const float*)d_in[5];
    const float* Wv  = (const float*)d_in[6];
    const float* bv  = (const float*)d_in[7];
    const float* Wl  = (const float*)d_in[8];
    const float* bl  = (const float*)d_in[9];
    const float* Wf1 = (const float*)d_in[10];
    const float* bf1 = (const float*)d_in[11];
    const float* Wf2 = (const float*)d_in[12];
    const float* bf2 = (const float*)d_in[13];
    float* out = (float*)d_out;

    __half *gQp, *gKp, *gVp, *gXsh, *gAtth, *gXs1h, *gFfh, *gSh;
    __half *gWqkvh, *gWlh, *gWf1h, *gWf2h;
    float *gS, *gPart;
    cudaGetSymbolAddress((void**)&gQp,    g_Qp);
    cudaGetSymbolAddress((void**)&gKp,    g_Kp);
    cudaGetSymbolAddress((void**)&gVp,    g_Vp);
    cudaGetSymbolAddress((void**)&gS,     g_S);
    cudaGetSymbolAddress((void**)&gSh,    g_Sh);
    cudaGetSymbolAddress((void**)&gPart,  g_part);
    cudaGetSymbolAddress((void**)&gXsh,   g_xsh);
    cudaGetSymbolAddress((void**)&gAtth,  g_atth);
    cudaGetSymbolAddress((void**)&gXs1h,  g_xs1h);
    cudaGetSymbolAddress((void**)&gFfh,   g_ffh);
    cudaGetSymbolAddress((void**)&gWqkvh, g_Wqkvh);
    cudaGetSymbolAddress((void**)&gWlh,   g_Wlh);
    cudaGetSymbolAddress((void**)&gWf1h,  g_Wf1h);
    cudaGetSymbolAddress((void**)&gWf2h,  g_Wf2h);

    cudaFuncSetAttribute(hconvK_kernel,
                         cudaFuncAttributeMaxDynamicSharedMemorySize, HK_SMEM);

    dim3 blk(256);
    dim3 qgrid(NIMG * 32, 2);

    // pre-convert inputs + weights (batched launches)
    f2h_kernel<<<16384, blk>>>(xs, gXsh);
    f2h3_kernel<<<192, blk>>>(Wq, Wk, Wv, gWqkvh);
    wtrans3_kernel<<<3 * 2304, blk>>>(Wl, Wf1, Wf2, gWlh, gWf1h, gWf2h);

    // fused QKV projection -> patchified half buffers (bias fused)
    hconv2_kernel<<<dim3(NIMG * 32, 6), blk>>>(gXsh, gWqkvh, bq, bk, bv, gQp, gKp, gVp);

    // ---- P=32 (n=32, d=65536) ----
    {
        const int n = 32, d = 65536, splitk = 256;
        hgemm32_kernel<<<dim3(1, 1, 2 * splitk), 64>>>(gQp, gKp, gPart, d, splitk);
        rsm_kernel<<<2 * n, blk>>>(gPart, gSh, n, splitk, 1.0f / 256.0f);
        gemm_av32_kernel<<<dim3(d / 64, 1, 2), blk>>>(gSh, gVp, gAtth, n, d, 5, 0);
    }
    // ---- P=16 (n=128, d=16384) ----
    {
        const int n = 128, d = 16384, splitk = 64;
        const long soff = 4194304;
        hgemm_nt_kernel<<<dim3(1, 1, 2 * splitk), blk>>>(
            gQp + soff, gKp + soff, gPart, n, d, splitk, (long)n * d, (long)n * n);
        rsm_kernel<<<2 * n, blk>>>(gPart, gSh, n, splitk, 1.0f / 128.0f);
        hgemm_av_kernel<<<dim3(d / 128, n / 128, 2), blk>>>(gSh, gVp + soff, gAtth, n, d, 4, 64);
    }
    // ---- P=8 (n=512, d=4096) ----
    {
        const int n = 512, d = 4096, splitk = 8;
        const long soff = 2L * 4194304;
        hgemm_nt_kernel<<<dim3(n / 128, n / 128, 2 * splitk), blk>>>(
            gQp + soff, gKp + soff, gPart, n, d, splitk, (long)n * d, (long)n * n);
        rsm_kernel<<<2 * n, blk>>>(gPart, gSh, n, splitk, 1.0f / 64.0f);
        hgemm_av_kernel<<<dim3(d / 128, n / 128, 2), blk>>>(gSh, gVp + soff, gAtth, n, d, 3, 128);
    }
    // ---- P=4 (n=2048, d=1024) ----
    {
        const int n = 2048, d = 1024;
        const long soff = 3L * 4194304;
        hgemm_nt_kernel<<<dim3(n / 128, n / 128, 2), blk>>>(
            gQp + soff, gKp + soff, gS, n, d, 1, (long)n * d, (long)n * n);
        softmax_kernel<<<2 * n, blk>>>(gS, gSh, n, 1.0f / 32.0f);
        hgemm_av_kernel<<<dim3(d / 128, n / 128, 2), blk>>>(gSh, gVp + soff, gAtth, n, d, 2, 192);
    }

    // convs: tap-row-major K, strip shared across 3 chunks; half residual chain
    hconvK_kernel<<<qgrid, blk, HK_SMEM>>>(gAtth, gWlh,  bl,  xs,      nullptr, nullptr, gXs1h, 1, 1);
    hconvK_kernel<<<qgrid, blk, HK_SMEM>>>(gXs1h, gWf1h, bf1, nullptr, nullptr, nullptr, gFfh,  1, 0);
    hconvK_kernel<<<qgrid, blk, HK_SMEM>>>(gFfh,  gWf2h, bf2, nullptr, gXs1h,   out,     nullptr, 2, 1);
}

// round 15
// speedup vs baseline: 1.1978x; 1.0019x over previous
#include <cuda_runtime.h>
#include <cuda_fp16.h>
#include <math.h>
#include <stdint.h>

#define NIMG 16
#define CCH 256
#define NPIX 4096            // 64*64

// ---- scratch (static device globals; no allocation) ----
__device__ __half g_Qp[16777216];
__device__ __half g_Kp[16777216];
__device__ __half g_Vp[16777216];
__device__ __half g_Sh[2*2048*2048];
__device__ float  g_part[8388608];
__device__ __half g_xsh [NIMG*CCH*NPIX];
__device__ __half g_atth[NIMG*CCH*NPIX];
__device__ __half g_xs1h[NIMG*CCH*NPIX];
__device__ __half g_ffh [NIMG*CCH*NPIX];
__device__ __half g_Wqkvh[196608];                                  // stacked [768][256]
__device__ __half g_Wlh[589824], g_Wf1h[589824], g_Wf2h[589824];   // tap-row-major

// ============================================================================
// helpers
// ============================================================================
__device__ __forceinline__ void mma16(float* d, const uint32_t* a, const uint32_t* b) {
    asm volatile(
        "mma.sync.aligned.m16n8k16.row.col.f32.f16.f16.f32 "
        "{%0,%1,%2,%3}, {%4,%5,%6,%7}, {%8,%9}, {%0,%1,%2,%3};"
        : "+f"(d[0]), "+f"(d[1]), "+f"(d[2]), "+f"(d[3])
        : "r"(a[0]), "r"(a[1]), "r"(a[2]), "r"(a[3]), "r"(b[0]), "r"(b[1]));
}

__device__ __forceinline__ void ldsm4(uint32_t* r, const void* p) {
    uint32_t addr = (uint32_t)__cvta_generic_to_shared(p);
    asm volatile("ldmatrix.sync.aligned.m8n8.x4.shared.b16 {%0,%1,%2,%3}, [%4];"
        : "=r"(r[0]), "=r"(r[1]), "=r"(r[2]), "=r"(r[3]) : "r"(addr));
}

__device__ __forceinline__ void ldsm4t(uint32_t* r, const void* p) {
    uint32_t addr = (uint32_t)__cvta_generic_to_shared(p);
    asm volatile("ldmatrix.sync.aligned.m8n8.x4.trans.shared.b16 {%0,%1,%2,%3}, [%4];"
        : "=r"(r[0]), "=r"(r[1]), "=r"(r[2]), "=r"(r[3]) : "r"(addr));
}

__device__ __forceinline__ uint32_t pack_h2(float a, float b) {
    __half2 h = __floats2half2_rn(a, b);
    return *(uint32_t*)&h;
}

__device__ __forceinline__ void cpa16(uint32_t dst, const void* src, unsigned sz) {
    asm volatile("cp.async.ca.shared.global [%0], [%1], 16, %2;"
                 :: "r"(dst), "l"(src), "r"(sz) : "memory");
}
__device__ __forceinline__ void cpcommit() {
    asm volatile("cp.async.commit_group;" ::: "memory");
}
template <int N>
__device__ __forceinline__ void cpwait() {
    asm volatile("cp.async.wait_group %0;" :: "n"(N) : "memory");
}

// f32 -> f16 bulk convert (exact multiples of 1024 elems)
__global__ void f2h_kernel(const float* __restrict__ src, __half* __restrict__ dst) {
    long i = ((long)blockIdx.x * 256 + threadIdx.x) * 4;
    float4 v = *(const float4*)(src + i);
    *(uint32_t*)(dst + i)     = pack_h2(v.x, v.y);
    *(uint32_t*)(dst + i + 2) = pack_h2(v.z, v.w);
}

// batched f2h: QKV weights into one stacked [768][256] half buffer
__global__ void f2h3_kernel(const float* __restrict__ s0, const float* __restrict__ s1,
                            const float* __restrict__ s2, __half* __restrict__ d) {
    int z = blockIdx.x >> 6;
    const float* s = (z == 0) ? s0 : ((z == 1) ? s1 : s2);
    long i = ((long)(blockIdx.x & 63) * 256 + threadIdx.x) * 4;
    __half* dz = d + (long)z * 65536;
    float4 v = *(const float4*)(s + i);
    *(uint32_t*)(dz + i)     = pack_h2(v.x, v.y);
    *(uint32_t*)(dz + i + 2) = pack_h2(v.z, v.w);
}

// batched conv weight permute to tap-row-major:
//   kNew = ((dy*4 + cg)*3 + tx)*64 + ci  <-  W[oc][cg*64+ci][dy*3+tx]
__global__ void wtrans3_kernel(const float* __restrict__ W0, const float* __restrict__ W1,
                               const float* __restrict__ W2,
                               __half* __restrict__ D0, __half* __restrict__ D1,
                               __half* __restrict__ D2) {
    int z = blockIdx.x / 2304;
    const float* W = (z == 0) ? W0 : ((z == 1) ? W1 : W2);
    __half* Wt2 = (z == 0) ? D0 : ((z == 1) ? D1 : D2);
    int idx = (blockIdx.x - z * 2304) * 256 + threadIdx.x;
    int oc = idx / 2304, r = idx - oc * 2304;
    int dy = r / 768;   int r2 = r - dy * 768;
    int cg = r2 / 192;  int r3 = r2 - cg * 192;
    int tx = r3 / 64;   int ci = r3 - tx * 64;
    Wt2[idx] = __float2half(W[oc * 2304 + (cg * 64 + ci) * 9 + dy * 3 + tx]);
}

// scatter index into patchified buffer: scale = oc>>6 (oc in [0,256))
__device__ __forceinline__ long pat_index(int img, int oc, int pix) {
    int s  = oc >> 6, cc = oc & 63;
    int lp = 5 - s;
    int lo = 1 + s;
    int Pm = (1 << lp) - 1;
    int y = pix >> 6, x = pix & 63;
    int ohi = y >> lp, pi = y & Pm, owi = x >> lp, pj = x & Pm;
    int t = img & 7, b = img >> 3;
    int nn = (t << (2*lo)) + (ohi << lo) + owi;
    int dd = (cc << (2*lp)) + (pi << lp) + pj;
    return (long)s * 4194304 + (long)b * 2097152 + (long)nn * (64 << (2*lp)) + dd;
}

// ============================================================================
// hconv2qkv: fused Q/K/V projection (stacked weights [768][256]), grid.y = 6
// ============================================================================
__global__ void __launch_bounds__(256, 2) hconv2_kernel(
    const __half* __restrict__ in, const __half* __restrict__ Wt,
    const float* __restrict__ bq, const float* __restrict__ bk, const float* __restrict__ bv,
    __half* __restrict__ Qp, __half* __restrict__ Kp, __half* __restrict__ Vp)
{
    __shared__ __half A2[2 * 128 * 40];
    __shared__ __half B2[2 * 32 * 136];

    const int tid = threadIdx.x;
    const int lane = tid & 31, wid = tid >> 5;
    const int wm = wid & 1, wn = wid >> 1;
    const int img = blockIdx.x >> 5;
    const int p0 = (blockIdx.x & 31) * 128;
    const int m0 = blockIdx.y * 128;          // 0..640 over stacked 768 rows
    const int proj = m0 >> 8;
    const __half* inimg = in + (long)img * CCH * NPIX;
    const float* bias = (proj == 0) ? bq : ((proj == 1) ? bk : bv);
    __half* outh_pat = (proj == 0) ? Qp : ((proj == 1) ? Kp : Vp);

    const uint32_t sA2 = (uint32_t)__cvta_generic_to_shared(A2);
    const uint32_t sB2 = (uint32_t)__cvta_generic_to_shared(B2);

#define ISSUE1(KCN, NB)                                                         \
    {                                                                           \
        const int k0n = (KCN) * 32;                                             \
        {                                                                       \
            int row = tid >> 1, seg = (tid & 1) * 16;                           \
            const __half* src = Wt + (long)(m0 + row) * 256 + k0n + seg;        \
            uint32_t dst = sA2 + (uint32_t)(((NB) * 5120 + row * 40 + seg) * 2);\
            cpa16(dst, src, 16u); cpa16(dst + 16, src + 8, 16u);                \
        }                                                                       \
        {                                                                       \
            int k = tid >> 3, u = tid & 7;                                      \
            const __half* src = inimg + ((long)(k0n + k) << 12) + p0 + u * 8;   \
            uint32_t dst = sB2 + (uint32_t)(((NB) * 4352 + k * 136 + u * 8) * 2); \
            cpa16(dst, src, 16u);                                               \
            cpa16(dst + 128, src + 64, 16u);                                    \
        }                                                                       \
        cpcommit();                                                             \
    }

    float acc[4][4][4] = {};
    ISSUE1(0, 0);

    for (int kc = 0; kc < 8; kc++) {
        cpwait<0>();
        __syncthreads();
        if (kc + 1 < 8) ISSUE1(kc + 1, (kc + 1) & 1);

        const __half* Ap = A2 + (kc & 1) * 5120;
        const __half* Bp = B2 + (kc & 1) * 4352;
#pragma unroll
        for (int kstep = 0; kstep < 2; kstep++) {
            uint32_t a[4][4], b[4][2];
            {
                const int arow = wm * 64 + ((lane >> 3) & 1) * 8 + (lane & 7);
                const int akc  = kstep * 16 + (lane >> 4) * 8;
#pragma unroll
                for (int mi = 0; mi < 4; mi++)
                    ldsm4(a[mi], Ap + (arow + mi * 16) * 40 + akc);
            }
            {
                const int brow = kstep * 16 + (lane & 7) + ((lane >> 3) & 1) * 8;
#pragma unroll
                for (int ni2 = 0; ni2 < 2; ni2++) {
                    const int bcol = wn * 32 + ni2 * 16 + ((lane >> 4) & 1) * 8;
                    uint32_t r[4];
                    ldsm4t(r, Bp + brow * 136 + bcol);
                    b[2*ni2    ][0] = r[0]; b[2*ni2    ][1] = r[1];
                    b[2*ni2 + 1][0] = r[2]; b[2*ni2 + 1][1] = r[3];
                }
            }
#pragma unroll
            for (int mi = 0; mi < 4; mi++)
#pragma unroll
                for (int ni = 0; ni < 4; ni++)
                    mma16(acc[mi][ni], a[mi], b[ni]);
        }
    }
#undef ISSUE1

    const int orow = (m0 & 255) + wm * 64 + (lane >> 2);
    const int ocol = p0 + wn * 32 + (lane & 3) * 2;
#pragma unroll
    for (int mi = 0; mi < 4; mi++) {
        const int oca = orow + mi * 16, ocb = oca + 8;
        const float ba = bias[oca], bb = bias[ocb];
#pragma unroll
        for (int ni = 0; ni < 4; ni++) {
            const int n = ocol + ni * 8;
            long ia = pat_index(img, oca, n);
            long ib = pat_index(img, ocb, n);
            *(__half2*)(outh_pat + ia) = __floats2half2_rn(acc[mi][ni][0] + ba, acc[mi][ni][1] + ba);
            *(__half2*)(outh_pat + ib) = __floats2half2_rn(acc[mi][ni][2] + bb, acc[mi][ni][3] + bb);
        }
    }
}

// ============================================================================
// hconvK: 3x3 conv, tap-ROW-major K (strip shared by 3 chunks), 256 threads
// ============================================================================
#define HK_A2    0
#define HK_BS    18432
#define HK_STRIP (18432 + 8704)
#define HK_SMEM  ((18432 + 8704 + 10240) * 2)

__global__ void __launch_bounds__(256, 2) hconvK_kernel(
    const __half* __restrict__ in, const __half* __restrict__ Wt,
    const float* __restrict__ bias, const float* __restrict__ res,
    const __half* __restrict__ resh,
    float* __restrict__ out, __half* __restrict__ outh_img,
    int dil, int addres)
{
    extern __shared__ __half sh[];
    __half* A2    = sh + HK_A2;
    __half* Bs    = sh + HK_BS;
    __half* Strip = sh + HK_STRIP;

    const int tid = threadIdx.x;
    const int lane = tid & 31, wid = tid >> 5;
    const int wm = wid & 1, wn = wid >> 1;
    const int img = blockIdx.x >> 5;
    const int p0 = (blockIdx.x & 31) * 128;
    const int y0 = p0 >> 6;
    const int m0 = blockIdx.y * 128;
    const __half* inimg = in + (long)img * CCH * NPIX;

    const uint32_t sA2    = (uint32_t)__cvta_generic_to_shared(A2);
    const uint32_t sStrip = (uint32_t)__cvta_generic_to_shared(Strip);

    {
        int c = tid >> 2, u = tid & 3, r = u >> 1, side = u & 1;
        *(uint4*)(Strip + c * 160 + r * 80 + side * 72) = make_uint4(0, 0, 0, 0);
    }

#define ISSUE_A(KCN, NB)                                                         \
    {                                                                            \
        int row = tid >> 1, seg = (tid & 1) * 32;                                \
        const __half* src = Wt + (long)(m0 + row) * 2304 + (KCN) * 64 + seg;     \
        uint32_t dst = sA2 + (uint32_t)(((NB) * 9216 + row * 72 + seg) * 2);     \
        cpa16(dst,      src,      16u);                                          \
        cpa16(dst + 16, src + 8,  16u);                                          \
        cpa16(dst + 32, src + 16, 16u);                                          \
        cpa16(dst + 48, src + 24, 16u);                                          \
    }

#define ISSUE_S(KCN)                                                             \
    {                                                                            \
        int dyg = (KCN) / 12;                                                    \
        int c0v = (((KCN) % 12) / 3) * 64;                                       \
        int dyd = (dyg - 1) * dil;                                               \
        int c = tid >> 2, u = tid & 3;                                           \
        int r = u >> 1, s = u & 1;                                               \
        int gy = y0 + r + dyd;                                                   \
        unsigned ok = ((unsigned)gy < 64u) ? 16u : 0u;                           \
        int gyc = gy < 0 ? 0 : (gy > 63 ? 63 : gy);                              \
        const __half* src = inimg + ((long)(c0v + c) << 12) + (gyc << 6) + s * 32; \
        uint32_t dst = sStrip + (uint32_t)((c * 160 + r * 80 + 8 + s * 32) * 2); \
        cpa16(dst,      src,      ok);                                           \
        cpa16(dst + 16, src + 8,  ok);                                           \
        cpa16(dst + 32, src + 16, ok);                                           \
        cpa16(dst + 48, src + 24, ok);                                           \
    }

    float acc[4][4][4] = {};
    ISSUE_A(0, 0);
    ISSUE_S(0);
    cpcommit();

    for (int kc = 0; kc < 36; kc++) {
        cpwait<0>();
        __syncthreads();

        {
            const int dxd = (kc % 3 - 1) * dil;
            const int c = tid >> 2, u = tid & 3, prow = u >> 1, xseg = (u & 1) * 32;
            const uint32_t* rowp = (const uint32_t*)(Strip + c * 160 + prow * 80);
            const int h0 = 8 + dxd + xseg;
            uint32_t w[16];
            if (dxd & 1) {
                int k0 = (h0 - 1) >> 1;
                uint32_t prev = rowp[k0];
#pragma unroll
                for (int j = 0; j < 16; j++) {
                    uint32_t nxt = rowp[k0 + 1 + j];
                    w[j] = __funnelshift_r(prev, nxt, 16);
                    prev = nxt;
                }
            } else {
                int k0 = h0 >> 1;
#pragma unroll
                for (int j = 0; j < 16; j++) w[j] = rowp[k0 + j];
            }
            uint4* bd = (uint4*)(Bs + c * 136 + prow * 64 + xseg);
#pragma unroll
            for (int j = 0; j < 4; j++)
                bd[j] = make_uint4(w[4*j], w[4*j+1], w[4*j+2], w[4*j+3]);
        }
        __syncthreads();

        if (kc + 1 < 36) {
            ISSUE_A(kc + 1, (kc + 1) & 1);
            if ((kc + 1) % 3 == 0) ISSUE_S(kc + 1);
            cpcommit();
        }

        const __half* Ap = A2 + (kc & 1) * 9216;
#pragma unroll
        for (int kstep = 0; kstep < 4; kstep++) {
            uint32_t a[4][4], b[4][2];
            {
                const int arow = wm * 64 + ((lane >> 3) & 1) * 8 + (lane & 7);
                const int akc  = kstep * 16 + (lane >> 4) * 8;
#pragma unroll
                for (int mi = 0; mi < 4; mi++)
                    ldsm4(a[mi], Ap + (arow + mi * 16) * 72 + akc);
            }
            {
                const int brow = kstep * 16 + (lane & 7) + ((lane >> 3) & 1) * 8;
#pragma unroll
                for (int ni2 = 0; ni2 < 2; ni2++) {
                    const int bcol = wn * 32 + ni2 * 16 + ((lane >> 4) & 1) * 8;
                    uint32_t r[4];
                    ldsm4t(r, Bs + brow * 136 + bcol);
                    b[2*ni2    ][0] = r[0]; b[2*ni2    ][1] = r[1];
                    b[2*ni2 + 1][0] = r[2]; b[2*ni2 + 1][1] = r[3];
                }
            }
#pragma unroll
            for (int mi = 0; mi < 4; mi++)
#pragma unroll
                for (int ni = 0; ni < 4; ni++)
                    mma16(acc[mi][ni], a[mi], b[ni]);
        }
    }
#undef ISSUE_A
#undef ISSUE_S

    const int orow = m0 + wm * 64 + (lane >> 2);
    const int ocol = p0 + wn * 32 + (lane & 3) * 2;
#pragma unroll
    for (int mi = 0; mi < 4; mi++) {
        const int oca = orow + mi * 16;
        const int ocb = oca + 8;
        const float ba = bias[oca], bb = bias[ocb];
#pragma unroll
        for (int ni = 0; ni < 4; ni++) {
            const int n = ocol + ni * 8;
            long ia = ((long)img * 256 + oca) * NPIX + n;
            long ib = ((long)img * 256 + ocb) * NPIX + n;
            float v0 = acc[mi][ni][0] + ba, v1 = acc[mi][ni][1] + ba;
            float v2 = acc[mi][ni][2] + bb, v3 = acc[mi][ni][3] + bb;
            v0 = (v0 > 0.f) ? v0 : 0.2f * v0;
            v1 = (v1 > 0.f) ? v1 : 0.2f * v1;
            v2 = (v2 > 0.f) ? v2 : 0.2f * v2;
            v3 = (v3 > 0.f) ? v3 : 0.2f * v3;
            if (addres) {
                if (resh) {
                    __half2 ra = *(const __half2*)(resh + ia);
                    __half2 rb = *(const __half2*)(resh + ib);
                    float2 fa = __half22float2(ra), fb = __half22float2(rb);
                    v0 += fa.x; v1 += fa.y; v2 += fb.x; v3 += fb.y;
                } else {
                    v0 += res[ia]; v1 += res[ia + 1];
                    v2 += res[ib]; v3 += res[ib + 1];
                }
            }
            if (out) {
                out[ia] = v0; out[ia + 1] = v1;
                out[ib] = v2; out[ib + 1] = v3;
            }
            if (outh_img) {
                *(__half2*)(outh_img + ia) = __floats2half2_rn(v0, v1);
                *(__half2*)(outh_img + ib) = __floats2half2_rn(v2, v3);
            }
        }
    }
}

// ============================================================================
// fp16 NT GEMM with split-K (scores), cp.async double-buffered
//   Ch != null (splitk==1 path): emit half scores scaled by emitScale
// ============================================================================
__global__ void __launch_bounds__(256) hgemm_nt_kernel(
    const __half* __restrict__ A, const __half* __restrict__ B, float* __restrict__ C,
    __half* __restrict__ Ch, float emitScale,
    int N, int K, int splitk, long sAB, long sC)
{
    __shared__ __half As[2 * 128 * 40];
    __shared__ __half Bs[2 * 128 * 40];
    const int tid = threadIdx.x;
    const int lane = tid & 31, wid = tid >> 5;
    const int wm = wid & 1, wn = wid >> 1;
    const int n0 = blockIdx.x * 128, m0 = blockIdx.y * 128;
    const int z = blockIdx.z, bat = z / splitk, ks = z - bat * splitk;
    A += (long)bat * sAB;
    B += (long)bat * sAB;
    const int kchunk = K / splitk, kbeg = ks * kchunk;
    const int nch = kchunk / 32;
    const int wr = tid >> 1, wkh = (tid & 1) * 16;

    const uint32_t sAs = (uint32_t)__cvta_generic_to_shared(As);
    const uint32_t sBs = (uint32_t)__cvta_generic_to_shared(Bs);

#define ISSUE_NT(K0v, NB)                                                       \
    {                                                                           \
        const __half* sa = A + (long)(m0 + wr) * K + (K0v) + wkh;               \
        const __half* sb = B + (long)(n0 + wr) * K + (K0v) + wkh;               \
        uint32_t da = sAs + (uint32_t)(((NB) * 5120 + wr * 40 + wkh) * 2);      \
        uint32_t db = sBs + (uint32_t)(((NB) * 5120 + wr * 40 + wkh) * 2);      \
        cpa16(da, sa, 16u); cpa16(da + 16, sa + 8, 16u);                        \
        cpa16(db, sb, 16u); cpa16(db + 16, sb + 8, 16u);                        \
        cpcommit();                                                             \
    }

    float acc[4][4][4] = {};
    ISSUE_NT(kbeg, 0);

    for (int i = 0; i < nch; i++) {
        cpwait<0>();
        __syncthreads();
        if (i + 1 < nch) ISSUE_NT(kbeg + (i + 1) * 32, (i + 1) & 1);

        const __half* Ap = As + (i & 1) * 5120;
        const __half* Bp = Bs + (i & 1) * 5120;
#pragma unroll
        for (int kstep = 0; kstep < 2; kstep++) {
            uint32_t a[4][4], b[4][2];
            {
                const int arow = wm * 64 + ((lane >> 3) & 1) * 8 + (lane & 7);
                const int akc  = kstep * 16 + (lane >> 4) * 8;
#pragma unroll
                for (int mi = 0; mi < 4; mi++)
                    ldsm4(a[mi], Ap + (arow + mi * 16) * 40 + akc);
            }
            {
                const int bkc = kstep * 16 + ((lane >> 3) & 1) * 8;
#pragma unroll
                for (int ni2 = 0; ni2 < 2; ni2++) {
                    const int brow = wn * 32 + ni2 * 16 + ((lane >> 4) & 1) * 8 + (lane & 7);
                    uint32_t r[4];
                    ldsm4(r, Bp + brow * 40 + bkc);
                    b[2*ni2    ][0] = r[0]; b[2*ni2    ][1] = r[1];
                    b[2*ni2 + 1][0] = r[2]; b[2*ni2 + 1][1] = r[3];
                }
            }
#pragma unroll
            for (int mi = 0; mi < 4; mi++)
#pragma unroll
                for (int ni = 0; ni < 4; ni++)
                    mma16(acc[mi][ni], a[mi], b[ni]);
        }
    }
#undef ISSUE_NT

    const int orow = m0 + wm * 64 + (lane >> 2);
    const int ocol = n0 + wn * 32 + (lane & 3) * 2;
    if (Ch) {
        Ch += (long)z * sC;
#pragma unroll
        for (int mi = 0; mi < 4; mi++) {
            long ra = (long)(orow + mi * 16) * N;
            long rb = (long)(orow + mi * 16 + 8) * N;
#pragma unroll
            for (int ni = 0; ni < 4; ni++) {
                int n = ocol + ni * 8;
                *(__half2*)(Ch + ra + n) = __floats2half2_rn(acc[mi][ni][0] * emitScale,
                                                             acc[mi][ni][1] * emitScale);
                *(__half2*)(Ch + rb + n) = __floats2half2_rn(acc[mi][ni][2] * emitScale,
                                                             acc[mi][ni][3] * emitScale);
            }
        }
    } else {
        C += (long)z * sC;
#pragma unroll
        for (int mi = 0; mi < 4; mi++) {
            long ra = (long)(orow + mi * 16) * N;
            long rb = (long)(orow + mi * 16 + 8) * N;
#pragma unroll
            for (int ni = 0; ni < 4; ni++) {
                int n = ocol + ni * 8;
                C[ra + n] = acc[mi][ni][0]; C[ra + n + 1] = acc[mi][ni][1];
                C[rb + n] = acc[mi][ni][2]; C[rb + n + 1] = acc[mi][ni][3];
            }
        }
    }
}

// ============================================================================
// fp16 AV GEMM (half probs, NN via trans-ldmatrix B), cp.async double-buffered
// ============================================================================
__global__ void __launch_bounds__(256) hgemm_av_kernel(
    const __half* __restrict__ S, const __half* __restrict__ V, __half* __restrict__ out,
    int n, int d, int lp, int c0)
{
    __shared__ __half As[2 * 128 * 40];
    __shared__ __half Bs[2 * 32 * 136];
    const int tid = threadIdx.x;
    const int lane = tid & 31, wid = tid >> 5;
    const int wm = wid & 1, wn = wid >> 1;
    const int z = blockIdx.z;
    S += (long)z * n * n;
    V += (long)z * n * d;
    const int n0 = blockIdx.x * 128;
    const int m0 = blockIdx.y * 128;
    const int wr = tid >> 1, wkh = (tid & 1) * 16;
    const int bk = tid >> 3, bn0 = (tid & 7) * 16;
    const int nch = n / 32;

    const uint32_t sAs = (uint32_t)__cvta_generic_to_shared(As);
    const uint32_t sBs = (uint32_t)__cvta_generic_to_shared(Bs);

#define ISSUE_AV(K0v, NB)                                                       \
    {                                                                           \
        const __half* sa = S + (long)(m0 + wr) * n + (K0v) + wkh;               \
        uint32_t da = sAs + (uint32_t)(((NB) * 5120 + wr * 40 + wkh) * 2);      \
        cpa16(da, sa, 16u); cpa16(da + 16, sa + 8, 16u);                        \
        const __half* sb = V + (long)((K0v) + bk) * d + n0 + bn0;               \
        uint32_t db = sBs + (uint32_t)(((NB) * 4352 + bk * 136 + bn0) * 2);     \
        cpa16(db, sb, 16u); cpa16(db + 16, sb + 8, 16u);                        \
        cpcommit();                                                             \
    }

    float acc[4][4][4] = {};
    ISSUE_AV(0, 0);

    for (int i = 0; i < nch; i++) {
        cpwait<0>();
        __syncthreads();
        if (i + 1 < nch) ISSUE_AV((i + 1) * 32, (i + 1) & 1);

        const __half* Ap = As + (i & 1) * 5120;
        const __half* Bp = Bs + (i & 1) * 4352;
#pragma unroll
        for (int kstep = 0; kstep < 2; kstep++) {
            uint32_t a[4][4], b[4][2];
            {
                const int arow = wm * 64 + ((lane >> 3) & 1) * 8 + (lane & 7);
                const int akc  = kstep * 16 + (lane >> 4) * 8;
#pragma unroll
                for (int mi = 0; mi < 4; mi++)
                    ldsm4(a[mi], Ap + (arow + mi * 16) * 40 + akc);
            }
            {
                const int brow = kstep * 16 + (lane & 7) + ((lane >> 3) & 1) * 8;
#pragma unroll
                for (int ni2 = 0; ni2 < 2; ni2++) {
                    const int bcol = wn * 32 + ni2 * 16 + ((lane >> 4) & 1) * 8;
                    uint32_t r[4];
                    ldsm4t(r, Bp + brow * 136 + bcol);
                    b[2*ni2    ][0] = r[0]; b[2*ni2    ][1] = r[1];
                    b[2*ni2 + 1][0] = r[2]; b[2*ni2 + 1][1] = r[3];
                }
            }
#pragma unroll
            for (int mi = 0; mi < 4; mi++)
#pragma unroll
                for (int ni = 0; ni < 4; ni++)
                    mma16(acc[mi][ni], a[mi], b[ni]);
        }
    }
#undef ISSUE_AV

    const int lo = 6 - lp;
    const int orow = m0 + wm * 64 + (lane >> 2);
    const int ocol = n0 + wn * 32 + (lane & 3) * 2;
#pragma unroll
    for (int mi = 0; mi < 4; mi++) {
#pragma unroll
        for (int hf = 0; hf < 2; hf++) {
            const int m = orow + mi * 16 + hf * 8;
            const int t = m >> (2 * lo);
            const int r = m & ((1 << (2 * lo)) - 1);
            const int ohi = r >> lo, owi = r & ((1 << lo) - 1);
#pragma unroll
            for (int ni = 0; ni < 4; ni++) {
                const int col = ocol + ni * 8;
                const int cc = col >> (2 * lp);
                const int rr = col & ((1 << (2 * lp)) - 1);
                const int pi = rr >> lp, pj = rr & ((1 << lp) - 1);
                long dst = ((long)((z * 8 + t) * 256 + c0 + cc) << 12)
                         + (((ohi << lp) + pi) << 6) + (owi << lp) + pj;
                *(__half2*)(out + dst) = __floats2half2_rn(acc[mi][ni][hf*2], acc[mi][ni][hf*2 + 1]);
            }
        }
    }
}

// ============================================================================
// fp16 mma 32x32 NT split-K (P=32 scores): 2 warps, cross-warp smem reduce
// ============================================================================
__global__ void __launch_bounds__(64) hgemm32_kernel(
    const __half* __restrict__ A, const __half* __restrict__ B, float* __restrict__ C,
    int K, int splitk)
{
    __shared__ __half Qs[32 * 136];
    __shared__ __half Ks[32 * 136];
    __shared__ float buf[32][33];
    const int tid = threadIdx.x;
    const int lane = tid & 31, wrp = tid >> 5;
    const int z = blockIdx.z, bat = z / splitk, ks = z - bat * splitk;
    A += (long)bat * 32 * K;
    B += (long)bat * 32 * K;
    const int kchunk = K / splitk, kbeg = ks * kchunk;

    float acc[2][4][4] = {};
    for (int k0 = kbeg; k0 < kbeg + kchunk; k0 += 128) {
        __syncthreads();
#pragma unroll
        for (int i = 0; i < 8; i++) {
            int u = i * 64 + tid;
            int row = u >> 4, seg = (u & 15) * 8;
            *(uint4*)(Qs + row * 136 + seg) = *(const uint4*)(A + (long)row * K + k0 + seg);
            *(uint4*)(Ks + row * 136 + seg) = *(const uint4*)(B + (long)row * K + k0 + seg);
        }
        __syncthreads();
        for (int s = wrp; s < 8; s += 2) {
            const int kc = s * 16;
            uint32_t a[2][4], b[4][2];
            {
                const int arow = ((lane >> 3) & 1) * 8 + (lane & 7);
                const int akc  = kc + (lane >> 4) * 8;
                ldsm4(a[0], Qs + arow * 136 + akc);
                ldsm4(a[1], Qs + (arow + 16) * 136 + akc);
            }
            {
                const int bkc = kc + ((lane >> 3) & 1) * 8;
#pragma unroll
                for (int ni2 = 0; ni2 < 2; ni2++) {
                    const int brow = ni2 * 16 + ((lane >> 4) & 1) * 8 + (lane & 7);
                    uint32_t r[4];
                    ldsm4(r, Ks + brow * 136 + bkc);
                    b[2*ni2    ][0] = r[0]; b[2*ni2    ][1] = r[1];
                    b[2*ni2 + 1][0] = r[2]; b[2*ni2 + 1][1] = r[3];
                }
            }
#pragma unroll
            for (int mi = 0; mi < 2; mi++)
#pragma unroll
                for (int ni = 0; ni < 4; ni++)
                    mma16(acc[mi][ni], a[mi], b[ni]);
        }
    }

    const int rr = lane >> 2, cc = (lane & 3) * 2;
    if (wrp == 0) {
#pragma unroll
        for (int mi = 0; mi < 2; mi++)
#pragma unroll
            for (int ni = 0; ni < 4; ni++) {
                buf[mi*16 + rr    ][ni*8 + cc]     = acc[mi][ni][0];
                buf[mi*16 + rr    ][ni*8 + cc + 1] = acc[mi][ni][1];
                buf[mi*16 + rr + 8][ni*8 + cc]     = acc[mi][ni][2];
                buf[mi*16 + rr + 8][ni*8 + cc + 1] = acc[mi][ni][3];
            }
    }
    __syncthreads();
    if (wrp == 1) {
#pragma unroll
        for (int mi = 0; mi < 2; mi++)
#pragma unroll
            for (int ni = 0; ni < 4; ni++) {
                buf[mi*16 + rr    ][ni*8 + cc]     += acc[mi][ni][0];
                buf[mi*16 + rr    ][ni*8 + cc + 1] += acc[mi][ni][1];
                buf[mi*16 + rr + 8][ni*8 + cc]     += acc[mi][ni][2];
                buf[mi*16 + rr + 8][ni*8 + cc + 1] += acc[mi][ni][3];
            }
    }
    __syncthreads();
    float* Cz = C + (long)z * 1024;
    for (int i = tid; i < 1024; i += 64)
        Cz[i] = buf[i >> 5][i & 31];
}

// ============================================================================
// fused split-K reduce + softmax + fp16 emit (one block per row)
// ============================================================================
__global__ void rsm_kernel(const float* __restrict__ part, __half* __restrict__ Sh,
                           int n, int splitk, float scale)
{
    __shared__ float buf[2048];
    __shared__ float red[256];
    const int row = blockIdx.x;
    const int b = row / n, r = row - b * n;
    const long base = ((long)b * splitk) * n * n + (long)r * n;
    const int tid = threadIdx.x;
    float m = -1e30f;
    for (int i = tid; i < n; i += 256) {
        float s = 0.f;
        for (int ks = 0; ks < splitk; ks++)
            s += part[base + (long)ks * n * n + i];
        s *= scale;
        buf[i] = s;
        m = fmaxf(m, s);
    }
    red[tid] = m; __syncthreads();
    for (int s = 128; s > 0; s >>= 1) { if (tid < s) red[tid] = fmaxf(red[tid], red[tid + s]); __syncthreads(); }
    m = red[0]; __syncthreads();
    float sum = 0.f;
    for (int i = tid; i < n; i += 256) { float e = expf(buf[i] - m); buf[i] = e; sum += e; }
    red[tid] = sum; __syncthreads();
    for (int s = 128; s > 0; s >>= 1) { if (tid < s) red[tid] += red[tid + s]; __syncthreads(); }
    float inv = 1.f / red[0];
    __half* ph = Sh + (long)row * n;
    for (int i = tid; i < n; i += 256) ph[i] = __float2half(buf[i] * inv);
}

// ===================== SIMT AV for P=32 (probs half, half V, half out) ============
__global__ void __launch_bounds__(256) gemm_av32_kernel(
    const __half* __restrict__ A, const __half* __restrict__ B, __half* __restrict__ out,
    int n, int d, int lp, int c0)
{
    const int z = blockIdx.z;
    A += (long)z * n * n;
    B += (long)z * n * d;
    const int m0 = blockIdx.y * 64, n0 = blockIdx.x * 64;
    __shared__ __align__(16) float As[16][68];
    __shared__ __align__(16) float Bs[16][64];
    const int tid = threadIdx.x;
    const int tx = tid & 15, ty = tid >> 4;
    float acc[4][4] = {};
    for (int k0 = 0; k0 < n; k0 += 16) {
#pragma unroll
        for (int it = 0; it < 4; it++) {
            int id = tid + it * 256;
            int m = id >> 4, kk = id & 15;
            As[kk][m] = (m0 + m < n) ? __half2float(A[(long)(m0 + m) * n + k0 + kk]) : 0.f;
        }
#pragma unroll
        for (int it = 0; it < 4; it++) {
            int id = tid + it * 256;
            int kk = id >> 6, nnn = id & 63;
            Bs[kk][nnn] = __half2float(B[(long)(k0 + kk) * d + n0 + nnn]);
        }
        __syncthreads();
#pragma unroll
        for (int kk = 0; kk < 16; kk++) {
            float4 a4 = *(const float4*)&As[kk][ty * 4];
            float4 b4 = *(const float4*)&Bs[kk][tx * 4];
            float ar[4] = {a4.x, a4.y, a4.z, a4.w};
            float br[4] = {b4.x, b4.y, b4.z, b4.w};
#pragma unroll
            for (int i = 0; i < 4; i++)
#pragma unroll
                for (int j = 0; j < 4; j++)
                    acc[i][j] += ar[i] * br[j];
        }
        __syncthreads();
    }
    const int lo = 6 - lp, o = 1 << lo, P = 1 << lp;
#pragma unroll
    for (int i = 0; i < 4; i++) {
        int m = m0 + ty * 4 + i;
        if (m >= n) continue;
        int t = m >> (2 * lo);
        int r = m & ((1 << (2 * lo)) - 1);
        int ohi = r >> lo, owi = r & (o - 1);
        int col = n0 + tx * 4;
        int cc = col >> (2 * lp);
        int rr = col & (P * P - 1);
        int pi = rr >> lp, pj = rr & (P - 1);
        long dst = ((long)((z * 8 + t) * 256 + c0 + cc) << 12)
                 + (((ohi << lp) + pi) << 6) + (owi << lp) + pj;
        *(__half2*)(out + dst)     = __floats2half2_rn(acc[i][0], acc[i][1]);
        *(__half2*)(out + dst + 2) = __floats2half2_rn(acc[i][2], acc[i][3]);
    }
}

// ===================== in-place softmax on half scores (scale pre-applied) =======
__global__ void softmax_h_kernel(__half* __restrict__ Sh, int n)
{
    __shared__ float buf[2048];
    __shared__ float red[256];
    const long row = blockIdx.x;
    __half* ph = Sh + row * (long)n;
    const int tid = threadIdx.x;
    float m = -1e30f;
    for (int i = tid; i < n; i += 256) { float v = __half2float(ph[i]); buf[i] = v; m = fmaxf(m, v); }
    red[tid] = m; __syncthreads();
    for (int s = 128; s > 0; s >>= 1) { if (tid < s) red[tid] = fmaxf(red[tid], red[tid + s]); __syncthreads(); }
    m = red[0]; __syncthreads();
    float sum = 0.f;
    for (int i = tid; i < n; i += 256) { float e = expf(buf[i] - m); buf[i] = e; sum += e; }
    red[tid] = sum; __syncthreads();
    for (int s = 128; s > 0; s >>= 1) { if (tid < s) red[tid] += red[tid + s]; __syncthreads(); }
    float inv = 1.f / red[0];
    for (int i = tid; i < n; i += 256) ph[i] = __float2half(buf[i] * inv);
}

// ===================== launcher ===================================================
extern "C" void kernel_launch(void* const* d_in, const int* in_sizes, int n_in,
                              void* d_out, int out_size)
{
    const float* xs  = (const float*)d_in[0];
    const float* Wq  = (const float*)d_in[2];
    const float* bq  = (const float*)d_in[3];
    const float* Wk  = (const float*)d_in[4];
    const float* bk  = (const float*)d_in[5];
    const float* Wv  = (const float*)d_in[6];
    const float* bv  = (const float*)d_in[7];
    const float* Wl  = (const float*)d_in[8];
    const float* bl  = (const float*)d_in[9];
    const float* Wf1 = (const float*)d_in[10];
    const float* bf1 = (const float*)d_in[11];
    const float* Wf2 = (const float*)d_in[12];
    const float* bf2 = (const float*)d_in[13];
    float* out = (float*)d_out;

    __half *gQp, *gKp, *gVp, *gXsh, *gAtth, *gXs1h, *gFfh, *gSh;
    __half *gWqkvh, *gWlh, *gWf1h, *gWf2h;
    float *gPart;
    cudaGetSymbolAddress((void**)&gQp,    g_Qp);
    cudaGetSymbolAddress((void**)&gKp,    g_Kp);
    cudaGetSymbolAddress((void**)&gVp,    g_Vp);
    cudaGetSymbolAddress((void**)&gSh,    g_Sh);
    cudaGetSymbolAddress((void**)&gPart,  g_part);
    cudaGetSymbolAddress((void**)&gXsh,   g_xsh);
    cudaGetSymbolAddress((void**)&gAtth,  g_atth);
    cudaGetSymbolAddress((void**)&gXs1h,  g_xs1h);
    cudaGetSymbolAddress((void**)&gFfh,   g_ffh);
    cudaGetSymbolAddress((void**)&gWqkvh, g_Wqkvh);
    cudaGetSymbolAddress((void**)&gWlh,   g_Wlh);
    cudaGetSymbolAddress((void**)&gWf1h,  g_Wf1h);
    cudaGetSymbolAddress((void**)&gWf2h,  g_Wf2h);

    cudaFuncSetAttribute(hconvK_kernel,
                         cudaFuncAttributeMaxDynamicSharedMemorySize, HK_SMEM);

    dim3 blk(256);
    dim3 qgrid(NIMG * 32, 2);

    // pre-convert inputs + weights (batched launches)
    f2h_kernel<<<16384, blk>>>(xs, gXsh);
    f2h3_kernel<<<192, blk>>>(Wq, Wk, Wv, gWqkvh);
    wtrans3_kernel<<<3 * 2304, blk>>>(Wl, Wf1, Wf2, gWlh, gWf1h, gWf2h);

    // fused QKV projection -> patchified half buffers (bias fused)
    hconv2_kernel<<<dim3(NIMG * 32, 6), blk>>>(gXsh, gWqkvh, bq, bk, bv, gQp, gKp, gVp);

    // ---- P=32 (n=32, d=65536) ----
    {
        const int n = 32, d = 65536, splitk = 256;
        hgemm32_kernel<<<dim3(1, 1, 2 * splitk), 64>>>(gQp, gKp, gPart, d, splitk);
        rsm_kernel<<<2 * n, blk>>>(gPart, gSh, n, splitk, 1.0f / 256.0f);
        gemm_av32_kernel<<<dim3(d / 64, 1, 2), blk>>>(gSh, gVp, gAtth, n, d, 5, 0);
    }
    // ---- P=16 (n=128, d=16384) ----
    {
        const int n = 128, d = 16384, splitk = 64;
        const long soff = 4194304;
        hgemm_nt_kernel<<<dim3(1, 1, 2 * splitk), blk>>>(
            gQp + soff, gKp + soff, gPart, nullptr, 1.0f,
            n, d, splitk, (long)n * d, (long)n * n);
        rsm_kernel<<<2 * n, blk>>>(gPart, gSh, n, splitk, 1.0f / 128.0f);
        hgemm_av_kernel<<<dim3(d / 128, n / 128, 2), blk>>>(gSh, gVp + soff, gAtth, n, d, 4, 64);
    }
    // ---- P=8 (n=512, d=4096) ----
    {
        const int n = 512, d = 4096, splitk = 8;
        const long soff = 2L * 4194304;
        hgemm_nt_kernel<<<dim3(n / 128, n / 128, 2 * splitk), blk>>>(
            gQp + soff, gKp + soff, gPart, nullptr, 1.0f,
            n, d, splitk, (long)n * d, (long)n * n);
        rsm_kernel<<<2 * n, blk>>>(gPart, gSh, n, splitk, 1.0f / 64.0f);
        hgemm_av_kernel<<<dim3(d / 128, n / 128, 2), blk>>>(gSh, gVp + soff, gAtth, n, d, 3, 128);
    }
    // ---- P=4 (n=2048, d=1024): scores -> scaled half, in-place softmax ----
    {
        const int n = 2048, d = 1024;
        const long soff = 3L * 4194304;
        hgemm_nt_kernel<<<dim3(n / 128, n / 128, 2), blk>>>(
            gQp + soff, gKp + soff, nullptr, gSh, 1.0f / 32.0f,
            n, d, 1, (long)n * d, (long)n * n);
        softmax_h_kernel<<<2 * n, blk>>>(gSh, n);
        hgemm_av_kernel<<<dim3(d / 128, n / 128, 2), blk>>>(gSh, gVp + soff, gAtth, n, d, 2, 192);
    }

    // convs: tap-row-major K, strip shared across 3 chunks; half residual chain
    hconvK_kernel<<<qgrid, blk, HK_SMEM>>>(gAtth, gWlh,  bl,  xs,      nullptr, nullptr, gXs1h, 1, 1);
    hconvK_kernel<<<qgrid, blk, HK_SMEM>>>(gXs1h, gWf1h, bf1, nullptr, nullptr, nullptr, gFfh,  1, 0);
    hconvK_kernel<<<qgrid, blk, HK_SMEM>>>(gFfh,  gWf2h, bf2, nullptr, gXs1h,   out,     nullptr, 2, 1);
}

// round 16
// speedup vs baseline: 1.2009x; 1.0026x over previous
#include <cuda_runtime.h>
#include <cuda_fp16.h>
#include <math.h>
#include <stdint.h>

#define NIMG 16
#define CCH 256
#define NPIX 4096            // 64*64

// scratch region offsets (disjoint so all scales can run concurrently)
#define SOFF16 4194304L
#define SOFF8  8388608L
#define SOFF4  12582912L
#define PART32 0L
#define PART16 524288L
#define PART8  2621440L
#define SH4    0L
#define SH8    8388608L
#define SH16   8912896L
#define SH32   8945664L

// ---- scratch (static device globals; no allocation) ----
__device__ __half g_Qp[16777216];
__device__ __half g_Kp[16777216];
__device__ __half g_Vp[16777216];
__device__ __half g_Sh[8947712];
__device__ float  g_part[8388608];
__device__ __half g_xsh [NIMG*CCH*NPIX];
__device__ __half g_atth[NIMG*CCH*NPIX];
__device__ __half g_xs1h[NIMG*CCH*NPIX];
__device__ __half g_ffh [NIMG*CCH*NPIX];
__device__ __half g_Wqkvh[196608];
__device__ __half g_Wlh[589824], g_Wf1h[589824], g_Wf2h[589824];

// ============================================================================
// helpers
// ============================================================================
__device__ __forceinline__ void mma16(float* d, const uint32_t* a, const uint32_t* b) {
    asm volatile(
        "mma.sync.aligned.m16n8k16.row.col.f32.f16.f16.f32 "
        "{%0,%1,%2,%3}, {%4,%5,%6,%7}, {%8,%9}, {%0,%1,%2,%3};"
        : "+f"(d[0]), "+f"(d[1]), "+f"(d[2]), "+f"(d[3])
        : "r"(a[0]), "r"(a[1]), "r"(a[2]), "r"(a[3]), "r"(b[0]), "r"(b[1]));
}

__device__ __forceinline__ void ldsm4(uint32_t* r, const void* p) {
    uint32_t addr = (uint32_t)__cvta_generic_to_shared(p);
    asm volatile("ldmatrix.sync.aligned.m8n8.x4.shared.b16 {%0,%1,%2,%3}, [%4];"
        : "=r"(r[0]), "=r"(r[1]), "=r"(r[2]), "=r"(r[3]) : "r"(addr));
}

__device__ __forceinline__ void ldsm4t(uint32_t* r, const void* p) {
    uint32_t addr = (uint32_t)__cvta_generic_to_shared(p);
    asm volatile("ldmatrix.sync.aligned.m8n8.x4.trans.shared.b16 {%0,%1,%2,%3}, [%4];"
        : "=r"(r[0]), "=r"(r[1]), "=r"(r[2]), "=r"(r[3]) : "r"(addr));
}

__device__ __forceinline__ uint32_t pack_h2(float a, float b) {
    __half2 h = __floats2half2_rn(a, b);
    return *(uint32_t*)&h;
}

__device__ __forceinline__ void cpa16(uint32_t dst, const void* src, unsigned sz) {
    asm volatile("cp.async.ca.shared.global [%0], [%1], 16, %2;"
                 :: "r"(dst), "l"(src), "r"(sz) : "memory");
}
__device__ __forceinline__ void cpcommit() {
    asm volatile("cp.async.commit_group;" ::: "memory");
}
template <int N>
__device__ __forceinline__ void cpwait() {
    asm volatile("cp.async.wait_group %0;" :: "n"(N) : "memory");
}

// f32 -> f16 bulk convert
__global__ void f2h_kernel(const float* __restrict__ src, __half* __restrict__ dst) {
    long i = ((long)blockIdx.x * 256 + threadIdx.x) * 4;
    float4 v = *(const float4*)(src + i);
    *(uint32_t*)(dst + i)     = pack_h2(v.x, v.y);
    *(uint32_t*)(dst + i + 2) = pack_h2(v.z, v.w);
}

// batched f2h: QKV weights -> stacked [768][256]
__global__ void f2h3_kernel(const float* __restrict__ s0, const float* __restrict__ s1,
                            const float* __restrict__ s2, __half* __restrict__ d) {
    int z = blockIdx.x >> 6;
    const float* s = (z == 0) ? s0 : ((z == 1) ? s1 : s2);
    long i = ((long)(blockIdx.x & 63) * 256 + threadIdx.x) * 4;
    __half* dz = d + (long)z * 65536;
    float4 v = *(const float4*)(s + i);
    *(uint32_t*)(dz + i)     = pack_h2(v.x, v.y);
    *(uint32_t*)(dz + i + 2) = pack_h2(v.z, v.w);
}

// batched conv weight permute to tap-row-major
__global__ void wtrans3_kernel(const float* __restrict__ W0, const float* __restrict__ W1,
                               const float* __restrict__ W2,
                               __half* __restrict__ D0, __half* __restrict__ D1,
                               __half* __restrict__ D2) {
    int z = blockIdx.x / 2304;
    const float* W = (z == 0) ? W0 : ((z == 1) ? W1 : W2);
    __half* Wt2 = (z == 0) ? D0 : ((z == 1) ? D1 : D2);
    int idx = (blockIdx.x - z * 2304) * 256 + threadIdx.x;
    int oc = idx / 2304, r = idx - oc * 2304;
    int dy = r / 768;   int r2 = r - dy * 768;
    int cg = r2 / 192;  int r3 = r2 - cg * 192;
    int tx = r3 / 64;   int ci = r3 - tx * 64;
    Wt2[idx] = __float2half(W[oc * 2304 + (cg * 64 + ci) * 9 + dy * 3 + tx]);
}

// scatter index into patchified buffer: scale = oc>>6
__device__ __forceinline__ long pat_index(int img, int oc, int pix) {
    int s  = oc >> 6, cc = oc & 63;
    int lp = 5 - s;
    int lo = 1 + s;
    int Pm = (1 << lp) - 1;
    int y = pix >> 6, x = pix & 63;
    int ohi = y >> lp, pi = y & Pm, owi = x >> lp, pj = x & Pm;
    int t = img & 7, b = img >> 3;
    int nn = (t << (2*lo)) + (ohi << lo) + owi;
    int dd = (cc << (2*lp)) + (pi << lp) + pj;
    return (long)s * 4194304 + (long)b * 2097152 + (long)nn * (64 << (2*lp)) + dd;
}

// ============================================================================
// hconv2qkv: fused Q/K/V projection (stacked weights [768][256]), grid.y = 6
// ============================================================================
__global__ void __launch_bounds__(256, 2) hconv2_kernel(
    const __half* __restrict__ in, const __half* __restrict__ Wt,
    const float* __restrict__ bq, const float* __restrict__ bk, const float* __restrict__ bv,
    __half* __restrict__ Qp, __half* __restrict__ Kp, __half* __restrict__ Vp)
{
    __shared__ __half A2[2 * 128 * 40];
    __shared__ __half B2[2 * 32 * 136];

    const int tid = threadIdx.x;
    const int lane = tid & 31, wid = tid >> 5;
    const int wm = wid & 1, wn = wid >> 1;
    const int img = blockIdx.x >> 5;
    const int p0 = (blockIdx.x & 31) * 128;
    const int m0 = blockIdx.y * 128;
    const int proj = m0 >> 8;
    const __half* inimg = in + (long)img * CCH * NPIX;
    const float* bias = (proj == 0) ? bq : ((proj == 1) ? bk : bv);
    __half* outh_pat = (proj == 0) ? Qp : ((proj == 1) ? Kp : Vp);

    const uint32_t sA2 = (uint32_t)__cvta_generic_to_shared(A2);
    const uint32_t sB2 = (uint32_t)__cvta_generic_to_shared(B2);

#define ISSUE1(KCN, NB)                                                         \
    {                                                                           \
        const int k0n = (KCN) * 32;                                             \
        {                                                                       \
            int row = tid >> 1, seg = (tid & 1) * 16;                           \
            const __half* src = Wt + (long)(m0 + row) * 256 + k0n + seg;        \
            uint32_t dst = sA2 + (uint32_t)(((NB) * 5120 + row * 40 + seg) * 2);\
            cpa16(dst, src, 16u); cpa16(dst + 16, src + 8, 16u);                \
        }                                                                       \
        {                                                                       \
            int k = tid >> 3, u = tid & 7;                                      \
            const __half* src = inimg + ((long)(k0n + k) << 12) + p0 + u * 8;   \
            uint32_t dst = sB2 + (uint32_t)(((NB) * 4352 + k * 136 + u * 8) * 2); \
            cpa16(dst, src, 16u);                                               \
            cpa16(dst + 128, src + 64, 16u);                                    \
        }                                                                       \
        cpcommit();                                                             \
    }

    float acc[4][4][4] = {};
    ISSUE1(0, 0);

    for (int kc = 0; kc < 8; kc++) {
        cpwait<0>();
        __syncthreads();
        if (kc + 1 < 8) ISSUE1(kc + 1, (kc + 1) & 1);

        const __half* Ap = A2 + (kc & 1) * 5120;
        const __half* Bp = B2 + (kc & 1) * 4352;
#pragma unroll
        for (int kstep = 0; kstep < 2; kstep++) {
            uint32_t a[4][4], b[4][2];
            {
                const int arow = wm * 64 + ((lane >> 3) & 1) * 8 + (lane & 7);
                const int akc  = kstep * 16 + (lane >> 4) * 8;
#pragma unroll
                for (int mi = 0; mi < 4; mi++)
                    ldsm4(a[mi], Ap + (arow + mi * 16) * 40 + akc);
            }
            {
                const int brow = kstep * 16 + (lane & 7) + ((lane >> 3) & 1) * 8;
#pragma unroll
                for (int ni2 = 0; ni2 < 2; ni2++) {
                    const int bcol = wn * 32 + ni2 * 16 + ((lane >> 4) & 1) * 8;
                    uint32_t r[4];
                    ldsm4t(r, Bp + brow * 136 + bcol);
                    b[2*ni2    ][0] = r[0]; b[2*ni2    ][1] = r[1];
                    b[2*ni2 + 1][0] = r[2]; b[2*ni2 + 1][1] = r[3];
                }
            }
#pragma unroll
            for (int mi = 0; mi < 4; mi++)
#pragma unroll
                for (int ni = 0; ni < 4; ni++)
                    mma16(acc[mi][ni], a[mi], b[ni]);
        }
    }
#undef ISSUE1

    const int orow = (m0 & 255) + wm * 64 + (lane >> 2);
    const int ocol = p0 + wn * 32 + (lane & 3) * 2;
#pragma unroll
    for (int mi = 0; mi < 4; mi++) {
        const int oca = orow + mi * 16, ocb = oca + 8;
        const float ba = bias[oca], bb = bias[ocb];
#pragma unroll
        for (int ni = 0; ni < 4; ni++) {
            const int n = ocol + ni * 8;
            long ia = pat_index(img, oca, n);
            long ib = pat_index(img, ocb, n);
            *(__half2*)(outh_pat + ia) = __floats2half2_rn(acc[mi][ni][0] + ba, acc[mi][ni][1] + ba);
            *(__half2*)(outh_pat + ib) = __floats2half2_rn(acc[mi][ni][2] + bb, acc[mi][ni][3] + bb);
        }
    }
}

// ============================================================================
// hconvK: 3x3 conv, tap-ROW-major K (strip shared by 3 chunks), 256 threads
// ============================================================================
#define HK_A2    0
#define HK_BS    18432
#define HK_STRIP (18432 + 8704)
#define HK_SMEM  ((18432 + 8704 + 10240) * 2)

__global__ void __launch_bounds__(256, 2) hconvK_kernel(
    const __half* __restrict__ in, const __half* __restrict__ Wt,
    const float* __restrict__ bias, const float* __restrict__ res,
    const __half* __restrict__ resh,
    float* __restrict__ out, __half* __restrict__ outh_img,
    int dil, int addres)
{
    extern __shared__ __half sh[];
    __half* A2    = sh + HK_A2;
    __half* Bs    = sh + HK_BS;
    __half* Strip = sh + HK_STRIP;

    const int tid = threadIdx.x;
    const int lane = tid & 31, wid = tid >> 5;
    const int wm = wid & 1, wn = wid >> 1;
    const int img = blockIdx.x >> 5;
    const int p0 = (blockIdx.x & 31) * 128;
    const int y0 = p0 >> 6;
    const int m0 = blockIdx.y * 128;
    const __half* inimg = in + (long)img * CCH * NPIX;

    const uint32_t sA2    = (uint32_t)__cvta_generic_to_shared(A2);
    const uint32_t sStrip = (uint32_t)__cvta_generic_to_shared(Strip);

    {
        int c = tid >> 2, u = tid & 3, r = u >> 1, side = u & 1;
        *(uint4*)(Strip + c * 160 + r * 80 + side * 72) = make_uint4(0, 0, 0, 0);
    }

#define ISSUE_A(KCN, NB)                                                         \
    {                                                                            \
        int row = tid >> 1, seg = (tid & 1) * 32;                                \
        const __half* src = Wt + (long)(m0 + row) * 2304 + (KCN) * 64 + seg;     \
        uint32_t dst = sA2 + (uint32_t)(((NB) * 9216 + row * 72 + seg) * 2);     \
        cpa16(dst,      src,      16u);                                          \
        cpa16(dst + 16, src + 8,  16u);                                          \
        cpa16(dst + 32, src + 16, 16u);                                          \
        cpa16(dst + 48, src + 24, 16u);                                          \
    }

#define ISSUE_S(KCN)                                                             \
    {                                                                            \
        int dyg = (KCN) / 12;                                                    \
        int c0v = (((KCN) % 12) / 3) * 64;                                       \
        int dyd = (dyg - 1) * dil;                                               \
        int c = tid >> 2, u = tid & 3;                                           \
        int r = u >> 1, s = u & 1;                                               \
        int gy = y0 + r + dyd;                                                   \
        unsigned ok = ((unsigned)gy < 64u) ? 16u : 0u;                           \
        int gyc = gy < 0 ? 0 : (gy > 63 ? 63 : gy);                              \
        const __half* src = inimg + ((long)(c0v + c) << 12) + (gyc << 6) + s * 32; \
        uint32_t dst = sStrip + (uint32_t)((c * 160 + r * 80 + 8 + s * 32) * 2); \
        cpa16(dst,      src,      ok);                                           \
        cpa16(dst + 16, src + 8,  ok);                                           \
        cpa16(dst + 32, src + 16, ok);                                           \
        cpa16(dst + 48, src + 24, ok);                                           \
    }

    float acc[4][4][4] = {};
    ISSUE_A(0, 0);
    ISSUE_S(0);
    cpcommit();

    for (int kc = 0; kc < 36; kc++) {
        cpwait<0>();
        __syncthreads();

        {
            const int dxd = (kc % 3 - 1) * dil;
            const int c = tid >> 2, u = tid & 3, prow = u >> 1, xseg = (u & 1) * 32;
            const uint32_t* rowp = (const uint32_t*)(Strip + c * 160 + prow * 80);
            const int h0 = 8 + dxd + xseg;
            uint32_t w[16];
            if (dxd & 1) {
                int k0 = (h0 - 1) >> 1;
                uint32_t prev = rowp[k0];
#pragma unroll
                for (int j = 0; j < 16; j++) {
                    uint32_t nxt = rowp[k0 + 1 + j];
                    w[j] = __funnelshift_r(prev, nxt, 16);
                    prev = nxt;
                }
            } else {
                int k0 = h0 >> 1;
#pragma unroll
                for (int j = 0; j < 16; j++) w[j] = rowp[k0 + j];
            }
            uint4* bd = (uint4*)(Bs + c * 136 + prow * 64 + xseg);
#pragma unroll
            for (int j = 0; j < 4; j++)
                bd[j] = make_uint4(w[4*j], w[4*j+1], w[4*j+2], w[4*j+3]);
        }
        __syncthreads();

        if (kc + 1 < 36) {
            ISSUE_A(kc + 1, (kc + 1) & 1);
            if ((kc + 1) % 3 == 0) ISSUE_S(kc + 1);
            cpcommit();
        }

        const __half* Ap = A2 + (kc & 1) * 9216;
#pragma unroll
        for (int kstep = 0; kstep < 4; kstep++) {
            uint32_t a[4][4], b[4][2];
            {
                const int arow = wm * 64 + ((lane >> 3) & 1) * 8 + (lane & 7);
                const int akc  = kstep * 16 + (lane >> 4) * 8;
#pragma unroll
                for (int mi = 0; mi < 4; mi++)
                    ldsm4(a[mi], Ap + (arow + mi * 16) * 72 + akc);
            }
            {
                const int brow = kstep * 16 + (lane & 7) + ((lane >> 3) & 1) * 8;
#pragma unroll
                for (int ni2 = 0; ni2 < 2; ni2++) {
                    const int bcol = wn * 32 + ni2 * 16 + ((lane >> 4) & 1) * 8;
                    uint32_t r[4];
                    ldsm4t(r, Bs + brow * 136 + bcol);
                    b[2*ni2    ][0] = r[0]; b[2*ni2    ][1] = r[1];
                    b[2*ni2 + 1][0] = r[2]; b[2*ni2 + 1][1] = r[3];
                }
            }
#pragma unroll
            for (int mi = 0; mi < 4; mi++)
#pragma unroll
                for (int ni = 0; ni < 4; ni++)
                    mma16(acc[mi][ni], a[mi], b[ni]);
        }
    }
#undef ISSUE_A
#undef ISSUE_S

    const int orow = m0 + wm * 64 + (lane >> 2);
    const int ocol = p0 + wn * 32 + (lane & 3) * 2;
#pragma unroll
    for (int mi = 0; mi < 4; mi++) {
        const int oca = orow + mi * 16;
        const int ocb = oca + 8;
        const float ba = bias[oca], bb = bias[ocb];
#pragma unroll
        for (int ni = 0; ni < 4; ni++) {
            const int n = ocol + ni * 8;
            long ia = ((long)img * 256 + oca) * NPIX + n;
            long ib = ((long)img * 256 + ocb) * NPIX + n;
            float v0 = acc[mi][ni][0] + ba, v1 = acc[mi][ni][1] + ba;
            float v2 = acc[mi][ni][2] + bb, v3 = acc[mi][ni][3] + bb;
            v0 = (v0 > 0.f) ? v0 : 0.2f * v0;
            v1 = (v1 > 0.f) ? v1 : 0.2f * v1;
            v2 = (v2 > 0.f) ? v2 : 0.2f * v2;
            v3 = (v3 > 0.f) ? v3 : 0.2f * v3;
            if (addres) {
                if (resh) {
                    __half2 ra = *(const __half2*)(resh + ia);
                    __half2 rb = *(const __half2*)(resh + ib);
                    float2 fa = __half22float2(ra), fb = __half22float2(rb);
                    v0 += fa.x; v1 += fa.y; v2 += fb.x; v3 += fb.y;
                } else {
                    v0 += res[ia]; v1 += res[ia + 1];
                    v2 += res[ib]; v3 += res[ib + 1];
                }
            }
            if (out) {
                out[ia] = v0; out[ia + 1] = v1;
                out[ib] = v2; out[ib + 1] = v3;
            }
            if (outh_img) {
                *(__half2*)(outh_img + ia) = __floats2half2_rn(v0, v1);
                *(__half2*)(outh_img + ib) = __floats2half2_rn(v2, v3);
            }
        }
    }
}

// ============================================================================
// nt_body: fp16 NT GEMM body (scores), cp.async double-buffered
// ============================================================================
__device__ __forceinline__ void nt_body(
    const __half* A, const __half* B, float* C, __half* Ch, float emitScale,
    int N, int K, int splitk, long sAB, long sC,
    int bxx, int byy, int bzz, __half* As, __half* Bs)
{
    const int tid = threadIdx.x;
    const int lane = tid & 31, wid = tid >> 5;
    const int wm = wid & 1, wn = wid >> 1;
    const int n0 = bxx * 128, m0 = byy * 128;
    const int z = bzz, bat = z / splitk, ks = z - bat * splitk;
    A += (long)bat * sAB;
    B += (long)bat * sAB;
    const int kchunk = K / splitk, kbeg = ks * kchunk;
    const int nch = kchunk / 32;
    const int wr = tid >> 1, wkh = (tid & 1) * 16;

    const uint32_t sAs = (uint32_t)__cvta_generic_to_shared(As);
    const uint32_t sBs = (uint32_t)__cvta_generic_to_shared(Bs);

#define ISSUE_NT(K0v, NB)                                                       \
    {                                                                           \
        const __half* sa = A + (long)(m0 + wr) * K + (K0v) + wkh;               \
        const __half* sb = B + (long)(n0 + wr) * K + (K0v) + wkh;               \
        uint32_t da = sAs + (uint32_t)(((NB) * 5120 + wr * 40 + wkh) * 2);      \
        uint32_t db = sBs + (uint32_t)(((NB) * 5120 + wr * 40 + wkh) * 2);      \
        cpa16(da, sa, 16u); cpa16(da + 16, sa + 8, 16u);                        \
        cpa16(db, sb, 16u); cpa16(db + 16, sb + 8, 16u);                        \
        cpcommit();                                                             \
    }

    float acc[4][4][4] = {};
    ISSUE_NT(kbeg, 0);

    for (int i = 0; i < nch; i++) {
        cpwait<0>();
        __syncthreads();
        if (i + 1 < nch) ISSUE_NT(kbeg + (i + 1) * 32, (i + 1) & 1);

        const __half* Ap = As + (i & 1) * 5120;
        const __half* Bp = Bs + (i & 1) * 5120;
#pragma unroll
        for (int kstep = 0; kstep < 2; kstep++) {
            uint32_t a[4][4], b[4][2];
            {
                const int arow = wm * 64 + ((lane >> 3) & 1) * 8 + (lane & 7);
                const int akc  = kstep * 16 + (lane >> 4) * 8;
#pragma unroll
                for (int mi = 0; mi < 4; mi++)
                    ldsm4(a[mi], Ap + (arow + mi * 16) * 40 + akc);
            }
            {
                const int bkc = kstep * 16 + ((lane >> 3) & 1) * 8;
#pragma unroll
                for (int ni2 = 0; ni2 < 2; ni2++) {
                    const int brow = wn * 32 + ni2 * 16 + ((lane >> 4) & 1) * 8 + (lane & 7);
                    uint32_t r[4];
                    ldsm4(r, Bs + ((i & 1) * 5120) + brow * 40 + bkc);
                    (void)Bp;
                    b[2*ni2    ][0] = r[0]; b[2*ni2    ][1] = r[1];
                    b[2*ni2 + 1][0] = r[2]; b[2*ni2 + 1][1] = r[3];
                }
            }
#pragma unroll
            for (int mi = 0; mi < 4; mi++)
#pragma unroll
                for (int ni = 0; ni < 4; ni++)
                    mma16(acc[mi][ni], a[mi], b[ni]);
        }
    }
#undef ISSUE_NT

    const int orow = m0 + wm * 64 + (lane >> 2);
    const int ocol = n0 + wn * 32 + (lane & 3) * 2;
    if (Ch) {
        Ch += (long)z * sC;
#pragma unroll
        for (int mi = 0; mi < 4; mi++) {
            long ra = (long)(orow + mi * 16) * N;
            long rb = (long)(orow + mi * 16 + 8) * N;
#pragma unroll
            for (int ni = 0; ni < 4; ni++) {
                int n = ocol + ni * 8;
                *(__half2*)(Ch + ra + n) = __floats2half2_rn(acc[mi][ni][0] * emitScale,
                                                             acc[mi][ni][1] * emitScale);
                *(__half2*)(Ch + rb + n) = __floats2half2_rn(acc[mi][ni][2] * emitScale,
                                                             acc[mi][ni][3] * emitScale);
            }
        }
    } else {
        C += (long)z * sC;
#pragma unroll
        for (int mi = 0; mi < 4; mi++) {
            long ra = (long)(orow + mi * 16) * N;
            long rb = (long)(orow + mi * 16 + 8) * N;
#pragma unroll
            for (int ni = 0; ni < 4; ni++) {
                int n = ocol + ni * 8;
                C[ra + n] = acc[mi][ni][0]; C[ra + n + 1] = acc[mi][ni][1];
                C[rb + n] = acc[mi][ni][2]; C[rb + n + 1] = acc[mi][ni][3];
            }
        }
    }
}

// combined scores launch: [0,128) P16 | [128,384) P8 | [384,896) P4
__global__ void __launch_bounds__(256) scores_all_kernel(
    const __half* __restrict__ Qp, const __half* __restrict__ Kp,
    float* __restrict__ part, __half* __restrict__ Sh)
{
    __shared__ __half As[2 * 128 * 40];
    __shared__ __half Bs[2 * 128 * 40];
    const int l = blockIdx.x;
    if (l < 128) {
        nt_body(Qp + SOFF16, Kp + SOFF16, part + PART16, nullptr, 1.0f,
                128, 16384, 64, 128L * 16384, 128L * 128, 0, 0, l, As, Bs);
    } else if (l < 384) {
        const int t = l - 128;
        nt_body(Qp + SOFF8, Kp + SOFF8, part + PART8, nullptr, 1.0f,
                512, 4096, 8, 512L * 4096, 512L * 512,
                t & 3, (t >> 2) & 3, t >> 4, As, Bs);
    } else {
        const int t = l - 384;
        nt_body(Qp + SOFF4, Kp + SOFF4, nullptr, Sh + SH4, 1.0f / 32.0f,
                2048, 1024, 1, 2048L * 1024, 2048L * 2048,
                t & 15, (t >> 4) & 15, t >> 8, As, Bs);
    }
}

// ============================================================================
// av_body: fp16 AV GEMM body (half probs), cp.async double-buffered
// ============================================================================
__device__ __forceinline__ void av_body(
    const __half* S, const __half* V, __half* out,
    int n, int d, int lp, int c0,
    int bxx, int byy, int bzz, __half* As, __half* Bs)
{
    const int tid = threadIdx.x;
    const int lane = tid & 31, wid = tid >> 5;
    const int wm = wid & 1, wn = wid >> 1;
    const int z = bzz;
    S += (long)z * n * n;
    V += (long)z * n * d;
    const int n0 = bxx * 128;
    const int m0 = byy * 128;
    const int wr = tid >> 1, wkh = (tid & 1) * 16;
    const int bk = tid >> 3, bn0 = (tid & 7) * 16;
    const int nch = n / 32;

    const uint32_t sAs = (uint32_t)__cvta_generic_to_shared(As);
    const uint32_t sBs = (uint32_t)__cvta_generic_to_shared(Bs);

#define ISSUE_AV(K0v, NB)                                                       \
    {                                                                           \
        const __half* sa = S + (long)(m0 + wr) * n + (K0v) + wkh;               \
        uint32_t da = sAs + (uint32_t)(((NB) * 5120 + wr * 40 + wkh) * 2);      \
        cpa16(da, sa, 16u); cpa16(da + 16, sa + 8, 16u);                        \
        const __half* sb = V + (long)((K0v) + bk) * d + n0 + bn0;               \
        uint32_t db = sBs + (uint32_t)(((NB) * 4352 + bk * 136 + bn0) * 2);     \
        cpa16(db, sb, 16u); cpa16(db + 16, sb + 8, 16u);                        \
        cpcommit();                                                             \
    }

    float acc[4][4][4] = {};
    ISSUE_AV(0, 0);

    for (int i = 0; i < nch; i++) {
        cpwait<0>();
        __syncthreads();
        if (i + 1 < nch) ISSUE_AV((i + 1) * 32, (i + 1) & 1);

        const __half* Ap = As + (i & 1) * 5120;
        const __half* Bp = Bs + (i & 1) * 4352;
#pragma unroll
        for (int kstep = 0; kstep < 2; kstep++) {
            uint32_t a[4][4], b[4][2];
            {
                const int arow = wm * 64 + ((lane >> 3) & 1) * 8 + (lane & 7);
                const int akc  = kstep * 16 + (lane >> 4) * 8;
#pragma unroll
                for (int mi = 0; mi < 4; mi++)
                    ldsm4(a[mi], Ap + (arow + mi * 16) * 40 + akc);
            }
            {
                const int brow = kstep * 16 + (lane & 7) + ((lane >> 3) & 1) * 8;
#pragma unroll
                for (int ni2 = 0; ni2 < 2; ni2++) {
                    const int bcol = wn * 32 + ni2 * 16 + ((lane >> 4) & 1) * 8;
                    uint32_t r[4];
                    ldsm4t(r, Bp + brow * 136 + bcol);
                    b[2*ni2    ][0] = r[0]; b[2*ni2    ][1] = r[1];
                    b[2*ni2 + 1][0] = r[2]; b[2*ni2 + 1][1] = r[3];
                }
            }
#pragma unroll
            for (int mi = 0; mi < 4; mi++)
#pragma unroll
                for (int ni = 0; ni < 4; ni++)
                    mma16(acc[mi][ni], a[mi], b[ni]);
        }
    }
#undef ISSUE_AV

    const int lo = 6 - lp;
    const int orow = m0 + wm * 64 + (lane >> 2);
    const int ocol = n0 + wn * 32 + (lane & 3) * 2;
#pragma unroll
    for (int mi = 0; mi < 4; mi++) {
#pragma unroll
        for (int hf = 0; hf < 2; hf++) {
            const int m = orow + mi * 16 + hf * 8;
            const int t = m >> (2 * lo);
            const int r = m & ((1 << (2 * lo)) - 1);
            const int ohi = r >> lo, owi = r & ((1 << lo) - 1);
#pragma unroll
            for (int ni = 0; ni < 4; ni++) {
                const int col = ocol + ni * 8;
                const int cc = col >> (2 * lp);
                const int rr = col & ((1 << (2 * lp)) - 1);
                const int pi = rr >> lp, pj = rr & ((1 << lp) - 1);
                long dst = ((long)((z * 8 + t) * 256 + c0 + cc) << 12)
                         + (((ohi << lp) + pi) << 6) + (owi << lp) + pj;
                *(__half2*)(out + dst) = __floats2half2_rn(acc[mi][ni][hf*2], acc[mi][ni][hf*2 + 1]);
            }
        }
    }
}

// combined AV launch: [0,256) P16 | [256,512) P8 | [512,768) P4
__global__ void __launch_bounds__(256) av_all_kernel(
    const __half* __restrict__ Sh, const __half* __restrict__ Vp,
    __half* __restrict__ atth)
{
    __shared__ __half As[2 * 128 * 40];
    __shared__ __half Bs[2 * 32 * 136];
    const int l = blockIdx.x;
    if (l < 256) {
        av_body(Sh + SH16, Vp + SOFF16, atth, 128, 16384, 4, 64,
                l & 127, 0, l >> 7, As, Bs);
    } else if (l < 512) {
        const int t = l - 256;
        av_body(Sh + SH8, Vp + SOFF8, atth, 512, 4096, 3, 128,
                t & 31, (t >> 5) & 3, t >> 7, As, Bs);
    } else {
        const int t = l - 512;
        av_body(Sh + SH4, Vp + SOFF4, atth, 2048, 1024, 2, 192,
                t & 7, (t >> 3) & 15, t >> 7, As, Bs);
    }
}

// ============================================================================
// fp16 mma 32x32 NT split-K (P=32 scores): 2 warps, cross-warp smem reduce
// ============================================================================
__global__ void __launch_bounds__(64) hgemm32_kernel(
    const __half* __restrict__ A, const __half* __restrict__ B, float* __restrict__ C,
    int K, int splitk)
{
    __shared__ __half Qs[32 * 136];
    __shared__ __half Ks[32 * 136];
    __shared__ float buf[32][33];
    const int tid = threadIdx.x;
    const int lane = tid & 31, wrp = tid >> 5;
    const int z = blockIdx.z, bat = z / splitk, ks = z - bat * splitk;
    A += (long)bat * 32 * K;
    B += (long)bat * 32 * K;
    const int kchunk = K / splitk, kbeg = ks * kchunk;

    float acc[2][4][4] = {};
    for (int k0 = kbeg; k0 < kbeg + kchunk; k0 += 128) {
        __syncthreads();
#pragma unroll
        for (int i = 0; i < 8; i++) {
            int u = i * 64 + tid;
            int row = u >> 4, seg = (u & 15) * 8;
            *(uint4*)(Qs + row * 136 + seg) = *(const uint4*)(A + (long)row * K + k0 + seg);
            *(uint4*)(Ks + row * 136 + seg) = *(const uint4*)(B + (long)row * K + k0 + seg);
        }
        __syncthreads();
        for (int s = wrp; s < 8; s += 2) {
            const int kc = s * 16;
            uint32_t a[2][4], b[4][2];
            {
                const int arow = ((lane >> 3) & 1) * 8 + (lane & 7);
                const int akc  = kc + (lane >> 4) * 8;
                ldsm4(a[0], Qs + arow * 136 + akc);
                ldsm4(a[1], Qs + (arow + 16) * 136 + akc);
            }
            {
                const int bkc = kc + ((lane >> 3) & 1) * 8;
#pragma unroll
                for (int ni2 = 0; ni2 < 2; ni2++) {
                    const int brow = ni2 * 16 + ((lane >> 4) & 1) * 8 + (lane & 7);
                    uint32_t r[4];
                    ldsm4(r, Ks + brow * 136 + bkc);
                    b[2*ni2    ][0] = r[0]; b[2*ni2    ][1] = r[1];
                    b[2*ni2 + 1][0] = r[2]; b[2*ni2 + 1][1] = r[3];
                }
            }
#pragma unroll
            for (int mi = 0; mi < 2; mi++)
#pragma unroll
                for (int ni = 0; ni < 4; ni++)
                    mma16(acc[mi][ni], a[mi], b[ni]);
        }
    }

    const int rr = lane >> 2, cc = (lane & 3) * 2;
    if (wrp == 0) {
#pragma unroll
        for (int mi = 0; mi < 2; mi++)
#pragma unroll
            for (int ni = 0; ni < 4; ni++) {
                buf[mi*16 + rr    ][ni*8 + cc]     = acc[mi][ni][0];
                buf[mi*16 + rr    ][ni*8 + cc + 1] = acc[mi][ni][1];
                buf[mi*16 + rr + 8][ni*8 + cc]     = acc[mi][ni][2];
                buf[mi*16 + rr + 8][ni*8 + cc + 1] = acc[mi][ni][3];
            }
    }
    __syncthreads();
    if (wrp == 1) {
#pragma unroll
        for (int mi = 0; mi < 2; mi++)
#pragma unroll
            for (int ni = 0; ni < 4; ni++) {
                buf[mi*16 + rr    ][ni*8 + cc]     += acc[mi][ni][0];
                buf[mi*16 + rr    ][ni*8 + cc + 1] += acc[mi][ni][1];
                buf[mi*16 + rr + 8][ni*8 + cc]     += acc[mi][ni][2];
                buf[mi*16 + rr + 8][ni*8 + cc + 1] += acc[mi][ni][3];
            }
    }
    __syncthreads();
    float* Cz = C + (long)z * 1024;
    for (int i = tid; i < 1024; i += 64)
        Cz[i] = buf[i >> 5][i & 31];
}

// ============================================================================
// softmax bodies + combined launch
// ============================================================================
__device__ __forceinline__ void rsm_body(
    const float* part, __half* Sh, int n, int splitk, float scale, int row,
    float* buf, float* red)
{
    const int b = row / n, r = row - b * n;
    const long base = ((long)b * splitk) * n * n + (long)r * n;
    const int tid = threadIdx.x;
    float m = -1e30f;
    for (int i = tid; i < n; i += 256) {
        float s = 0.f;
        for (int ks = 0; ks < splitk; ks++)
            s += part[base + (long)ks * n * n + i];
        s *= scale;
        buf[i] = s;
        m = fmaxf(m, s);
    }
    red[tid] = m; __syncthreads();
    for (int s = 128; s > 0; s >>= 1) { if (tid < s) red[tid] = fmaxf(red[tid], red[tid + s]); __syncthreads(); }
    m = red[0]; __syncthreads();
    float sum = 0.f;
    for (int i = tid; i < n; i += 256) { float e = expf(buf[i] - m); buf[i] = e; sum += e; }
    red[tid] = sum; __syncthreads();
    for (int s = 128; s > 0; s >>= 1) { if (tid < s) red[tid] += red[tid + s]; __syncthreads(); }
    float inv = 1.f / red[0];
    __half* ph = Sh + (long)row * n;
    for (int i = tid; i < n; i += 256) ph[i] = __float2half(buf[i] * inv);
}

__device__ __forceinline__ void softmaxh_body(__half* Sh, int n, int row,
                                              float* buf, float* red)
{
    __half* ph = Sh + (long)row * n;
    const int tid = threadIdx.x;
    float m = -1e30f;
    for (int i = tid; i < n; i += 256) { float v = __half2float(ph[i]); buf[i] = v; m = fmaxf(m, v); }
    red[tid] = m; __syncthreads();
    for (int s = 128; s > 0; s >>= 1) { if (tid < s) red[tid] = fmaxf(red[tid], red[tid + s]); __syncthreads(); }
    m = red[0]; __syncthreads();
    float sum = 0.f;
    for (int i = tid; i < n; i += 256) { float e = expf(buf[i] - m); buf[i] = e; sum += e; }
    red[tid] = sum; __syncthreads();
    for (int s = 128; s > 0; s >>= 1) { if (tid < s) red[tid] += red[tid + s]; __syncthreads(); }
    float inv = 1.f / red[0];
    for (int i = tid; i < n; i += 256) ph[i] = __float2half(buf[i] * inv);
}

// [0,64) rsm32 | [64,320) rsm16 | [320,1344) rsm8 | [1344,5440) softmax_h P4
__global__ void __launch_bounds__(256) smax_all_kernel(
    const float* __restrict__ part, __half* __restrict__ Sh)
{
    __shared__ float buf[2048];
    __shared__ float red[256];
    const int l = blockIdx.x;
    if (l < 64)        rsm_body(part + PART32, Sh + SH32, 32, 256, 1.0f / 256.0f, l, buf, red);
    else if (l < 320)  rsm_body(part + PART16, Sh + SH16, 128, 64, 1.0f / 128.0f, l - 64, buf, red);
    else if (l < 1344) rsm_body(part + PART8,  Sh + SH8,  512, 8,  1.0f / 64.0f,  l - 320, buf, red);
    else               softmaxh_body(Sh + SH4, 2048, l - 1344, buf, red);
}

// ===================== SIMT AV for P=32 (probs half, half V, half out) ============
__global__ void __launch_bounds__(256) gemm_av32_kernel(
    const __half* __restrict__ A, const __half* __restrict__ B, __half* __restrict__ out,
    int n, int d, int lp, int c0)
{
    const int z = blockIdx.z;
    A += (long)z * n * n;
    B += (long)z * n * d;
    const int m0 = blockIdx.y * 64, n0 = blockIdx.x * 64;
    __shared__ __align__(16) float As[16][68];
    __shared__ __align__(16) float Bs[16][64];
    const int tid = threadIdx.x;
    const int tx = tid & 15, ty = tid >> 4;
    float acc[4][4] = {};
    for (int k0 = 0; k0 < n; k0 += 16) {
#pragma unroll
        for (int it = 0; it < 4; it++) {
            int id = tid + it * 256;
            int m = id >> 4, kk = id & 15;
            As[kk][m] = (m0 + m < n) ? __half2float(A[(long)(m0 + m) * n + k0 + kk]) : 0.f;
        }
#pragma unroll
        for (int it = 0; it < 4; it++) {
            int id = tid + it * 256;
            int kk = id >> 6, nnn = id & 63;
            Bs[kk][nnn] = __half2float(B[(long)(k0 + kk) * d + n0 + nnn]);
        }
        __syncthreads();
#pragma unroll
        for (int kk = 0; kk < 16; kk++) {
            float4 a4 = *(const float4*)&As[kk][ty * 4];
            float4 b4 = *(const float4*)&Bs[kk][tx * 4];
            float ar[4] = {a4.x, a4.y, a4.z, a4.w};
            float br[4] = {b4.x, b4.y, b4.z, b4.w};
#pragma unroll
            for (int i = 0; i < 4; i++)
#pragma unroll
                for (int j = 0; j < 4; j++)
                    acc[i][j] += ar[i] * br[j];
        }
        __syncthreads();
    }
    const int lo = 6 - lp, o = 1 << lo, P = 1 << lp;
#pragma unroll
    for (int i = 0; i < 4; i++) {
        int m = m0 + ty * 4 + i;
        if (m >= n) continue;
        int t = m >> (2 * lo);
        int r = m & ((1 << (2 * lo)) - 1);
        int ohi = r >> lo, owi = r & (o - 1);
        int col = n0 + tx * 4;
        int cc = col >> (2 * lp);
        int rr = col & (P * P - 1);
        int pi = rr >> lp, pj = rr & (P - 1);
        long dst = ((long)((z * 8 + t) * 256 + c0 + cc) << 12)
                 + (((ohi << lp) + pi) << 6) + (owi << lp) + pj;
        *(__half2*)(out + dst)     = __floats2half2_rn(acc[i][0], acc[i][1]);
        *(__half2*)(out + dst + 2) = __floats2half2_rn(acc[i][2], acc[i][3]);
    }
}

// ===================== launcher ===================================================
extern "C" void kernel_launch(void* const* d_in, const int* in_sizes, int n_in,
                              void* d_out, int out_size)
{
    const float* xs  = (const float*)d_in[0];
    const float* Wq  = (const float*)d_in[2];
    const float* bq  = (const float*)d_in[3];
    const float* Wk  = (const float*)d_in[4];
    const float* bk  = (const float*)d_in[5];
    const float* Wv  = (const float*)d_in[6];
    const float* bv  = (const float*)d_in[7];
    const float* Wl  = (const float*)d_in[8];
    const float* bl  = (const float*)d_in[9];
    const float* Wf1 = (const float*)d_in[10];
    const float* bf1 = (const float*)d_in[11];
    const float* Wf2 = (const float*)d_in[12];
    const float* bf2 = (const float*)d_in[13];
    float* out = (float*)d_out;

    __half *gQp, *gKp, *gVp, *gXsh, *gAtth, *gXs1h, *gFfh, *gSh;
    __half *gWqkvh, *gWlh, *gWf1h, *gWf2h;
    float *gPart;
    cudaGetSymbolAddress((void**)&gQp,    g_Qp);
    cudaGetSymbolAddress((void**)&gKp,    g_Kp);
    cudaGetSymbolAddress((void**)&gVp,    g_Vp);
    cudaGetSymbolAddress((void**)&gSh,    g_Sh);
    cudaGetSymbolAddress((void**)&gPart,  g_part);
    cudaGetSymbolAddress((void**)&gXsh,   g_xsh);
    cudaGetSymbolAddress((void**)&gAtth,  g_atth);
    cudaGetSymbolAddress((void**)&gXs1h,  g_xs1h);
    cudaGetSymbolAddress((void**)&gFfh,   g_ffh);
    cudaGetSymbolAddress((void**)&gWqkvh, g_Wqkvh);
    cudaGetSymbolAddress((void**)&gWlh,   g_Wlh);
    cudaGetSymbolAddress((void**)&gWf1h,  g_Wf1h);
    cudaGetSymbolAddress((void**)&gWf2h,  g_Wf2h);

    cudaFuncSetAttribute(hconvK_kernel,
                         cudaFuncAttributeMaxDynamicSharedMemorySize, HK_SMEM);

    dim3 blk(256);
    dim3 qgrid(NIMG * 32, 2);

    // pre-convert inputs + weights
    f2h_kernel<<<16384, blk>>>(xs, gXsh);
    f2h3_kernel<<<192, blk>>>(Wq, Wk, Wv, gWqkvh);
    wtrans3_kernel<<<3 * 2304, blk>>>(Wl, Wf1, Wf2, gWlh, gWf1h, gWf2h);

    // fused QKV projection -> patchified half buffers (bias fused)
    hconv2_kernel<<<dim3(NIMG * 32, 6), blk>>>(gXsh, gWqkvh, bq, bk, bv, gQp, gKp, gVp);

    // attention, 3 wide phases (+ the P=32 specials)
    hgemm32_kernel<<<dim3(1, 1, 512), 64>>>(gQp, gKp, gPart + PART32, 65536, 256);
    scores_all_kernel<<<896, blk>>>(gQp, gKp, gPart, gSh);
    smax_all_kernel<<<5440, blk>>>(gPart, gSh);
    gemm_av32_kernel<<<dim3(1024, 1, 2), blk>>>(gSh + SH32, gVp, gAtth, 32, 65536, 5, 0);
    av_all_kernel<<<768, blk>>>(gSh, gVp, gAtth);

    // convs: tap-row-major K, strip shared across 3 chunks; half residual chain
    hconvK_kernel<<<qgrid, blk, HK_SMEM>>>(gAtth, gWlh,  bl,  xs,      nullptr, nullptr, gXs1h, 1, 1);
    hconvK_kernel<<<qgrid, blk, HK_SMEM>>>(gXs1h, gWf1h, bf1, nullptr, nullptr, nullptr, gFfh,  1, 0);
    hconvK_kernel<<<qgrid, blk, HK_SMEM>>>(gFfh,  gWf2h, bf2, nullptr, gXs1h,   out,     nullptr, 2, 1);
}

// round 17
// speedup vs baseline: 1.2155x; 1.0122x over previous
#include <cuda_runtime.h>
#include <cuda_fp16.h>
#include <math.h>
#include <stdint.h>

#define NIMG 16
#define CCH 256
#define NPIX 4096            // 64*64

// scratch region offsets (disjoint so all scales can run concurrently)
#define SOFF16 4194304L
#define SOFF8  8388608L
#define SOFF4  12582912L
#define PART32 0L
#define PART16 524288L
#define PART8  2621440L
#define SH4    0L
#define SH8    8388608L
#define SH16   8912896L
#define SH32   8945664L

// ---- scratch (static device globals; no allocation) ----
__device__ __half g_Qp[16777216];
__device__ __half g_Kp[16777216];
__device__ __half g_Vp[16777216];
__device__ __half g_Sh[8947712];
__device__ float  g_part[8388608];
__device__ __half g_xsh [NIMG*CCH*NPIX];
__device__ __half g_atth[NIMG*CCH*NPIX];
__device__ __half g_xs1h[NIMG*CCH*NPIX];
__device__ __half g_ffh [NIMG*CCH*NPIX];
__device__ __half g_Wqkvh[196608];
__device__ __half g_Wlh[589824], g_Wf1h[589824], g_Wf2h[589824];

// ============================================================================
// helpers
// ============================================================================
__device__ __forceinline__ void mma16(float* d, const uint32_t* a, const uint32_t* b) {
    asm volatile(
        "mma.sync.aligned.m16n8k16.row.col.f32.f16.f16.f32 "
        "{%0,%1,%2,%3}, {%4,%5,%6,%7}, {%8,%9}, {%0,%1,%2,%3};"
        : "+f"(d[0]), "+f"(d[1]), "+f"(d[2]), "+f"(d[3])
        : "r"(a[0]), "r"(a[1]), "r"(a[2]), "r"(a[3]), "r"(b[0]), "r"(b[1]));
}

__device__ __forceinline__ void ldsm4(uint32_t* r, const void* p) {
    uint32_t addr = (uint32_t)__cvta_generic_to_shared(p);
    asm volatile("ldmatrix.sync.aligned.m8n8.x4.shared.b16 {%0,%1,%2,%3}, [%4];"
        : "=r"(r[0]), "=r"(r[1]), "=r"(r[2]), "=r"(r[3]) : "r"(addr));
}

__device__ __forceinline__ void ldsm4t(uint32_t* r, const void* p) {
    uint32_t addr = (uint32_t)__cvta_generic_to_shared(p);
    asm volatile("ldmatrix.sync.aligned.m8n8.x4.trans.shared.b16 {%0,%1,%2,%3}, [%4];"
        : "=r"(r[0]), "=r"(r[1]), "=r"(r[2]), "=r"(r[3]) : "r"(addr));
}

__device__ __forceinline__ uint32_t pack_h2(float a, float b) {
    __half2 h = __floats2half2_rn(a, b);
    return *(uint32_t*)&h;
}

__device__ __forceinline__ void cpa16(uint32_t dst, const void* src, unsigned sz) {
    asm volatile("cp.async.ca.shared.global [%0], [%1], 16, %2;"
                 :: "r"(dst), "l"(src), "r"(sz) : "memory");
}
__device__ __forceinline__ void cpcommit() {
    asm volatile("cp.async.commit_group;" ::: "memory");
}
template <int N>
__device__ __forceinline__ void cpwait() {
    asm volatile("cp.async.wait_group %0;" :: "n"(N) : "memory");
}

// f32 -> f16 bulk convert
__global__ void f2h_kernel(const float* __restrict__ src, __half* __restrict__ dst) {
    long i = ((long)blockIdx.x * 256 + threadIdx.x) * 4;
    float4 v = *(const float4*)(src + i);
    *(uint32_t*)(dst + i)     = pack_h2(v.x, v.y);
    *(uint32_t*)(dst + i + 2) = pack_h2(v.z, v.w);
}

// batched f2h: QKV weights -> stacked [768][256]
__global__ void f2h3_kernel(const float* __restrict__ s0, const float* __restrict__ s1,
                            const float* __restrict__ s2, __half* __restrict__ d) {
    int z = blockIdx.x >> 6;
    const float* s = (z == 0) ? s0 : ((z == 1) ? s1 : s2);
    long i = ((long)(blockIdx.x & 63) * 256 + threadIdx.x) * 4;
    __half* dz = d + (long)z * 65536;
    float4 v = *(const float4*)(s + i);
    *(uint32_t*)(dz + i)     = pack_h2(v.x, v.y);
    *(uint32_t*)(dz + i + 2) = pack_h2(v.z, v.w);
}

// batched conv weight permute to tap-row-major
__global__ void wtrans3_kernel(const float* __restrict__ W0, const float* __restrict__ W1,
                               const float* __restrict__ W2,
                               __half* __restrict__ D0, __half* __restrict__ D1,
                               __half* __restrict__ D2) {
    int z = blockIdx.x / 2304;
    const float* W = (z == 0) ? W0 : ((z == 1) ? W1 : W2);
    __half* Wt2 = (z == 0) ? D0 : ((z == 1) ? D1 : D2);
    int idx = (blockIdx.x - z * 2304) * 256 + threadIdx.x;
    int oc = idx / 2304, r = idx - oc * 2304;
    int dy = r / 768;   int r2 = r - dy * 768;
    int cg = r2 / 192;  int r3 = r2 - cg * 192;
    int tx = r3 / 64;   int ci = r3 - tx * 64;
    Wt2[idx] = __float2half(W[oc * 2304 + (cg * 64 + ci) * 9 + dy * 3 + tx]);
}

// scatter index into patchified buffer: scale = oc>>6
__device__ __forceinline__ long pat_index(int img, int oc, int pix) {
    int s  = oc >> 6, cc = oc & 63;
    int lp = 5 - s;
    int lo = 1 + s;
    int Pm = (1 << lp) - 1;
    int y = pix >> 6, x = pix & 63;
    int ohi = y >> lp, pi = y & Pm, owi = x >> lp, pj = x & Pm;
    int t = img & 7, b = img >> 3;
    int nn = (t << (2*lo)) + (ohi << lo) + owi;
    int dd = (cc << (2*lp)) + (pi << lp) + pj;
    return (long)s * 4194304 + (long)b * 2097152 + (long)nn * (64 << (2*lp)) + dd;
}

// ============================================================================
// hconv2qkv: fused Q/K/V projection (stacked weights [768][256]), grid.y = 6
// ============================================================================
__global__ void __launch_bounds__(256, 2) hconv2_kernel(
    const __half* __restrict__ in, const __half* __restrict__ Wt,
    const float* __restrict__ bq, const float* __restrict__ bk, const float* __restrict__ bv,
    __half* __restrict__ Qp, __half* __restrict__ Kp, __half* __restrict__ Vp)
{
    __shared__ __half A2[2 * 128 * 40];
    __shared__ __half B2[2 * 32 * 136];

    const int tid = threadIdx.x;
    const int lane = tid & 31, wid = tid >> 5;
    const int wm = wid & 1, wn = wid >> 1;
    const int img = blockIdx.x >> 5;
    const int p0 = (blockIdx.x & 31) * 128;
    const int m0 = blockIdx.y * 128;
    const int proj = m0 >> 8;
    const __half* inimg = in + (long)img * CCH * NPIX;
    const float* bias = (proj == 0) ? bq : ((proj == 1) ? bk : bv);
    __half* outh_pat = (proj == 0) ? Qp : ((proj == 1) ? Kp : Vp);

    const uint32_t sA2 = (uint32_t)__cvta_generic_to_shared(A2);
    const uint32_t sB2 = (uint32_t)__cvta_generic_to_shared(B2);

#define ISSUE1(KCN, NB)                                                         \
    {                                                                           \
        const int k0n = (KCN) * 32;                                             \
        {                                                                       \
            int row = tid >> 1, seg = (tid & 1) * 16;                           \
            const __half* src = Wt + (long)(m0 + row) * 256 + k0n + seg;        \
            uint32_t dst = sA2 + (uint32_t)(((NB) * 5120 + row * 40 + seg) * 2);\
            cpa16(dst, src, 16u); cpa16(dst + 16, src + 8, 16u);                \
        }                                                                       \
        {                                                                       \
            int k = tid >> 3, u = tid & 7;                                      \
            const __half* src = inimg + ((long)(k0n + k) << 12) + p0 + u * 8;   \
            uint32_t dst = sB2 + (uint32_t)(((NB) * 4352 + k * 136 + u * 8) * 2); \
            cpa16(dst, src, 16u);                                               \
            cpa16(dst + 128, src + 64, 16u);                                    \
        }                                                                       \
        cpcommit();                                                             \
    }

    float acc[4][4][4] = {};
    ISSUE1(0, 0);

    for (int kc = 0; kc < 8; kc++) {
        cpwait<0>();
        __syncthreads();
        if (kc + 1 < 8) ISSUE1(kc + 1, (kc + 1) & 1);

        const __half* Ap = A2 + (kc & 1) * 5120;
        const __half* Bp = B2 + (kc & 1) * 4352;
#pragma unroll
        for (int kstep = 0; kstep < 2; kstep++) {
            uint32_t a[4][4], b[4][2];
            {
                const int arow = wm * 64 + ((lane >> 3) & 1) * 8 + (lane & 7);
                const int akc  = kstep * 16 + (lane >> 4) * 8;
#pragma unroll
                for (int mi = 0; mi < 4; mi++)
                    ldsm4(a[mi], Ap + (arow + mi * 16) * 40 + akc);
            }
            {
                const int brow = kstep * 16 + (lane & 7) + ((lane >> 3) & 1) * 8;
#pragma unroll
                for (int ni2 = 0; ni2 < 2; ni2++) {
                    const int bcol = wn * 32 + ni2 * 16 + ((lane >> 4) & 1) * 8;
                    uint32_t r[4];
                    ldsm4t(r, Bp + brow * 136 + bcol);
                    b[2*ni2    ][0] = r[0]; b[2*ni2    ][1] = r[1];
                    b[2*ni2 + 1][0] = r[2]; b[2*ni2 + 1][1] = r[3];
                }
            }
#pragma unroll
            for (int mi = 0; mi < 4; mi++)
#pragma unroll
                for (int ni = 0; ni < 4; ni++)
                    mma16(acc[mi][ni], a[mi], b[ni]);
        }
    }
#undef ISSUE1

    const int orow = (m0 & 255) + wm * 64 + (lane >> 2);
    const int ocol = p0 + wn * 32 + (lane & 3) * 2;
#pragma unroll
    for (int mi = 0; mi < 4; mi++) {
        const int oca = orow + mi * 16, ocb = oca + 8;
        const float ba = bias[oca], bb = bias[ocb];
#pragma unroll
        for (int ni = 0; ni < 4; ni++) {
            const int n = ocol + ni * 8;
            long ia = pat_index(img, oca, n);
            long ib = pat_index(img, ocb, n);
            *(__half2*)(outh_pat + ia) = __floats2half2_rn(acc[mi][ni][0] + ba, acc[mi][ni][1] + ba);
            *(__half2*)(outh_pat + ib) = __floats2half2_rn(acc[mi][ni][2] + bb, acc[mi][ni][3] + bb);
        }
    }
}

// ============================================================================
// hconvK: 3x3 conv, tap-ROW-major K (strip shared by 3 chunks), 256 threads
//   center-tap chunks (kc%3==1, dxd==0) skip the B-build and ldsm directly
//   from the strip (identical data, halo zeros = out-of-image zeros).
// ============================================================================
#define HK_A2    0
#define HK_BS    18432
#define HK_STRIP (18432 + 8704)
#define HK_SMEM  ((18432 + 8704 + 10240) * 2)

__global__ void __launch_bounds__(256, 2) hconvK_kernel(
    const __half* __restrict__ in, const __half* __restrict__ Wt,
    const float* __restrict__ bias, const float* __restrict__ res,
    const __half* __restrict__ resh,
    float* __restrict__ out, __half* __restrict__ outh_img,
    int dil, int addres)
{
    extern __shared__ __half sh[];
    __half* A2    = sh + HK_A2;
    __half* Bs    = sh + HK_BS;
    __half* Strip = sh + HK_STRIP;

    const int tid = threadIdx.x;
    const int lane = tid & 31, wid = tid >> 5;
    const int wm = wid & 1, wn = wid >> 1;
    const int img = blockIdx.x >> 5;
    const int p0 = (blockIdx.x & 31) * 128;
    const int y0 = p0 >> 6;
    const int m0 = blockIdx.y * 128;
    const __half* inimg = in + (long)img * CCH * NPIX;

    const uint32_t sA2    = (uint32_t)__cvta_generic_to_shared(A2);
    const uint32_t sStrip = (uint32_t)__cvta_generic_to_shared(Strip);

    {
        int c = tid >> 2, u = tid & 3, r = u >> 1, side = u & 1;
        *(uint4*)(Strip + c * 160 + r * 80 + side * 72) = make_uint4(0, 0, 0, 0);
    }

#define ISSUE_A(KCN, NB)                                                         \
    {                                                                            \
        int row = tid >> 1, seg = (tid & 1) * 32;                                \
        const __half* src = Wt + (long)(m0 + row) * 2304 + (KCN) * 64 + seg;     \
        uint32_t dst = sA2 + (uint32_t)(((NB) * 9216 + row * 72 + seg) * 2);     \
        cpa16(dst,      src,      16u);                                          \
        cpa16(dst + 16, src + 8,  16u);                                          \
        cpa16(dst + 32, src + 16, 16u);                                          \
        cpa16(dst + 48, src + 24, 16u);                                          \
    }

#define ISSUE_S(KCN)                                                             \
    {                                                                            \
        int dyg = (KCN) / 12;                                                    \
        int c0v = (((KCN) % 12) / 3) * 64;                                       \
        int dyd = (dyg - 1) * dil;                                               \
        int c = tid >> 2, u = tid & 3;                                           \
        int r = u >> 1, s = u & 1;                                               \
        int gy = y0 + r + dyd;                                                   \
        unsigned ok = ((unsigned)gy < 64u) ? 16u : 0u;                           \
        int gyc = gy < 0 ? 0 : (gy > 63 ? 63 : gy);                              \
        const __half* src = inimg + ((long)(c0v + c) << 12) + (gyc << 6) + s * 32; \
        uint32_t dst = sStrip + (uint32_t)((c * 160 + r * 80 + 8 + s * 32) * 2); \
        cpa16(dst,      src,      ok);                                           \
        cpa16(dst + 16, src + 8,  ok);                                           \
        cpa16(dst + 32, src + 16, ok);                                           \
        cpa16(dst + 48, src + 24, ok);                                           \
    }

    float acc[4][4][4] = {};
    ISSUE_A(0, 0);
    ISSUE_S(0);
    cpcommit();

    for (int kc = 0; kc < 36; kc++) {
        cpwait<0>();
        __syncthreads();

        const bool direct = ((kc % 3) == 1);   // dxd == 0: read strip directly
        if (!direct) {
            const int dxd = (kc % 3 - 1) * dil;
            const int c = tid >> 2, u = tid & 3, prow = u >> 1, xseg = (u & 1) * 32;
            const uint32_t* rowp = (const uint32_t*)(Strip + c * 160 + prow * 80);
            const int h0 = 8 + dxd + xseg;
            uint32_t w[16];
            if (dxd & 1) {
                int k0 = (h0 - 1) >> 1;
                uint32_t prev = rowp[k0];
#pragma unroll
                for (int j = 0; j < 16; j++) {
                    uint32_t nxt = rowp[k0 + 1 + j];
                    w[j] = __funnelshift_r(prev, nxt, 16);
                    prev = nxt;
                }
            } else {
                int k0 = h0 >> 1;
#pragma unroll
                for (int j = 0; j < 16; j++) w[j] = rowp[k0 + j];
            }
            uint4* bd = (uint4*)(Bs + c * 136 + prow * 64 + xseg);
#pragma unroll
            for (int j = 0; j < 4; j++)
                bd[j] = make_uint4(w[4*j], w[4*j+1], w[4*j+2], w[4*j+3]);
            __syncthreads();
        }

        if (kc + 1 < 36) {
            ISSUE_A(kc + 1, (kc + 1) & 1);
            if ((kc + 1) % 3 == 0) ISSUE_S(kc + 1);
            cpcommit();
        }

        const __half* Ap = A2 + (kc & 1) * 9216;
#pragma unroll
        for (int kstep = 0; kstep < 4; kstep++) {
            uint32_t a[4][4], b[4][2];
            {
                const int arow = wm * 64 + ((lane >> 3) & 1) * 8 + (lane & 7);
                const int akc  = kstep * 16 + (lane >> 4) * 8;
#pragma unroll
                for (int mi = 0; mi < 4; mi++)
                    ldsm4(a[mi], Ap + (arow + mi * 16) * 72 + akc);
            }
            {
                const int brow = kstep * 16 + (lane & 7) + ((lane >> 3) & 1) * 8;
#pragma unroll
                for (int ni2 = 0; ni2 < 2; ni2++) {
                    const int bcol = wn * 32 + ni2 * 16 + ((lane >> 4) & 1) * 8;
                    uint32_t r[4];
                    if (direct)
                        ldsm4t(r, Strip + brow * 160 + (bcol >> 6) * 80 + 8 + (bcol & 63));
                    else
                        ldsm4t(r, Bs + brow * 136 + bcol);
                    b[2*ni2    ][0] = r[0]; b[2*ni2    ][1] = r[1];
                    b[2*ni2 + 1][0] = r[2]; b[2*ni2 + 1][1] = r[3];
                }
            }
#pragma unroll
            for (int mi = 0; mi < 4; mi++)
#pragma unroll
                for (int ni = 0; ni < 4; ni++)
                    mma16(acc[mi][ni], a[mi], b[ni]);
        }
    }
#undef ISSUE_A
#undef ISSUE_S

    const int orow = m0 + wm * 64 + (lane >> 2);
    const int ocol = p0 + wn * 32 + (lane & 3) * 2;
#pragma unroll
    for (int mi = 0; mi < 4; mi++) {
        const int oca = orow + mi * 16;
        const int ocb = oca + 8;
        const float ba = bias[oca], bb = bias[ocb];
#pragma unroll
        for (int ni = 0; ni < 4; ni++) {
            const int n = ocol + ni * 8;
            long ia = ((long)img * 256 + oca) * NPIX + n;
            long ib = ((long)img * 256 + ocb) * NPIX + n;
            float v0 = acc[mi][ni][0] + ba, v1 = acc[mi][ni][1] + ba;
            float v2 = acc[mi][ni][2] + bb, v3 = acc[mi][ni][3] + bb;
            v0 = (v0 > 0.f) ? v0 : 0.2f * v0;
            v1 = (v1 > 0.f) ? v1 : 0.2f * v1;
            v2 = (v2 > 0.f) ? v2 : 0.2f * v2;
            v3 = (v3 > 0.f) ? v3 : 0.2f * v3;
            if (addres) {
                if (resh) {
                    __half2 ra = *(const __half2*)(resh + ia);
                    __half2 rb = *(const __half2*)(resh + ib);
                    float2 fa = __half22float2(ra), fb = __half22float2(rb);
                    v0 += fa.x; v1 += fa.y; v2 += fb.x; v3 += fb.y;
                } else {
                    v0 += res[ia]; v1 += res[ia + 1];
                    v2 += res[ib]; v3 += res[ib + 1];
                }
            }
            if (out) {
                out[ia] = v0; out[ia + 1] = v1;
                out[ib] = v2; out[ib + 1] = v3;
            }
            if (outh_img) {
                *(__half2*)(outh_img + ia) = __floats2half2_rn(v0, v1);
                *(__half2*)(outh_img + ib) = __floats2half2_rn(v2, v3);
            }
        }
    }
}

// ============================================================================
// nt_body: fp16 NT GEMM body (scores), cp.async double-buffered
// ============================================================================
__device__ __forceinline__ void nt_body(
    const __half* A, const __half* B, float* C, __half* Ch, float emitScale,
    int N, int K, int splitk, long sAB, long sC,
    int bxx, int byy, int bzz, __half* As, __half* Bs)
{
    const int tid = threadIdx.x;
    const int lane = tid & 31, wid = tid >> 5;
    const int wm = wid & 1, wn = wid >> 1;
    const int n0 = bxx * 128, m0 = byy * 128;
    const int z = bzz, bat = z / splitk, ks = z - bat * splitk;
    A += (long)bat * sAB;
    B += (long)bat * sAB;
    const int kchunk = K / splitk, kbeg = ks * kchunk;
    const int nch = kchunk / 32;
    const int wr = tid >> 1, wkh = (tid & 1) * 16;

    const uint32_t sAs = (uint32_t)__cvta_generic_to_shared(As);
    const uint32_t sBs = (uint32_t)__cvta_generic_to_shared(Bs);

#define ISSUE_NT(K0v, NB)                                                       \
    {                                                                           \
        const __half* sa = A + (long)(m0 + wr) * K + (K0v) + wkh;               \
        const __half* sb = B + (long)(n0 + wr) * K + (K0v) + wkh;               \
        uint32_t da = sAs + (uint32_t)(((NB) * 5120 + wr * 40 + wkh) * 2);      \
        uint32_t db = sBs + (uint32_t)(((NB) * 5120 + wr * 40 + wkh) * 2);      \
        cpa16(da, sa, 16u); cpa16(da + 16, sa + 8, 16u);                        \
        cpa16(db, sb, 16u); cpa16(db + 16, sb + 8, 16u);                        \
        cpcommit();                                                             \
    }

    float acc[4][4][4] = {};
    ISSUE_NT(kbeg, 0);

    for (int i = 0; i < nch; i++) {
        cpwait<0>();
        __syncthreads();
        if (i + 1 < nch) ISSUE_NT(kbeg + (i + 1) * 32, (i + 1) & 1);

        const __half* Ap = As + (i & 1) * 5120;
        const __half* Bp = Bs + (i & 1) * 5120;
#pragma unroll
        for (int kstep = 0; kstep < 2; kstep++) {
            uint32_t a[4][4], b[4][2];
            {
                const int arow = wm * 64 + ((lane >> 3) & 1) * 8 + (lane & 7);
                const int akc  = kstep * 16 + (lane >> 4) * 8;
#pragma unroll
                for (int mi = 0; mi < 4; mi++)
                    ldsm4(a[mi], Ap + (arow + mi * 16) * 40 + akc);
            }
            {
                const int bkc = kstep * 16 + ((lane >> 3) & 1) * 8;
#pragma unroll
                for (int ni2 = 0; ni2 < 2; ni2++) {
                    const int brow = wn * 32 + ni2 * 16 + ((lane >> 4) & 1) * 8 + (lane & 7);
                    uint32_t r[4];
                    ldsm4(r, Bp + brow * 40 + bkc);
                    b[2*ni2    ][0] = r[0]; b[2*ni2    ][1] = r[1];
                    b[2*ni2 + 1][0] = r[2]; b[2*ni2 + 1][1] = r[3];
                }
            }
#pragma unroll
            for (int mi = 0; mi < 4; mi++)
#pragma unroll
                for (int ni = 0; ni < 4; ni++)
                    mma16(acc[mi][ni], a[mi], b[ni]);
        }
    }
#undef ISSUE_NT

    const int orow = m0 + wm * 64 + (lane >> 2);
    const int ocol = n0 + wn * 32 + (lane & 3) * 2;
    if (Ch) {
        Ch += (long)z * sC;
#pragma unroll
        for (int mi = 0; mi < 4; mi++) {
            long ra = (long)(orow + mi * 16) * N;
            long rb = (long)(orow + mi * 16 + 8) * N;
#pragma unroll
            for (int ni = 0; ni < 4; ni++) {
                int n = ocol + ni * 8;
                *(__half2*)(Ch + ra + n) = __floats2half2_rn(acc[mi][ni][0] * emitScale,
                                                             acc[mi][ni][1] * emitScale);
                *(__half2*)(Ch + rb + n) = __floats2half2_rn(acc[mi][ni][2] * emitScale,
                                                             acc[mi][ni][3] * emitScale);
            }
        }
    } else {
        C += (long)z * sC;
#pragma unroll
        for (int mi = 0; mi < 4; mi++) {
            long ra = (long)(orow + mi * 16) * N;
            long rb = (long)(orow + mi * 16 + 8) * N;
#pragma unroll
            for (int ni = 0; ni < 4; ni++) {
                int n = ocol + ni * 8;
                C[ra + n] = acc[mi][ni][0]; C[ra + n + 1] = acc[mi][ni][1];
                C[rb + n] = acc[mi][ni][2]; C[rb + n + 1] = acc[mi][ni][3];
            }
        }
    }
}

// combined scores launch: [0,128) P16 | [128,384) P8 | [384,896) P4
__global__ void __launch_bounds__(256) scores_all_kernel(
    const __half* __restrict__ Qp, const __half* __restrict__ Kp,
    float* __restrict__ part, __half* __restrict__ Sh)
{
    __shared__ __half As[2 * 128 * 40];
    __shared__ __half Bs[2 * 128 * 40];
    const int l = blockIdx.x;
    if (l < 128) {
        nt_body(Qp + SOFF16, Kp + SOFF16, part + PART16, nullptr, 1.0f,
                128, 16384, 64, 128L * 16384, 128L * 128, 0, 0, l, As, Bs);
    } else if (l < 384) {
        const int t = l - 128;
        nt_body(Qp + SOFF8, Kp + SOFF8, part + PART8, nullptr, 1.0f,
                512, 4096, 8, 512L * 4096, 512L * 512,
                t & 3, (t >> 2) & 3, t >> 4, As, Bs);
    } else {
        const int t = l - 384;
        nt_body(Qp + SOFF4, Kp + SOFF4, nullptr, Sh + SH4, 1.0f / 32.0f,
                2048, 1024, 1, 2048L * 1024, 2048L * 2048,
                t & 15, (t >> 4) & 15, t >> 8, As, Bs);
    }
}

// ============================================================================
// av_body: fp16 AV GEMM body (half probs), cp.async double-buffered
// ============================================================================
__device__ __forceinline__ void av_body(
    const __half* S, const __half* V, __half* out,
    int n, int d, int lp, int c0,
    int bxx, int byy, int bzz, __half* As, __half* Bs)
{
    const int tid = threadIdx.x;
    const int lane = tid & 31, wid = tid >> 5;
    const int wm = wid & 1, wn = wid >> 1;
    const int z = bzz;
    S += (long)z * n * n;
    V += (long)z * n * d;
    const int n0 = bxx * 128;
    const int m0 = byy * 128;
    const int wr = tid >> 1, wkh = (tid & 1) * 16;
    const int bk = tid >> 3, bn0 = (tid & 7) * 16;
    const int nch = n / 32;

    const uint32_t sAs = (uint32_t)__cvta_generic_to_shared(As);
    const uint32_t sBs = (uint32_t)__cvta_generic_to_shared(Bs);

#define ISSUE_AV(K0v, NB)                                                       \
    {                                                                           \
        const __half* sa = S + (long)(m0 + wr) * n + (K0v) + wkh;               \
        uint32_t da = sAs + (uint32_t)(((NB) * 5120 + wr * 40 + wkh) * 2);      \
        cpa16(da, sa, 16u); cpa16(da + 16, sa + 8, 16u);                        \
        const __half* sb = V + (long)((K0v) + bk) * d + n0 + bn0;               \
        uint32_t db = sBs + (uint32_t)(((NB) * 4352 + bk * 136 + bn0) * 2);     \
        cpa16(db, sb, 16u); cpa16(db + 16, sb + 8, 16u);                        \
        cpcommit();                                                             \
    }

    float acc[4][4][4] = {};
    ISSUE_AV(0, 0);

    for (int i = 0; i < nch; i++) {
        cpwait<0>();
        __syncthreads();
        if (i + 1 < nch) ISSUE_AV((i + 1) * 32, (i + 1) & 1);

        const __half* Ap = As + (i & 1) * 5120;
        const __half* Bp = Bs + (i & 1) * 4352;
#pragma unroll
        for (int kstep = 0; kstep < 2; kstep++) {
            uint32_t a[4][4], b[4][2];
            {
                const int arow = wm * 64 + ((lane >> 3) & 1) * 8 + (lane & 7);
                const int akc  = kstep * 16 + (lane >> 4) * 8;
#pragma unroll
                for (int mi = 0; mi < 4; mi++)
                    ldsm4(a[mi], Ap + (arow + mi * 16) * 40 + akc);
            }
            {
                const int brow = kstep * 16 + (lane & 7) + ((lane >> 3) & 1) * 8;
#pragma unroll
                for (int ni2 = 0; ni2 < 2; ni2++) {
                    const int bcol = wn * 32 + ni2 * 16 + ((lane >> 4) & 1) * 8;
                    uint32_t r[4];
                    ldsm4t(r, Bp + brow * 136 + bcol);
                    b[2*ni2    ][0] = r[0]; b[2*ni2    ][1] = r[1];
                    b[2*ni2 + 1][0] = r[2]; b[2*ni2 + 1][1] = r[3];
                }
            }
#pragma unroll
            for (int mi = 0; mi < 4; mi++)
#pragma unroll
                for (int ni = 0; ni < 4; ni++)
                    mma16(acc[mi][ni], a[mi], b[ni]);
        }
    }
#undef ISSUE_AV

    const int lo = 6 - lp;
    const int orow = m0 + wm * 64 + (lane >> 2);
    const int ocol = n0 + wn * 32 + (lane & 3) * 2;
#pragma unroll
    for (int mi = 0; mi < 4; mi++) {
#pragma unroll
        for (int hf = 0; hf < 2; hf++) {
            const int m = orow + mi * 16 + hf * 8;
            const int t = m >> (2 * lo);
            const int r = m & ((1 << (2 * lo)) - 1);
            const int ohi = r >> lo, owi = r & ((1 << lo) - 1);
#pragma unroll
            for (int ni = 0; ni < 4; ni++) {
                const int col = ocol + ni * 8;
                const int cc = col >> (2 * lp);
                const int rr = col & ((1 << (2 * lp)) - 1);
                const int pi = rr >> lp, pj = rr & ((1 << lp) - 1);
                long dst = ((long)((z * 8 + t) * 256 + c0 + cc) << 12)
                         + (((ohi << lp) + pi) << 6) + (owi << lp) + pj;
                *(__half2*)(out + dst) = __floats2half2_rn(acc[mi][ni][hf*2], acc[mi][ni][hf*2 + 1]);
            }
        }
    }
}

// combined AV launch: [0,256) P16 | [256,512) P8 | [512,768) P4
__global__ void __launch_bounds__(256) av_all_kernel(
    const __half* __restrict__ Sh, const __half* __restrict__ Vp,
    __half* __restrict__ atth)
{
    __shared__ __half As[2 * 128 * 40];
    __shared__ __half Bs[2 * 32 * 136];
    const int l = blockIdx.x;
    if (l < 256) {
        av_body(Sh + SH16, Vp + SOFF16, atth, 128, 16384, 4, 64,
                l & 127, 0, l >> 7, As, Bs);
    } else if (l < 512) {
        const int t = l - 256;
        av_body(Sh + SH8, Vp + SOFF8, atth, 512, 4096, 3, 128,
                t & 31, (t >> 5) & 3, t >> 7, As, Bs);
    } else {
        const int t = l - 512;
        av_body(Sh + SH4, Vp + SOFF4, atth, 2048, 1024, 2, 192,
                t & 7, (t >> 3) & 15, t >> 7, As, Bs);
    }
}

// ============================================================================
// fp16 mma 32x32 NT split-K (P=32 scores): 2 warps, cross-warp smem reduce
// ============================================================================
__global__ void __launch_bounds__(64) hgemm32_kernel(
    const __half* __restrict__ A, const __half* __restrict__ B, float* __restrict__ C,
    int K, int splitk)
{
    __shared__ __half Qs[32 * 136];
    __shared__ __half Ks[32 * 136];
    __shared__ float buf[32][33];
    const int tid = threadIdx.x;
    const int lane = tid & 31, wrp = tid >> 5;
    const int z = blockIdx.z, bat = z / splitk, ks = z - bat * splitk;
    A += (long)bat * 32 * K;
    B += (long)bat * 32 * K;
    const int kchunk = K / splitk, kbeg = ks * kchunk;

    float acc[2][4][4] = {};
    for (int k0 = kbeg; k0 < kbeg + kchunk; k0 += 128) {
        __syncthreads();
#pragma unroll
        for (int i = 0; i < 8; i++) {
            int u = i * 64 + tid;
            int row = u >> 4, seg = (u & 15) * 8;
            *(uint4*)(Qs + row * 136 + seg) = *(const uint4*)(A + (long)row * K + k0 + seg);
            *(uint4*)(Ks + row * 136 + seg) = *(const uint4*)(B + (long)row * K + k0 + seg);
        }
        __syncthreads();
        for (int s = wrp; s < 8; s += 2) {
            const int kc = s * 16;
            uint32_t a[2][4], b[4][2];
            {
                const int arow = ((lane >> 3) & 1) * 8 + (lane & 7);
                const int akc  = kc + (lane >> 4) * 8;
                ldsm4(a[0], Qs + arow * 136 + akc);
                ldsm4(a[1], Qs + (arow + 16) * 136 + akc);
            }
            {
                const int bkc = kc + ((lane >> 3) & 1) * 8;
#pragma unroll
                for (int ni2 = 0; ni2 < 2; ni2++) {
                    const int brow = ni2 * 16 + ((lane >> 4) & 1) * 8 + (lane & 7);
                    uint32_t r[4];
                    ldsm4(r, Ks + brow * 136 + bkc);
                    b[2*ni2    ][0] = r[0]; b[2*ni2    ][1] = r[1];
                    b[2*ni2 + 1][0] = r[2]; b[2*ni2 + 1][1] = r[3];
                }
            }
#pragma unroll
            for (int mi = 0; mi < 2; mi++)
#pragma unroll
                for (int ni = 0; ni < 4; ni++)
                    mma16(acc[mi][ni], a[mi], b[ni]);
        }
    }

    const int rr = lane >> 2, cc = (lane & 3) * 2;
    if (wrp == 0) {
#pragma unroll
        for (int mi = 0; mi < 2; mi++)
#pragma unroll
            for (int ni = 0; ni < 4; ni++) {
                buf[mi*16 + rr    ][ni*8 + cc]     = acc[mi][ni][0];
                buf[mi*16 + rr    ][ni*8 + cc + 1] = acc[mi][ni][1];
                buf[mi*16 + rr + 8][ni*8 + cc]     = acc[mi][ni][2];
                buf[mi*16 + rr + 8][ni*8 + cc + 1] = acc[mi][ni][3];
            }
    }
    __syncthreads();
    if (wrp == 1) {
#pragma unroll
        for (int mi = 0; mi < 2; mi++)
#pragma unroll
            for (int ni = 0; ni < 4; ni++) {
                buf[mi*16 + rr    ][ni*8 + cc]     += acc[mi][ni][0];
                buf[mi*16 + rr    ][ni*8 + cc + 1] += acc[mi][ni][1];
                buf[mi*16 + rr + 8][ni*8 + cc]     += acc[mi][ni][2];
                buf[mi*16 + rr + 8][ni*8 + cc + 1] += acc[mi][ni][3];
            }
    }
    __syncthreads();
    float* Cz = C + (long)z * 1024;
    for (int i = tid; i < 1024; i += 64)
        Cz[i] = buf[i >> 5][i & 31];
}

// ============================================================================
// softmax bodies + combined launch
// ============================================================================
__device__ __forceinline__ void rsm_body(
    const float* part, __half* Sh, int n, int splitk, float scale, int row,
    float* buf, float* red)
{
    const int b = row / n, r = row - b * n;
    const long base = ((long)b * splitk) * n * n + (long)r * n;
    const int tid = threadIdx.x;
    float m = -1e30f;
    for (int i = tid; i < n; i += 256) {
        float s = 0.f;
        for (int ks = 0; ks < splitk; ks++)
            s += part[base + (long)ks * n * n + i];
        s *= scale;
        buf[i] = s;
        m = fmaxf(m, s);
    }
    red[tid] = m; __syncthreads();
    for (int s = 128; s > 0; s >>= 1) { if (tid < s) red[tid] = fmaxf(red[tid], red[tid + s]); __syncthreads(); }
    m = red[0]; __syncthreads();
    float sum = 0.f;
    for (int i = tid; i < n; i += 256) { float e = expf(buf[i] - m); buf[i] = e; sum += e; }
    red[tid] = sum; __syncthreads();
    for (int s = 128; s > 0; s >>= 1) { if (tid < s) red[tid] += red[tid + s]; __syncthreads(); }
    float inv = 1.f / red[0];
    __half* ph = Sh + (long)row * n;
    for (int i = tid; i < n; i += 256) ph[i] = __float2half(buf[i] * inv);
}

__device__ __forceinline__ void softmaxh_body(__half* Sh, int n, int row,
                                              float* buf, float* red)
{
    __half* ph = Sh + (long)row * n;
    const int tid = threadIdx.x;
    float m = -1e30f;
    for (int i = tid; i < n; i += 256) { float v = __half2float(ph[i]); buf[i] = v; m = fmaxf(m, v); }
    red[tid] = m; __syncthreads();
    for (int s = 128; s > 0; s >>= 1) { if (tid < s) red[tid] = fmaxf(red[tid], red[tid + s]); __syncthreads(); }
    m = red[0]; __syncthreads();
    float sum = 0.f;
    for (int i = tid; i < n; i += 256) { float e = expf(buf[i] - m); buf[i] = e; sum += e; }
    red[tid] = sum; __syncthreads();
    for (int s = 128; s > 0; s >>= 1) { if (tid < s) red[tid] += red[tid + s]; __syncthreads(); }
    float inv = 1.f / red[0];
    for (int i = tid; i < n; i += 256) ph[i] = __float2half(buf[i] * inv);
}

// [0,64) rsm32 | [64,320) rsm16 | [320,1344) rsm8 | [1344,5440) softmax_h P4
__global__ void __launch_bounds__(256) smax_all_kernel(
    const float* __restrict__ part, __half* __restrict__ Sh)
{
    __shared__ float buf[2048];
    __shared__ float red[256];
    const int l = blockIdx.x;
    if (l < 64)        rsm_body(part + PART32, Sh + SH32, 32, 256, 1.0f / 256.0f, l, buf, red);
    else if (l < 320)  rsm_body(part + PART16, Sh + SH16, 128, 64, 1.0f / 128.0f, l - 64, buf, red);
    else if (l < 1344) rsm_body(part + PART8,  Sh + SH8,  512, 8,  1.0f / 64.0f,  l - 320, buf, red);
    else               softmaxh_body(Sh + SH4, 2048, l - 1344, buf, red);
}

// ===================== SIMT AV for P=32 (probs half, half V, half out) ============
__global__ void __launch_bounds__(256) gemm_av32_kernel(
    const __half* __restrict__ A, const __half* __restrict__ B, __half* __restrict__ out,
    int n, int d, int lp, int c0)
{
    const int z = blockIdx.z;
    A += (long)z * n * n;
    B += (long)z * n * d;
    const int m0 = blockIdx.y * 64, n0 = blockIdx.x * 64;
    __shared__ __align__(16) float As[16][68];
    __shared__ __align__(16) float Bs[16][64];
    const int tid = threadIdx.x;
    const int tx = tid & 15, ty = tid >> 4;
    float acc[4][4] = {};
    for (int k0 = 0; k0 < n; k0 += 16) {
#pragma unroll
        for (int it = 0; it < 4; it++) {
            int id = tid + it * 256;
            int m = id >> 4, kk = id & 15;
            As[kk][m] = (m0 + m < n) ? __half2float(A[(long)(m0 + m) * n + k0 + kk]) : 0.f;
        }
#pragma unroll
        for (int it = 0; it < 4; it++) {
            int id = tid + it * 256;
            int kk = id >> 6, nnn = id & 63;
            Bs[kk][nnn] = __half2float(B[(long)(k0 + kk) * d + n0 + nnn]);
        }
        __syncthreads();
#pragma unroll
        for (int kk = 0; kk < 16; kk++) {
            float4 a4 = *(const float4*)&As[kk][ty * 4];
            float4 b4 = *(const float4*)&Bs[kk][tx * 4];
            float ar[4] = {a4.x, a4.y, a4.z, a4.w};
            float br[4] = {b4.x, b4.y, b4.z, b4.w};
#pragma unroll
            for (int i = 0; i < 4; i++)
#pragma unroll
                for (int j = 0; j < 4; j++)
                    acc[i][j] += ar[i] * br[j];
        }
        __syncthreads();
    }
    const int lo = 6 - lp, o = 1 << lo, P = 1 << lp;
#pragma unroll
    for (int i = 0; i < 4; i++) {
        int m = m0 + ty * 4 + i;
        if (m >= n) continue;
        int t = m >> (2 * lo);
        int r = m & ((1 << (2 * lo)) - 1);
        int ohi = r >> lo, owi = r & (o - 1);
        int col = n0 + tx * 4;
        int cc = col >> (2 * lp);
        int rr = col & (P * P - 1);
        int pi = rr >> lp, pj = rr & (P - 1);
        long dst = ((long)((z * 8 + t) * 256 + c0 + cc) << 12)
                 + (((ohi << lp) + pi) << 6) + (owi << lp) + pj;
        *(__half2*)(out + dst)     = __floats2half2_rn(acc[i][0], acc[i][1]);
        *(__half2*)(out + dst + 2) = __floats2half2_rn(acc[i][2], acc[i][3]);
    }
}

// ===================== launcher ===================================================
extern "C" void kernel_launch(void* const* d_in, const int* in_sizes, int n_in,
                              void* d_out, int out_size)
{
    const float* xs  = (const float*)d_in[0];
    const float* Wq  = (const float*)d_in[2];
    const float* bq  = (const float*)d_in[3];
    const float* Wk  = (const float*)d_in[4];
    const float* bk  = (const float*)d_in[5];
    const float* Wv  = (const float*)d_in[6];
    const float* bv  = (const float*)d_in[7];
    const float* Wl  = (const float*)d_in[8];
    const float* bl  = (const float*)d_in[9];
    const float* Wf1 = (const float*)d_in[10];
    const float* bf1 = (const float*)d_in[11];
    const float* Wf2 = (const float*)d_in[12];
    const float* bf2 = (const float*)d_in[13];
    float* out = (float*)d_out;

    __half *gQp, *gKp, *gVp, *gXsh, *gAtth, *gXs1h, *gFfh, *gSh;
    __half *gWqkvh, *gWlh, *gWf1h, *gWf2h;
    float *gPart;
    cudaGetSymbolAddress((void**)&gQp,    g_Qp);
    cudaGetSymbolAddress((void**)&gKp,    g_Kp);
    cudaGetSymbolAddress((void**)&gVp,    g_Vp);
    cudaGetSymbolAddress((void**)&gSh,    g_Sh);
    cudaGetSymbolAddress((void**)&gPart,  g_part);
    cudaGetSymbolAddress((void**)&gXsh,   g_xsh);
    cudaGetSymbolAddress((void**)&gAtth,  g_atth);
    cudaGetSymbolAddress((void**)&gXs1h,  g_xs1h);
    cudaGetSymbolAddress((void**)&gFfh,   g_ffh);
    cudaGetSymbolAddress((void**)&gWqkvh, g_Wqkvh);
    cudaGetSymbolAddress((void**)&gWlh,   g_Wlh);
    cudaGetSymbolAddress((void**)&gWf1h,  g_Wf1h);
    cudaGetSymbolAddress((void**)&gWf2h,  g_Wf2h);

    cudaFuncSetAttribute(hconvK_kernel,
                         cudaFuncAttributeMaxDynamicSharedMemorySize, HK_SMEM);

    dim3 blk(256);
    dim3 qgrid(NIMG * 32, 2);

    // pre-convert inputs + weights
    f2h_kernel<<<16384, blk>>>(xs, gXsh);
    f2h3_kernel<<<192, blk>>>(Wq, Wk, Wv, gWqkvh);
    wtrans3_kernel<<<3 * 2304, blk>>>(Wl, Wf1, Wf2, gWlh, gWf1h, gWf2h);

    // fused QKV projection -> patchified half buffers (bias fused)
    hconv2_kernel<<<dim3(NIMG * 32, 6), blk>>>(gXsh, gWqkvh, bq, bk, bv, gQp, gKp, gVp);

    // attention, 3 wide phases (+ the P=32 specials)
    hgemm32_kernel<<<dim3(1, 1, 512), 64>>>(gQp, gKp, gPart + PART32, 65536, 256);
    scores_all_kernel<<<896, blk>>>(gQp, gKp, gPart, gSh);
    smax_all_kernel<<<5440, blk>>>(gPart, gSh);
    gemm_av32_kernel<<<dim3(1024, 1, 2), blk>>>(gSh + SH32, gVp, gAtth, 32, 65536, 5, 0);
    av_all_kernel<<<768, blk>>>(gSh, gVp, gAtth);

    // convs: tap-row-major K, strip shared across 3 chunks; half residual chain
    hconvK_kernel<<<qgrid, blk, HK_SMEM>>>(gAtth, gWlh,  bl,  xs,      nullptr, nullptr, gXs1h, 1, 1);
    hconvK_kernel<<<qgrid, blk, HK_SMEM>>>(gXs1h, gWf1h, bf1, nullptr, nullptr, nullptr, gFfh,  1, 0);
    hconvK_kernel<<<qgrid, blk, HK_SMEM>>>(gFfh,  gWf2h, bf2, nullptr, gXs1h,   out,     nullptr, 2, 1);
}